// round 9
// baseline (speedup 1.0000x reference)
#include <cuda_runtime.h>
#include <cuda_bf16.h>
#include <math.h>
#include <stdint.h>

// ----------------------------------------------------------------------------
// DecoderBlock: B=1, T=4096, C=768, H=12, D=64, F=3072
// Round 8: issue-slot reduction. Raw-f32-as-tf32 (truncation; mma ignores low
// 13 mantissa bits) removes all cvt from hot loops; attention S-phase K frags
// and PV-phase P frags via ldmatrix; P stored with STS.64. QKV stays fused.
// ----------------------------------------------------------------------------

#define T_SEQ 4096
#define C_EMB 768
#define N_HEAD 12
#define D_HEAD 64
#define F_FFN 3072

__device__ float g_h  [T_SEQ * C_EMB];
__device__ float g_q  [T_SEQ * C_EMB];
__device__ float g_k  [T_SEQ * C_EMB];
__device__ float g_v  [T_SEQ * C_EMB];
__device__ float g_ctx[T_SEQ * C_EMB];
__device__ float g_x2 [T_SEQ * C_EMB];
__device__ float g_h2 [T_SEQ * C_EMB];
__device__ float g_m1 [T_SEQ * F_FFN];

// ----------------------------------------------------------------------------
// LayerNorm (unchanged)
// ----------------------------------------------------------------------------
__global__ __launch_bounds__(256) void layernorm_k(
    const float* __restrict__ in, const float* __restrict__ gamma,
    const float* __restrict__ beta, float* __restrict__ out)
{
    int row = blockIdx.x;
    const float* xr = in + (size_t)row * C_EMB;
    float s = 0.f, s2 = 0.f;
    float v0[3];
#pragma unroll
    for (int i = 0; i < 3; i++) {
        float v = xr[threadIdx.x + i * 256];
        v0[i] = v;
        s += v; s2 += v * v;
    }
#pragma unroll
    for (int off = 16; off > 0; off >>= 1) {
        s  += __shfl_down_sync(0xffffffffu, s,  off);
        s2 += __shfl_down_sync(0xffffffffu, s2, off);
    }
    __shared__ float shs[8], shs2[8];
    int lane = threadIdx.x & 31, warp = threadIdx.x >> 5;
    if (lane == 0) { shs[warp] = s; shs2[warp] = s2; }
    __syncthreads();
    s = 0.f; s2 = 0.f;
#pragma unroll
    for (int i = 0; i < 8; i++) { s += shs[i]; s2 += shs2[i]; }
    float mu  = s * (1.0f / C_EMB);
    float var = s2 * (1.0f / C_EMB) - mu * mu;
    float inv = rsqrtf(var + 1e-5f);
    float* orow = out + (size_t)row * C_EMB;
#pragma unroll
    for (int i = 0; i < 3; i++) {
        int c = threadIdx.x + i * 256;
        orow[c] = (v0[i] - mu) * inv * gamma[c] + beta[c];
    }
}

// ----------------------------------------------------------------------------
// helpers
// ----------------------------------------------------------------------------
__device__ __forceinline__ void mma_tf32(float* d, const uint32_t* a, const uint32_t* b) {
    asm volatile(
        "mma.sync.aligned.m16n8k8.row.col.f32.tf32.tf32.f32 "
        "{%0,%1,%2,%3}, {%4,%5,%6,%7}, {%8,%9}, {%0,%1,%2,%3};\n"
        : "+f"(d[0]), "+f"(d[1]), "+f"(d[2]), "+f"(d[3])
        : "r"(a[0]), "r"(a[1]), "r"(a[2]), "r"(a[3]), "r"(b[0]), "r"(b[1]));
}

__device__ __forceinline__ uint32_t s2u(const void* p) {
    return (uint32_t)__cvta_generic_to_shared(p);
}

#define LDSM_X4(r0, r1, r2, r3, addr)                                          \
    asm volatile("ldmatrix.sync.aligned.m8n8.x4.shared.b16 {%0,%1,%2,%3}, [%4];" \
                 : "=r"(r0), "=r"(r1), "=r"(r2), "=r"(r3) : "r"(addr))

__device__ __forceinline__ float gelu_exact(float v) {
    return 0.5f * v * (1.0f + erff(v * 0.70710678118654752440f));
}

// ----------------------------------------------------------------------------
// tf32 GEMM body (ldmatrix fragments, raw f32 bits as tf32 operands).
// BM=BN=128, BK=16, 256 thr, 8 warps 2x4. As[m][k], Bs[n][k], stride 20.
// ----------------------------------------------------------------------------
template<int ACT>
__device__ __forceinline__ void gemm_body(
    const float* __restrict__ A, const float* __restrict__ B,
    const float* __restrict__ bias, const float* __restrict__ res,
    float* __restrict__ C, int M, int N, int K, int bx, int by)
{
    constexpr int BK = 16;
    constexpr int S  = 20;
    __shared__ uint32_t As[2][128][S];
    __shared__ uint32_t Bs[2][128][S];

    int tid  = threadIdx.x;
    int lane = tid & 31;
    int wid  = tid >> 5;
    int wm   = wid & 1;
    int wn   = wid >> 1;
    int gid  = lane >> 2;
    int tig  = lane & 3;

    int bm = by * 128;
    int bn = bx * 128;

    int a_row = wm * 64 + (lane & 15);
    int a_col = (lane >> 4) << 2;
    int b_row = wn * 32 + ((lane >> 4) << 3) + (lane & 7);
    int b_col = ((lane >> 3) & 1) << 2;

    float acc[4][4][4];
#pragma unroll
    for (int i = 0; i < 4; i++)
#pragma unroll
        for (int j = 0; j < 4; j++)
#pragma unroll
            for (int r = 0; r < 4; r++) acc[i][j][r] = 0.f;

    int nt = K / BK;

    uint4 av[2];
    uint32_t bv[2][4];

#pragma unroll
    for (int i = 0; i < 2; i++) {
        int id = tid + i * 256;
        int r = id >> 2, c4 = id & 3;
        av[i] = *(const uint4*)(A + (size_t)(bm + r) * K + c4 * 4);
        int n = id & 127, kg = id >> 7;
#pragma unroll
        for (int j = 0; j < 4; j++)
            bv[i][j] = __float_as_uint(B[(size_t)(kg * 4 + j) * N + bn + n]);
    }
#pragma unroll
    for (int i = 0; i < 2; i++) {
        int id = tid + i * 256;
        int r = id >> 2, c4 = id & 3;
        *(uint4*)&As[0][r][c4 * 4] = av[i];
        int n = id & 127, kg = id >> 7;
        *(uint4*)&Bs[0][n][kg * 4] = make_uint4(bv[i][0], bv[i][1], bv[i][2], bv[i][3]);
    }
    __syncthreads();

    for (int kt = 0; kt < nt; kt++) {
        int buf = kt & 1, nxt = buf ^ 1;
        bool has_next = (kt + 1 < nt);
        if (has_next) {
            int k0 = (kt + 1) * BK;
#pragma unroll
            for (int i = 0; i < 2; i++) {
                int id = tid + i * 256;
                int r = id >> 2, c4 = id & 3;
                av[i] = *(const uint4*)(A + (size_t)(bm + r) * K + k0 + c4 * 4);
                int n = id & 127, kg = id >> 7;
#pragma unroll
                for (int j = 0; j < 4; j++)
                    bv[i][j] = __float_as_uint(B[(size_t)(k0 + kg * 4 + j) * N + bn + n]);
            }
        }

#pragma unroll
        for (int ks = 0; ks < 2; ks++) {
            int kk = ks * 8;
            uint32_t af[4][4];
#pragma unroll
            for (int mt = 0; mt < 4; mt++) {
                uint32_t addr = s2u(&As[buf][a_row + mt * 16][kk + a_col]);
                LDSM_X4(af[mt][0], af[mt][1], af[mt][2], af[mt][3], addr);
            }
            uint32_t bf[4][2];
#pragma unroll
            for (int np = 0; np < 2; np++) {
                uint32_t addr = s2u(&Bs[buf][b_row + np * 16][kk + b_col]);
                LDSM_X4(bf[2 * np][0], bf[2 * np][1],
                        bf[2 * np + 1][0], bf[2 * np + 1][1], addr);
            }
#pragma unroll
            for (int mt = 0; mt < 4; mt++)
#pragma unroll
                for (int ntl = 0; ntl < 4; ntl++)
                    mma_tf32(acc[mt][ntl], af[mt], bf[ntl]);
        }

        if (has_next) {
#pragma unroll
            for (int i = 0; i < 2; i++) {
                int id = tid + i * 256;
                int r = id >> 2, c4 = id & 3;
                *(uint4*)&As[nxt][r][c4 * 4] = av[i];
                int n = id & 127, kg = id >> 7;
                *(uint4*)&Bs[nxt][n][kg * 4] = make_uint4(bv[i][0], bv[i][1], bv[i][2], bv[i][3]);
            }
            __syncthreads();
        }
    }

#pragma unroll
    for (int mt = 0; mt < 4; mt++) {
#pragma unroll
        for (int ntl = 0; ntl < 4; ntl++) {
#pragma unroll
            for (int r = 0; r < 4; r++) {
                int row = bm + wm * 64 + mt * 16 + gid + (r >> 1) * 8;
                int col = bn + wn * 32 + ntl * 8 + tig * 2 + (r & 1);
                float v = acc[mt][ntl][r] + bias[col];
                if (res) v += res[(size_t)row * N + col];
                if (ACT == 1) v = gelu_exact(v);
                C[(size_t)row * N + col] = v;
            }
        }
    }
}

template<int ACT>
__global__ __launch_bounds__(256) void mmgemm_k(
    const float* __restrict__ A, const float* __restrict__ B,
    const float* __restrict__ bias, const float* __restrict__ res,
    float* __restrict__ C, int M, int N, int K)
{
    gemm_body<ACT>(A, B, bias, res, C, M, N, K, blockIdx.x, blockIdx.y);
}

__global__ __launch_bounds__(256) void mmgemm_qkv_k(
    const float* __restrict__ A,
    const float* __restrict__ B0, const float* __restrict__ b0, float* __restrict__ C0,
    const float* __restrict__ B1, const float* __restrict__ b1, float* __restrict__ C1,
    const float* __restrict__ B2, const float* __restrict__ b2, float* __restrict__ C2)
{
    int sel = blockIdx.x / 6;
    int bx  = blockIdx.x % 6;
    const float* B  = (sel == 0) ? B0 : (sel == 1) ? B1 : B2;
    const float* bb = (sel == 0) ? b0 : (sel == 1) ? b1 : b2;
    float*       C  = (sel == 0) ? C0 : (sel == 1) ? C1 : C2;
    gemm_body<0>(A, B, bb, nullptr, C, T_SEQ, C_EMB, C_EMB, bx, blockIdx.y);
}

// ----------------------------------------------------------------------------
// Flash attention: ldmatrix for K b-frags (S phase) + P a-frags (PV phase),
// raw f32 bits as tf32 operands, STS.64 P stores. Fixed causal gate.
// ----------------------------------------------------------------------------
#define KS_STRIDE 68
#define VS_STRIDE 72
#define ATTN_SMEM_BYTES ((64 * KS_STRIDE + 64 * VS_STRIDE + 8 * 16 * KS_STRIDE) * 4)

__global__ __launch_bounds__(256, 2) void fattn_k(
    const float* __restrict__ Q, const float* __restrict__ Kg,
    const float* __restrict__ Vg, float* __restrict__ O)
{
    extern __shared__ uint32_t sm[];
    uint32_t* Ks = sm;                         // [64][68]
    uint32_t* Vs = Ks + 64 * KS_STRIDE;        // [64][72]
    uint32_t* Ps = Vs + 64 * VS_STRIDE;        // [8][16][68]

    int hd   = blockIdx.y;
    int qt   = (int)gridDim.x - 1 - (int)blockIdx.x;
    int tid  = threadIdx.x;
    int w    = tid >> 5;
    int lane = tid & 31;
    int gid  = lane >> 2;
    int tig  = lane & 3;

    int rbase = qt * 128 + w * 16;
    uint32_t* Pw = Ps + w * 16 * KS_STRIDE;

    // ldmatrix lane patterns
    int bs_row = ((lane >> 4) << 3) + (lane & 7);    // K b-frag: + np*16
    int bs_col = ((lane >> 3) & 1) << 2;
    int pa_row = lane & 15;                          // P a-frag
    int pa_col = (lane >> 4) << 2;

    // Q fragments (scale 1/8, raw bits)
    uint32_t aq[8][4];
    {
        const float* qp = Q + (size_t)rbase * C_EMB + hd * D_HEAD;
#pragma unroll
        for (int kk = 0; kk < 8; kk++) {
            aq[kk][0] = __float_as_uint(0.125f * qp[(size_t)gid * C_EMB + kk * 8 + tig]);
            aq[kk][1] = __float_as_uint(0.125f * qp[(size_t)(gid + 8) * C_EMB + kk * 8 + tig]);
            aq[kk][2] = __float_as_uint(0.125f * qp[(size_t)gid * C_EMB + kk * 8 + tig + 4]);
            aq[kk][3] = __float_as_uint(0.125f * qp[(size_t)(gid + 8) * C_EMB + kk * 8 + tig + 4]);
        }
    }

    float oacc[8][4];
#pragma unroll
    for (int i = 0; i < 8; i++)
#pragma unroll
        for (int r = 0; r < 4; r++) oacc[i][r] = 0.f;
    float m_lo = -1e30f, m_hi = -1e30f, l_lo = 0.f, l_hi = 0.f;

    int row0 = rbase + gid;
    int row1 = row0 + 8;
    int wrow_max = rbase + 15;

    int kb_last = 2 * qt + 1;
    for (int kb = 0; kb <= kb_last; kb++) {
        int kbase = kb * 64;
        // cooperative K/V tile load (raw f32 bits, vectorized)
#pragma unroll
        for (int i = 0; i < 4; i++) {
            int id = tid + i * 256;
            int rr = id >> 4, c4 = (id & 15) * 4;
            size_t goff = (size_t)(kbase + rr) * C_EMB + hd * D_HEAD + c4;
            uint4 kv = *(const uint4*)(Kg + goff);
            uint4 vv = *(const uint4*)(Vg + goff);
            *(uint4*)(Ks + rr * KS_STRIDE + c4) = kv;
            *(uint4*)(Vs + rr * VS_STRIDE + c4) = vv;
        }
        __syncthreads();

        if (kbase <= wrow_max) {
            // S = Q K^T : b-frags via ldmatrix (n-major Ks)
            float sacc[8][4];
#pragma unroll
            for (int n = 0; n < 8; n++)
#pragma unroll
                for (int r = 0; r < 4; r++) sacc[n][r] = 0.f;
#pragma unroll
            for (int kk = 0; kk < 8; kk++) {
#pragma unroll
                for (int np = 0; np < 4; np++) {
                    uint32_t b4[4];
                    uint32_t addr = s2u(&Ks[(bs_row + np * 16) * KS_STRIDE + kk * 8 + bs_col]);
                    LDSM_X4(b4[0], b4[1], b4[2], b4[3], addr);
                    mma_tf32(sacc[2 * np],     aq[kk], b4);
                    mma_tf32(sacc[2 * np + 1], aq[kk], b4 + 2);
                }
            }

            // causal mask (gate on FIRST row of warp) + row max
            bool boundary = (kbase + 63 > rbase);
            float ml0 = -1e30f, ml1 = -1e30f;
#pragma unroll
            for (int n = 0; n < 8; n++) {
                if (boundary) {
                    int c = kbase + n * 8 + 2 * tig;
                    if (c     > row0) sacc[n][0] = -1e30f;
                    if (c + 1 > row0) sacc[n][1] = -1e30f;
                    if (c     > row1) sacc[n][2] = -1e30f;
                    if (c + 1 > row1) sacc[n][3] = -1e30f;
                }
                ml0 = fmaxf(ml0, fmaxf(sacc[n][0], sacc[n][1]));
                ml1 = fmaxf(ml1, fmaxf(sacc[n][2], sacc[n][3]));
            }
            ml0 = fmaxf(ml0, __shfl_xor_sync(0xffffffffu, ml0, 1));
            ml0 = fmaxf(ml0, __shfl_xor_sync(0xffffffffu, ml0, 2));
            ml1 = fmaxf(ml1, __shfl_xor_sync(0xffffffffu, ml1, 1));
            ml1 = fmaxf(ml1, __shfl_xor_sync(0xffffffffu, ml1, 2));

            float mn0 = fmaxf(m_lo, ml0), mn1 = fmaxf(m_hi, ml1);
            float al0 = __expf(m_lo - mn0), al1 = __expf(m_hi - mn1);
            m_lo = mn0; m_hi = mn1;

            __syncwarp();   // prev-iter Ps reads complete before overwrite
            float ls0 = 0.f, ls1 = 0.f;
#pragma unroll
            for (int n = 0; n < 8; n++) {
                float p0 = __expf(sacc[n][0] - mn0);
                float p1 = __expf(sacc[n][1] - mn0);
                float p2 = __expf(sacc[n][2] - mn1);
                float p3 = __expf(sacc[n][3] - mn1);
                ls0 += p0 + p1;
                ls1 += p2 + p3;
                *(uint2*)(Pw + gid * KS_STRIDE + n * 8 + 2 * tig) =
                    make_uint2(__float_as_uint(p0), __float_as_uint(p1));
                *(uint2*)(Pw + (gid + 8) * KS_STRIDE + n * 8 + 2 * tig) =
                    make_uint2(__float_as_uint(p2), __float_as_uint(p3));
            }
            ls0 += __shfl_xor_sync(0xffffffffu, ls0, 1);
            ls0 += __shfl_xor_sync(0xffffffffu, ls0, 2);
            ls1 += __shfl_xor_sync(0xffffffffu, ls1, 1);
            ls1 += __shfl_xor_sync(0xffffffffu, ls1, 2);
            l_lo = l_lo * al0 + ls0;
            l_hi = l_hi * al1 + ls1;

#pragma unroll
            for (int n = 0; n < 8; n++) {
                oacc[n][0] *= al0; oacc[n][1] *= al0;
                oacc[n][2] *= al1; oacc[n][3] *= al1;
            }
            __syncwarp();   // Ps writes visible to whole warp

            // O += P V : P a-frags via ldmatrix; V b-frags scalar (conflict-free)
#pragma unroll
            for (int kt = 0; kt < 8; kt++) {
                uint32_t ap[4];
                uint32_t addr = s2u(&Pw[pa_row * KS_STRIDE + kt * 8 + pa_col]);
                LDSM_X4(ap[0], ap[1], ap[2], ap[3], addr);
#pragma unroll
                for (int n = 0; n < 8; n++) {
                    uint32_t b[2];
                    const uint32_t* vp = Vs + (kt * 8 + tig) * VS_STRIDE + n * 8 + gid;
                    b[0] = vp[0];
                    b[1] = vp[4 * VS_STRIDE];
                    mma_tf32(oacc[n], ap, b);
                }
            }
        }
        __syncthreads();
    }

    float inv0 = 1.0f / l_lo;
    float inv1 = 1.0f / l_hi;
    float* o0 = O + (size_t)row0 * C_EMB + hd * D_HEAD;
    float* o1 = O + (size_t)row1 * C_EMB + hd * D_HEAD;
#pragma unroll
    for (int n = 0; n < 8; n++) {
        int c = n * 8 + 2 * tig;
        float2 t0 = make_float2(oacc[n][0] * inv0, oacc[n][1] * inv0);
        float2 t1 = make_float2(oacc[n][2] * inv1, oacc[n][3] * inv1);
        *(float2*)(o0 + c) = t0;
        *(float2*)(o1 + c) = t1;
    }
}

// ----------------------------------------------------------------------------
// launch
// ----------------------------------------------------------------------------
extern "C" void kernel_launch(void* const* d_in, const int* in_sizes, int n_in,
                              void* d_out, int out_size)
{
    const float* x     = (const float*)d_in[0];
    const float* Wq    = (const float*)d_in[1];
    const float* bq    = (const float*)d_in[2];
    const float* Wk    = (const float*)d_in[3];
    const float* bk    = (const float*)d_in[4];
    const float* Wv    = (const float*)d_in[5];
    const float* bv    = (const float*)d_in[6];
    const float* Wo    = (const float*)d_in[7];
    const float* bo    = (const float*)d_in[8];
    const float* ln1_g = (const float*)d_in[9];
    const float* ln1_b = (const float*)d_in[10];
    const float* ln2_g = (const float*)d_in[11];
    const float* ln2_b = (const float*)d_in[12];
    const float* W1    = (const float*)d_in[13];
    const float* b1    = (const float*)d_in[14];
    const float* W2    = (const float*)d_in[15];
    const float* b2    = (const float*)d_in[16];
    float* out = (float*)d_out;

    float *h, *q, *k, *v, *ctx, *x2, *h2, *m1;
    cudaGetSymbolAddress((void**)&h,   g_h);
    cudaGetSymbolAddress((void**)&q,   g_q);
    cudaGetSymbolAddress((void**)&k,   g_k);
    cudaGetSymbolAddress((void**)&v,   g_v);
    cudaGetSymbolAddress((void**)&ctx, g_ctx);
    cudaGetSymbolAddress((void**)&x2,  g_x2);
    cudaGetSymbolAddress((void**)&h2,  g_h2);
    cudaGetSymbolAddress((void**)&m1,  g_m1);

    cudaFuncSetAttribute(fattn_k, cudaFuncAttributeMaxDynamicSharedMemorySize,
                         ATTN_SMEM_BYTES);

    dim3 gC(C_EMB / 128, T_SEQ / 128);     // (6, 32)
    dim3 gQKV(18, T_SEQ / 128);
    dim3 gF(F_FFN / 128, T_SEQ / 128);     // (24, 32)

    layernorm_k<<<T_SEQ, 256>>>(x, ln1_g, ln1_b, h);
    mmgemm_qkv_k<<<gQKV, 256>>>(h, Wq, bq, q, Wk, bk, k, Wv, bv, v);
    fattn_k<<<dim3(T_SEQ / 128, N_HEAD), 256, ATTN_SMEM_BYTES>>>(q, k, v, ctx);
    mmgemm_k<0><<<gC, 256>>>(ctx, Wo, bo, h, x2, T_SEQ, C_EMB, C_EMB);
    layernorm_k<<<T_SEQ, 256>>>(x2, ln2_g, ln2_b, h2);
    mmgemm_k<1><<<gF, 256>>>(h2, W1, b1, nullptr, m1, T_SEQ, F_FFN, C_EMB);
    mmgemm_k<0><<<gC, 256>>>(m1, W2, b2, h2, out, T_SEQ, C_EMB, F_FFN);
}

// round 11
// speedup vs baseline: 1.0460x; 1.0460x over previous
#include <cuda_runtime.h>
#include <cuda_bf16.h>
#include <math.h>
#include <stdint.h>

#define T_SEQ 4096
#define C_EMB 768
#define N_HEAD 12
#define D_HEAD 64
#define F_FFN 3072

__device__ float g_h  [T_SEQ * C_EMB];
__device__ float g_q  [T_SEQ * C_EMB];
__device__ float g_k  [T_SEQ * C_EMB];
__device__ float g_v  [T_SEQ * C_EMB];
__device__ float g_ctx[T_SEQ * C_EMB];
__device__ float g_x2 [T_SEQ * C_EMB];
__device__ float g_h2 [T_SEQ * C_EMB];
__device__ float g_m1 [T_SEQ * F_FFN];
__device__ float g_part[2 * T_SEQ * C_EMB];   // split-K partials

__device__ __forceinline__ void mma_tf32(float* d, const uint32_t* a, const uint32_t* b) {
    asm volatile(
        "mma.sync.aligned.m16n8k8.row.col.f32.tf32.tf32.f32 "
        "{%0,%1,%2,%3}, {%4,%5,%6,%7}, {%8,%9}, {%0,%1,%2,%3};\n"
        : "+f"(d[0]), "+f"(d[1]), "+f"(d[2]), "+f"(d[3])
        : "r"(a[0]), "r"(a[1]), "r"(a[2]), "r"(a[3]), "r"(b[0]), "r"(b[1]));
}
__device__ __forceinline__ uint32_t s2u(const void* p) {
    return (uint32_t)__cvta_generic_to_shared(p);
}
#define LDSM_X4(r0, r1, r2, r3, addr)                                          \
    asm volatile("ldmatrix.sync.aligned.m8n8.x4.shared.b16 {%0,%1,%2,%3}, [%4];" \
                 : "=r"(r0), "=r"(r1), "=r"(r2), "=r"(r3) : "r"(addr))
__device__ __forceinline__ void cp_async16(uint32_t dst, const void* src) {
    asm volatile("cp.async.cg.shared.global [%0], [%1], 16;" :: "r"(dst), "l"(src));
}
#define CP_COMMIT() asm volatile("cp.async.commit_group;" ::: "memory")
#define CP_WAIT(n)  asm volatile("cp.async.wait_group %0;" :: "n"(n) : "memory")

__device__ __forceinline__ float gelu_exact(float v) {
    return 0.5f * v * (1.0f + erff(v * 0.70710678118654752440f));
}

// ----------------------------------------------------------------------------
// LayerNorm
// ----------------------------------------------------------------------------
__global__ __launch_bounds__(256) void layernorm_k(
    const float* __restrict__ in, const float* __restrict__ gamma,
    const float* __restrict__ beta, float* __restrict__ out)
{
    int row = blockIdx.x;
    const float* xr = in + (size_t)row * C_EMB;
    float s = 0.f, s2 = 0.f, v0[3];
#pragma unroll
    for (int i = 0; i < 3; i++) {
        float v = xr[threadIdx.x + i * 256];
        v0[i] = v; s += v; s2 += v * v;
    }
#pragma unroll
    for (int off = 16; off > 0; off >>= 1) {
        s  += __shfl_down_sync(0xffffffffu, s,  off);
        s2 += __shfl_down_sync(0xffffffffu, s2, off);
    }
    __shared__ float shs[8], shs2[8];
    int lane = threadIdx.x & 31, warp = threadIdx.x >> 5;
    if (lane == 0) { shs[warp] = s; shs2[warp] = s2; }
    __syncthreads();
    s = 0.f; s2 = 0.f;
#pragma unroll
    for (int i = 0; i < 8; i++) { s += shs[i]; s2 += shs2[i]; }
    float mu = s * (1.0f / C_EMB);
    float var = s2 * (1.0f / C_EMB) - mu * mu;
    float inv = rsqrtf(var + 1e-5f);
    float* orow = out + (size_t)row * C_EMB;
#pragma unroll
    for (int i = 0; i < 3; i++) {
        int c = threadIdx.x + i * 256;
        orow[c] = (v0[i] - mu) * inv * gamma[c] + beta[c];
    }
}

// ----------------------------------------------------------------------------
// tf32 GEMM body (R8, + kbeg/klen for split-K, PARTIAL raw store)
// ----------------------------------------------------------------------------
template<int ACT, int PARTIAL>
__device__ __forceinline__ void gemm_body(
    const float* __restrict__ A, const float* __restrict__ B,
    const float* __restrict__ bias, const float* __restrict__ res,
    float* __restrict__ C, int N, int K, int kbeg, int klen, int bx, int by)
{
    constexpr int BK = 16;
    constexpr int S  = 20;
    __shared__ uint32_t As[2][128][S];
    __shared__ uint32_t Bs[2][128][S];

    int tid = threadIdx.x, lane = tid & 31, wid = tid >> 5;
    int wm = wid & 1, wn = wid >> 1;
    int gid = lane >> 2, tig = lane & 3;
    int bm = by * 128, bn = bx * 128;

    int a_row = wm * 64 + (lane & 15);
    int a_col = (lane >> 4) << 2;
    int b_row = wn * 32 + ((lane >> 4) << 3) + (lane & 7);
    int b_col = ((lane >> 3) & 1) << 2;

    float acc[4][4][4];
#pragma unroll
    for (int i = 0; i < 4; i++)
#pragma unroll
        for (int j = 0; j < 4; j++)
#pragma unroll
            for (int r = 0; r < 4; r++) acc[i][j][r] = 0.f;

    int nt = klen / BK;
    uint4 av[2];
    uint32_t bv[2][4];

#pragma unroll
    for (int i = 0; i < 2; i++) {
        int id = tid + i * 256;
        int r = id >> 2, c4 = id & 3;
        av[i] = *(const uint4*)(A + (size_t)(bm + r) * K + kbeg + c4 * 4);
        int n = id & 127, kg = id >> 7;
#pragma unroll
        for (int j = 0; j < 4; j++)
            bv[i][j] = __float_as_uint(B[(size_t)(kbeg + kg * 4 + j) * N + bn + n]);
    }
#pragma unroll
    for (int i = 0; i < 2; i++) {
        int id = tid + i * 256;
        int r = id >> 2, c4 = id & 3;
        *(uint4*)&As[0][r][c4 * 4] = av[i];
        int n = id & 127, kg = id >> 7;
        *(uint4*)&Bs[0][n][kg * 4] = make_uint4(bv[i][0], bv[i][1], bv[i][2], bv[i][3]);
    }
    __syncthreads();

    for (int kt = 0; kt < nt; kt++) {
        int buf = kt & 1, nxt = buf ^ 1;
        bool has_next = (kt + 1 < nt);
        if (has_next) {
            int k0 = kbeg + (kt + 1) * BK;
#pragma unroll
            for (int i = 0; i < 2; i++) {
                int id = tid + i * 256;
                int r = id >> 2, c4 = id & 3;
                av[i] = *(const uint4*)(A + (size_t)(bm + r) * K + k0 + c4 * 4);
                int n = id & 127, kg = id >> 7;
#pragma unroll
                for (int j = 0; j < 4; j++)
                    bv[i][j] = __float_as_uint(B[(size_t)(k0 + kg * 4 + j) * N + bn + n]);
            }
        }
#pragma unroll
        for (int ks = 0; ks < 2; ks++) {
            int kk = ks * 8;
            uint32_t af[4][4];
#pragma unroll
            for (int mt = 0; mt < 4; mt++) {
                uint32_t addr = s2u(&As[buf][a_row + mt * 16][kk + a_col]);
                LDSM_X4(af[mt][0], af[mt][1], af[mt][2], af[mt][3], addr);
            }
            uint32_t bf[4][2];
#pragma unroll
            for (int np = 0; np < 2; np++) {
                uint32_t addr = s2u(&Bs[buf][b_row + np * 16][kk + b_col]);
                LDSM_X4(bf[2 * np][0], bf[2 * np][1],
                        bf[2 * np + 1][0], bf[2 * np + 1][1], addr);
            }
#pragma unroll
            for (int mt = 0; mt < 4; mt++)
#pragma unroll
                for (int ntl = 0; ntl < 4; ntl++)
                    mma_tf32(acc[mt][ntl], af[mt], bf[ntl]);
        }
        if (has_next) {
#pragma unroll
            for (int i = 0; i < 2; i++) {
                int id = tid + i * 256;
                int r = id >> 2, c4 = id & 3;
                *(uint4*)&As[nxt][r][c4 * 4] = av[i];
                int n = id & 127, kg = id >> 7;
                *(uint4*)&Bs[nxt][n][kg * 4] = make_uint4(bv[i][0], bv[i][1], bv[i][2], bv[i][3]);
            }
            __syncthreads();
        }
    }

#pragma unroll
    for (int mt = 0; mt < 4; mt++) {
#pragma unroll
        for (int ntl = 0; ntl < 4; ntl++) {
#pragma unroll
            for (int r = 0; r < 4; r++) {
                int row = bm + wm * 64 + mt * 16 + gid + (r >> 1) * 8;
                int col = bn + wn * 32 + ntl * 8 + tig * 2 + (r & 1);
                float v = acc[mt][ntl][r];
                if (!PARTIAL) {
                    v += bias[col];
                    if (res) v += res[(size_t)row * N + col];
                    if (ACT == 1) v = gelu_exact(v);
                }
                C[(size_t)row * N + col] = v;
            }
        }
    }
}

template<int ACT>
__global__ __launch_bounds__(256) void mmgemm_k(
    const float* __restrict__ A, const float* __restrict__ B,
    const float* __restrict__ bias, const float* __restrict__ res,
    float* __restrict__ C, int N, int K)
{
    gemm_body<ACT, 0>(A, B, bias, res, C, N, K, 0, K, blockIdx.x, blockIdx.y);
}

__global__ __launch_bounds__(256) void mmgemm_qkv_k(
    const float* __restrict__ A,
    const float* __restrict__ B0, const float* __restrict__ b0, float* __restrict__ C0,
    const float* __restrict__ B1, const float* __restrict__ b1, float* __restrict__ C1,
    const float* __restrict__ B2, const float* __restrict__ b2, float* __restrict__ C2)
{
    int sel = blockIdx.x / 6, bx = blockIdx.x % 6;
    const float* B  = (sel == 0) ? B0 : (sel == 1) ? B1 : B2;
    const float* bb = (sel == 0) ? b0 : (sel == 1) ? b1 : b2;
    float*       C  = (sel == 0) ? C0 : (sel == 1) ? C1 : C2;
    gemm_body<0, 0>(A, B, bb, nullptr, C, C_EMB, C_EMB, 0, C_EMB, bx, blockIdx.y);
}

// split-K x2: grid (6, 32, 2); z picks K-half and partial buffer
__global__ __launch_bounds__(256) void mmgemm_split_k(
    const float* __restrict__ A, const float* __restrict__ B,
    float* __restrict__ part, int K)
{
    int z = blockIdx.z;
    gemm_body<0, 1>(A, B, nullptr, nullptr,
                    part + (size_t)z * T_SEQ * C_EMB,
                    C_EMB, K, z * (K / 2), K / 2, blockIdx.x, blockIdx.y);
}

// out = p0 + p1 + bias + res, float4 per thread
__global__ __launch_bounds__(256) void combine_k(
    const float* __restrict__ part, const float* __restrict__ bias,
    const float* __restrict__ res, float* __restrict__ out)
{
    int i = blockIdx.x * 256 + threadIdx.x;
    int col = (i * 4) % C_EMB;
    float4 a = ((const float4*)part)[i];
    float4 b = ((const float4*)(part + (size_t)T_SEQ * C_EMB))[i];
    float4 bi = *(const float4*)(bias + col);
    float4 r = ((const float4*)res)[i];
    float4 o;
    o.x = a.x + b.x + bi.x + r.x;
    o.y = a.y + b.y + bi.y + r.y;
    o.z = a.z + b.z + bi.z + r.z;
    o.w = a.w + b.w + bi.w + r.w;
    ((float4*)out)[i] = o;
}

// ----------------------------------------------------------------------------
// Flash attention: R8 compute + cp.async double-buffered K/V tiles
// ----------------------------------------------------------------------------
#define KS_STRIDE 68
#define VS_STRIDE 72
#define ATTN_SMEM_BYTES ((2 * 64 * KS_STRIDE + 2 * 64 * VS_STRIDE + 8 * 16 * KS_STRIDE) * 4)

__global__ __launch_bounds__(256, 2) void fattn_k(
    const float* __restrict__ Q, const float* __restrict__ Kg,
    const float* __restrict__ Vg, float* __restrict__ O)
{
    extern __shared__ uint32_t sm[];
    uint32_t* KsB = sm;                              // [2][64][68]
    uint32_t* VsB = KsB + 2 * 64 * KS_STRIDE;        // [2][64][72]
    uint32_t* Ps  = VsB + 2 * 64 * VS_STRIDE;        // [8][16][68]

    int hd = blockIdx.y;
    int qt = (int)gridDim.x - 1 - (int)blockIdx.x;
    int tid = threadIdx.x, w = tid >> 5, lane = tid & 31;
    int gid = lane >> 2, tig = lane & 3;
    int rbase = qt * 128 + w * 16;
    uint32_t* Pw = Ps + w * 16 * KS_STRIDE;

    int bs_row = ((lane >> 4) << 3) + (lane & 7);
    int bs_col = ((lane >> 3) & 1) << 2;
    int pa_row = lane & 15;
    int pa_col = (lane >> 4) << 2;

    // per-thread load slots (4 rows of K + V each)
    int l_rr[4], l_c4[4];
#pragma unroll
    for (int i = 0; i < 4; i++) {
        int id = tid + i * 256;
        l_rr[i] = id >> 4;
        l_c4[i] = (id & 15) * 4;
    }

    uint32_t aq[8][4];
    {
        const float* qp = Q + (size_t)rbase * C_EMB + hd * D_HEAD;
#pragma unroll
        for (int kk = 0; kk < 8; kk++) {
            aq[kk][0] = __float_as_uint(0.125f * qp[(size_t)gid * C_EMB + kk * 8 + tig]);
            aq[kk][1] = __float_as_uint(0.125f * qp[(size_t)(gid + 8) * C_EMB + kk * 8 + tig]);
            aq[kk][2] = __float_as_uint(0.125f * qp[(size_t)gid * C_EMB + kk * 8 + tig + 4]);
            aq[kk][3] = __float_as_uint(0.125f * qp[(size_t)(gid + 8) * C_EMB + kk * 8 + tig + 4]);
        }
    }
    float oacc[8][4];
#pragma unroll
    for (int i = 0; i < 8; i++)
#pragma unroll
        for (int r = 0; r < 4; r++) oacc[i][r] = 0.f;
    float m_lo = -1e30f, m_hi = -1e30f, l_lo = 0.f, l_hi = 0.f;
    int row0 = rbase + gid, row1 = row0 + 8;

    int kb_last = 2 * qt + 1;

    // prefetch tile 0 -> buf 0
#pragma unroll
    for (int i = 0; i < 4; i++) {
        size_t goff = (size_t)l_rr[i] * C_EMB + hd * D_HEAD + l_c4[i];
        cp_async16(s2u(KsB + l_rr[i] * KS_STRIDE + l_c4[i]), Kg + goff);
        cp_async16(s2u(VsB + l_rr[i] * VS_STRIDE + l_c4[i]), Vg + goff);
    }
    CP_COMMIT();

    for (int kb = 0; kb <= kb_last; kb++) {
        int cur = kb & 1;
        if (kb < kb_last) {
            int nb = (kb + 1) & 1;
            int nbase = (kb + 1) * 64;
#pragma unroll
            for (int i = 0; i < 4; i++) {
                size_t goff = (size_t)(nbase + l_rr[i]) * C_EMB + hd * D_HEAD + l_c4[i];
                cp_async16(s2u(KsB + (nb * 64 + l_rr[i]) * KS_STRIDE + l_c4[i]), Kg + goff);
                cp_async16(s2u(VsB + (nb * 64 + l_rr[i]) * VS_STRIDE + l_c4[i]), Vg + goff);
            }
            CP_COMMIT();
            CP_WAIT(1);
        } else {
            CP_WAIT(0);
        }
        __syncthreads();

        uint32_t* Ks = KsB + cur * 64 * KS_STRIDE;
        uint32_t* Vs = VsB + cur * 64 * VS_STRIDE;
        int kbase = kb * 64;

        if (kbase <= rbase + 15) {
            float sacc[8][4];
#pragma unroll
            for (int n = 0; n < 8; n++)
#pragma unroll
                for (int r = 0; r < 4; r++) sacc[n][r] = 0.f;
#pragma unroll
            for (int kk = 0; kk < 8; kk++) {
#pragma unroll
                for (int np = 0; np < 4; np++) {
                    uint32_t b4[4];
                    uint32_t addr = s2u(&Ks[(bs_row + np * 16) * KS_STRIDE + kk * 8 + bs_col]);
                    LDSM_X4(b4[0], b4[1], b4[2], b4[3], addr);
                    mma_tf32(sacc[2 * np], aq[kk], b4);
                    mma_tf32(sacc[2 * np + 1], aq[kk], b4 + 2);
                }
            }
            bool boundary = (kbase + 63 > rbase);
            float ml0 = -1e30f, ml1 = -1e30f;
#pragma unroll
            for (int n = 0; n < 8; n++) {
                if (boundary) {
                    int c = kbase + n * 8 + 2 * tig;
                    if (c     > row0) sacc[n][0] = -1e30f;
                    if (c + 1 > row0) sacc[n][1] = -1e30f;
                    if (c     > row1) sacc[n][2] = -1e30f;
                    if (c + 1 > row1) sacc[n][3] = -1e30f;
                }
                ml0 = fmaxf(ml0, fmaxf(sacc[n][0], sacc[n][1]));
                ml1 = fmaxf(ml1, fmaxf(sacc[n][2], sacc[n][3]));
            }
            ml0 = fmaxf(ml0, __shfl_xor_sync(0xffffffffu, ml0, 1));
            ml0 = fmaxf(ml0, __shfl_xor_sync(0xffffffffu, ml0, 2));
            ml1 = fmaxf(ml1, __shfl_xor_sync(0xffffffffu, ml1, 1));
            ml1 = fmaxf(ml1, __shfl_xor_sync(0xffffffffu, ml1, 2));
            float mn0 = fmaxf(m_lo, ml0), mn1 = fmaxf(m_hi, ml1);
            float al0 = __expf(m_lo - mn0), al1 = __expf(m_hi - mn1);
            m_lo = mn0; m_hi = mn1;

            __syncwarp();
            float ls0 = 0.f, ls1 = 0.f;
#pragma unroll
            for (int n = 0; n < 8; n++) {
                float p0 = __expf(sacc[n][0] - mn0);
                float p1 = __expf(sacc[n][1] - mn0);
                float p2 = __expf(sacc[n][2] - mn1);
                float p3 = __expf(sacc[n][3] - mn1);
                ls0 += p0 + p1; ls1 += p2 + p3;
                *(uint2*)(Pw + gid * KS_STRIDE + n * 8 + 2 * tig) =
                    make_uint2(__float_as_uint(p0), __float_as_uint(p1));
                *(uint2*)(Pw + (gid + 8) * KS_STRIDE + n * 8 + 2 * tig) =
                    make_uint2(__float_as_uint(p2), __float_as_uint(p3));
            }
            ls0 += __shfl_xor_sync(0xffffffffu, ls0, 1);
            ls0 += __shfl_xor_sync(0xffffffffu, ls0, 2);
            ls1 += __shfl_xor_sync(0xffffffffu, ls1, 1);
            ls1 += __shfl_xor_sync(0xffffffffu, ls1, 2);
            l_lo = l_lo * al0 + ls0;
            l_hi = l_hi * al1 + ls1;
#pragma unroll
            for (int n = 0; n < 8; n++) {
                oacc[n][0] *= al0; oacc[n][1] *= al0;
                oacc[n][2] *= al1; oacc[n][3] *= al1;
            }
            __syncwarp();
#pragma unroll
            for (int kt = 0; kt < 8; kt++) {
                uint32_t ap[4];
                uint32_t addr = s2u(&Pw[pa_row * KS_STRIDE + kt * 8 + pa_col]);
                LDSM_X4(ap[0], ap[1], ap[2], ap[3], addr);
#pragma unroll
                for (int n = 0; n < 8; n++) {
                    uint32_t b[2];
                    const uint32_t* vp = Vs + (kt * 8 + tig) * VS_STRIDE + n * 8 + gid;
                    b[0] = vp[0];
                    b[1] = vp[4 * VS_STRIDE];
                    mma_tf32(oacc[n], ap, b);
                }
            }
        }
        __syncthreads();
    }

    float inv0 = 1.0f / l_lo, inv1 = 1.0f / l_hi;
    float* o0 = O + (size_t)row0 * C_EMB + hd * D_HEAD;
    float* o1 = O + (size_t)row1 * C_EMB + hd * D_HEAD;
#pragma unroll
    for (int n = 0; n < 8; n++) {
        int c = n * 8 + 2 * tig;
        *(float2*)(o0 + c) = make_float2(oacc[n][0] * inv0, oacc[n][1] * inv0);
        *(float2*)(o1 + c) = make_float2(oacc[n][2] * inv1, oacc[n][3] * inv1);
    }
}

// ----------------------------------------------------------------------------
// launch
// ----------------------------------------------------------------------------
extern "C" void kernel_launch(void* const* d_in, const int* in_sizes, int n_in,
                              void* d_out, int out_size)
{
    const float* x     = (const float*)d_in[0];
    const float* Wq    = (const float*)d_in[1];
    const float* bq    = (const float*)d_in[2];
    const float* Wk    = (const float*)d_in[3];
    const float* bk    = (const float*)d_in[4];
    const float* Wv    = (const float*)d_in[5];
    const float* bv    = (const float*)d_in[6];
    const float* Wo    = (const float*)d_in[7];
    const float* bo    = (const float*)d_in[8];
    const float* ln1_g = (const float*)d_in[9];
    const float* ln1_b = (const float*)d_in[10];
    const float* ln2_g = (const float*)d_in[11];
    const float* ln2_b = (const float*)d_in[12];
    const float* W1    = (const float*)d_in[13];
    const float* b1    = (const float*)d_in[14];
    const float* W2    = (const float*)d_in[15];
    const float* b2    = (const float*)d_in[16];
    float* out = (float*)d_out;

    float *h, *q, *k, *v, *ctx, *x2, *h2, *m1, *part;
    cudaGetSymbolAddress((void**)&h,    g_h);
    cudaGetSymbolAddress((void**)&q,    g_q);
    cudaGetSymbolAddress((void**)&k,    g_k);
    cudaGetSymbolAddress((void**)&v,    g_v);
    cudaGetSymbolAddress((void**)&ctx,  g_ctx);
    cudaGetSymbolAddress((void**)&x2,   g_x2);
    cudaGetSymbolAddress((void**)&h2,   g_h2);
    cudaGetSymbolAddress((void**)&m1,   g_m1);
    cudaGetSymbolAddress((void**)&part, g_part);

    cudaFuncSetAttribute(fattn_k, cudaFuncAttributeMaxDynamicSharedMemorySize,
                         ATTN_SMEM_BYTES);

    dim3 gQKV(18, T_SEQ / 128);            // fused q,k,v
    dim3 gF(F_FFN / 128, T_SEQ / 128);     // (24, 32)
    dim3 gSplit(C_EMB / 128, T_SEQ / 128, 2);
    int  gComb = T_SEQ * C_EMB / 4 / 256;  // 3072

    layernorm_k<<<T_SEQ, 256>>>(x, ln1_g, ln1_b, h);
    mmgemm_qkv_k<<<gQKV, 256>>>(h, Wq, bq, q, Wk, bk, k, Wv, bv, v);
    fattn_k<<<dim3(T_SEQ / 128, N_HEAD), 256, ATTN_SMEM_BYTES>>>(q, k, v, ctx);
    // x2 = ctx @ Wo + bo + h   (split-K x2)
    mmgemm_split_k<<<gSplit, 256>>>(ctx, Wo, part, C_EMB);
    combine_k<<<gComb, 256>>>(part, bo, h, x2);
    layernorm_k<<<T_SEQ, 256>>>(x2, ln2_g, ln2_b, h2);
    // m1 = gelu(h2 @ W1 + b1)
    mmgemm_k<1><<<gF, 256>>>(h2, W1, b1, nullptr, m1, F_FFN, C_EMB);
    // out = m1 @ W2 + b2 + h2  (split-K x2)
    mmgemm_split_k<<<gSplit, 256>>>(m1, W2, part, F_FFN);
    combine_k<<<gComb, 256>>>(part, b2, h2, out);
}

// round 12
// speedup vs baseline: 1.4394x; 1.3761x over previous
#include <cuda_runtime.h>
#include <cuda_fp16.h>
#include <math.h>
#include <stdint.h>

#define T_SEQ 4096
#define C_EMB 768
#define N_HEAD 12
#define D_HEAD 64
#define F_FFN 3072

__device__ float  g_h  [T_SEQ * C_EMB];
__device__ __half g_qh [T_SEQ * C_EMB];
__device__ __half g_kh [T_SEQ * C_EMB];
__device__ __half g_vh [T_SEQ * C_EMB];
__device__ float  g_ctx[T_SEQ * C_EMB];
__device__ float  g_x2 [T_SEQ * C_EMB];
__device__ float  g_h2 [T_SEQ * C_EMB];
__device__ float  g_m1 [T_SEQ * F_FFN];
__device__ float  g_part[2 * T_SEQ * C_EMB];

__device__ __forceinline__ uint32_t s2u(const void* p) {
    return (uint32_t)__cvta_generic_to_shared(p);
}
__device__ __forceinline__ uint32_t packh(float lo, float hi) {
    __half2 h = __floats2half2_rn(lo, hi);
    return *reinterpret_cast<uint32_t*>(&h);
}
__device__ __forceinline__ void mma_f16(float* d, const uint32_t* a, const uint32_t* b) {
    asm volatile(
        "mma.sync.aligned.m16n8k16.row.col.f32.f16.f16.f32 "
        "{%0,%1,%2,%3}, {%4,%5,%6,%7}, {%8,%9}, {%0,%1,%2,%3};\n"
        : "+f"(d[0]), "+f"(d[1]), "+f"(d[2]), "+f"(d[3])
        : "r"(a[0]), "r"(a[1]), "r"(a[2]), "r"(a[3]), "r"(b[0]), "r"(b[1]));
}
#define LDSM_X4(r0, r1, r2, r3, addr)                                          \
    asm volatile("ldmatrix.sync.aligned.m8n8.x4.shared.b16 {%0,%1,%2,%3}, [%4];" \
                 : "=r"(r0), "=r"(r1), "=r"(r2), "=r"(r3) : "r"(addr))
#define LDSM_X4_T(r0, r1, r2, r3, addr)                                        \
    asm volatile("ldmatrix.sync.aligned.m8n8.x4.trans.shared.b16 {%0,%1,%2,%3}, [%4];" \
                 : "=r"(r0), "=r"(r1), "=r"(r2), "=r"(r3) : "r"(addr))
__device__ __forceinline__ void cp_async16(uint32_t dst, const void* src) {
    asm volatile("cp.async.cg.shared.global [%0], [%1], 16;" :: "r"(dst), "l"(src));
}
#define CP_COMMIT() asm volatile("cp.async.commit_group;" ::: "memory")
#define CP_WAIT(n)  asm volatile("cp.async.wait_group %0;" :: "n"(n) : "memory")

__device__ __forceinline__ float gelu_exact(float v) {
    return 0.5f * v * (1.0f + erff(v * 0.70710678118654752440f));
}

// ----------------------------------------------------------------------------
// LayerNorm
// ----------------------------------------------------------------------------
__global__ __launch_bounds__(256) void layernorm_k(
    const float* __restrict__ in, const float* __restrict__ gamma,
    const float* __restrict__ beta, float* __restrict__ out)
{
    int row = blockIdx.x;
    const float* xr = in + (size_t)row * C_EMB;
    float s = 0.f, s2 = 0.f, v0[3];
#pragma unroll
    for (int i = 0; i < 3; i++) {
        float v = xr[threadIdx.x + i * 256];
        v0[i] = v; s += v; s2 += v * v;
    }
#pragma unroll
    for (int off = 16; off > 0; off >>= 1) {
        s  += __shfl_down_sync(0xffffffffu, s,  off);
        s2 += __shfl_down_sync(0xffffffffu, s2, off);
    }
    __shared__ float shs[8], shs2[8];
    int lane = threadIdx.x & 31, warp = threadIdx.x >> 5;
    if (lane == 0) { shs[warp] = s; shs2[warp] = s2; }
    __syncthreads();
    s = 0.f; s2 = 0.f;
#pragma unroll
    for (int i = 0; i < 8; i++) { s += shs[i]; s2 += shs2[i]; }
    float mu = s * (1.0f / C_EMB);
    float var = s2 * (1.0f / C_EMB) - mu * mu;
    float inv = rsqrtf(var + 1e-5f);
    float* orow = out + (size_t)row * C_EMB;
#pragma unroll
    for (int i = 0; i < 3; i++) {
        int c = threadIdx.x + i * 256;
        orow[c] = (v0[i] - mu) * inv * gamma[c] + beta[c];
    }
}

// ----------------------------------------------------------------------------
// fp16 GEMM body. BM=BN=128, BK=16 (halves), 8 warps 2x4, m16n8k16.
// As[m][k] halves stride 40; Bs[n][k] halves stride 40.
// OUTH: write packed fp16 to Ch with (acc+bias)*oscale. Else f32 path.
// ----------------------------------------------------------------------------
template<int ACT, int PARTIAL, int OUTH>
__device__ __forceinline__ void hgemm_body(
    const float* __restrict__ A, const float* __restrict__ B,
    const float* __restrict__ bias, const float* __restrict__ res,
    float* __restrict__ C, __half* __restrict__ Ch,
    int N, int K, int kbeg, int klen, int bx, int by, float oscale)
{
    constexpr int S = 40;
    __shared__ __half As[2][128][S];
    __shared__ __half Bs[2][128][S];

    int tid = threadIdx.x, lane = tid & 31, wid = tid >> 5;
    int wm = wid & 1, wn = wid >> 1;
    int gid = lane >> 2, tig = lane & 3;
    int bm = by * 128, bn = bx * 128;

    int a_row  = wm * 64 + (lane & 15);
    int a_colh = (lane >> 4) << 3;
    int b_row  = wn * 32 + ((lane >> 4) << 3) + (lane & 7);
    int b_colh = ((lane >> 3) & 1) << 3;

    float acc[4][4][4];
#pragma unroll
    for (int i = 0; i < 4; i++)
#pragma unroll
        for (int j = 0; j < 4; j++)
#pragma unroll
            for (int r = 0; r < 4; r++) acc[i][j][r] = 0.f;

    int nt = klen / 16;
    float4 av[2];
    float  bv[2][4];

#pragma unroll
    for (int i = 0; i < 2; i++) {
        int id = tid + i * 256;
        int r = id >> 2, c4 = id & 3;
        av[i] = *(const float4*)(A + (size_t)(bm + r) * K + kbeg + c4 * 4);
        int n = id & 127, kg = id >> 7;
#pragma unroll
        for (int j = 0; j < 4; j++)
            bv[i][j] = B[(size_t)(kbeg + kg * 4 + j) * N + bn + n];
    }
#pragma unroll
    for (int i = 0; i < 2; i++) {
        int id = tid + i * 256;
        int r = id >> 2, c4 = id & 3;
        *(uint2*)&As[0][r][c4 * 4] =
            make_uint2(packh(av[i].x, av[i].y), packh(av[i].z, av[i].w));
        int n = id & 127, kg = id >> 7;
        *(uint2*)&Bs[0][n][kg * 4] =
            make_uint2(packh(bv[i][0], bv[i][1]), packh(bv[i][2], bv[i][3]));
    }
    __syncthreads();

    for (int kt = 0; kt < nt; kt++) {
        int buf = kt & 1, nxt = buf ^ 1;
        bool has_next = (kt + 1 < nt);
        if (has_next) {
            int k0 = kbeg + (kt + 1) * 16;
#pragma unroll
            for (int i = 0; i < 2; i++) {
                int id = tid + i * 256;
                int r = id >> 2, c4 = id & 3;
                av[i] = *(const float4*)(A + (size_t)(bm + r) * K + k0 + c4 * 4);
                int n = id & 127, kg = id >> 7;
#pragma unroll
                for (int j = 0; j < 4; j++)
                    bv[i][j] = B[(size_t)(k0 + kg * 4 + j) * N + bn + n];
            }
        }

        uint32_t af[4][4];
#pragma unroll
        for (int mt = 0; mt < 4; mt++) {
            uint32_t addr = s2u(&As[buf][a_row + mt * 16][a_colh]);
            LDSM_X4(af[mt][0], af[mt][1], af[mt][2], af[mt][3], addr);
        }
        uint32_t bf[4][2];
#pragma unroll
        for (int np = 0; np < 2; np++) {
            uint32_t addr = s2u(&Bs[buf][b_row + np * 16][b_colh]);
            LDSM_X4(bf[2 * np][0], bf[2 * np][1],
                    bf[2 * np + 1][0], bf[2 * np + 1][1], addr);
        }
#pragma unroll
        for (int mt = 0; mt < 4; mt++)
#pragma unroll
            for (int ntl = 0; ntl < 4; ntl++)
                mma_f16(acc[mt][ntl], af[mt], bf[ntl]);

        if (has_next) {
#pragma unroll
            for (int i = 0; i < 2; i++) {
                int id = tid + i * 256;
                int r = id >> 2, c4 = id & 3;
                *(uint2*)&As[nxt][r][c4 * 4] =
                    make_uint2(packh(av[i].x, av[i].y), packh(av[i].z, av[i].w));
                int n = id & 127, kg = id >> 7;
                *(uint2*)&Bs[nxt][n][kg * 4] =
                    make_uint2(packh(bv[i][0], bv[i][1]), packh(bv[i][2], bv[i][3]));
            }
            __syncthreads();
        }
    }

#pragma unroll
    for (int mt = 0; mt < 4; mt++) {
#pragma unroll
        for (int ntl = 0; ntl < 4; ntl++) {
            int row = bm + wm * 64 + mt * 16 + gid;
            int col = bn + wn * 32 + ntl * 8 + tig * 2;
            if (OUTH) {
                float v0 = (acc[mt][ntl][0] + bias[col])     * oscale;
                float v1 = (acc[mt][ntl][1] + bias[col + 1]) * oscale;
                float v2 = (acc[mt][ntl][2] + bias[col])     * oscale;
                float v3 = (acc[mt][ntl][3] + bias[col + 1]) * oscale;
                *(uint32_t*)&Ch[(size_t)row * N + col]       = packh(v0, v1);
                *(uint32_t*)&Ch[(size_t)(row + 8) * N + col] = packh(v2, v3);
            } else {
#pragma unroll
                for (int r = 0; r < 4; r++) {
                    int rr = row + (r >> 1) * 8;
                    int cc = col + (r & 1);
                    float v = acc[mt][ntl][r];
                    if (!PARTIAL) {
                        v += bias[cc];
                        if (res) v += res[(size_t)rr * N + cc];
                        if (ACT == 1) v = gelu_exact(v);
                    }
                    C[(size_t)rr * N + cc] = v;
                }
            }
        }
    }
}

template<int ACT>
__global__ __launch_bounds__(256) void hgemm_k(
    const float* __restrict__ A, const float* __restrict__ B,
    const float* __restrict__ bias, const float* __restrict__ res,
    float* __restrict__ C, int N, int K)
{
    hgemm_body<ACT, 0, 0>(A, B, bias, res, C, nullptr, N, K, 0, K,
                          blockIdx.x, blockIdx.y, 1.0f);
}

__global__ __launch_bounds__(256) void hgemm_qkv_k(
    const float* __restrict__ A,
    const float* __restrict__ B0, const float* __restrict__ b0, __half* __restrict__ C0,
    const float* __restrict__ B1, const float* __restrict__ b1, __half* __restrict__ C1,
    const float* __restrict__ B2, const float* __restrict__ b2, __half* __restrict__ C2)
{
    int sel = blockIdx.x / 6, bx = blockIdx.x % 6;
    const float* B  = (sel == 0) ? B0 : (sel == 1) ? B1 : B2;
    const float* bb = (sel == 0) ? b0 : (sel == 1) ? b1 : b2;
    __half*      Ch = (sel == 0) ? C0 : (sel == 1) ? C1 : C2;
    float sc = (sel == 0) ? 0.125f : 1.0f;   // q pre-scaled by 1/sqrt(D)
    hgemm_body<0, 0, 1>(A, B, bb, nullptr, nullptr, Ch, C_EMB, C_EMB, 0, C_EMB,
                        bx, blockIdx.y, sc);
}

__global__ __launch_bounds__(256) void hgemm_split_k(
    const float* __restrict__ A, const float* __restrict__ B,
    float* __restrict__ part, int K)
{
    int z = blockIdx.z;
    hgemm_body<0, 1, 0>(A, B, nullptr, nullptr,
                        part + (size_t)z * T_SEQ * C_EMB, nullptr,
                        C_EMB, K, z * (K / 2), K / 2, blockIdx.x, blockIdx.y, 1.0f);
}

__global__ __launch_bounds__(256) void combine_k(
    const float* __restrict__ part, const float* __restrict__ bias,
    const float* __restrict__ res, float* __restrict__ out)
{
    int i = blockIdx.x * 256 + threadIdx.x;
    int col = (i * 4) % C_EMB;
    float4 a = ((const float4*)part)[i];
    float4 b = ((const float4*)(part + (size_t)T_SEQ * C_EMB))[i];
    float4 bi = *(const float4*)(bias + col);
    float4 r = ((const float4*)res)[i];
    float4 o;
    o.x = a.x + b.x + bi.x + r.x;
    o.y = a.y + b.y + bi.y + r.y;
    o.z = a.z + b.z + bi.z + r.z;
    o.w = a.w + b.w + bi.w + r.w;
    ((float4*)out)[i] = o;
}

// ----------------------------------------------------------------------------
// Flash attention, fp16 m16n8k16. K/V/Q already fp16 (q pre-scaled).
// Ks/Vs [64 keys][72 halves] x2 buffers; Ps [8][16][72 halves].
// cp.async double-buffered tiles; fixed causal gate.
// ----------------------------------------------------------------------------
#define AKS 72
#define ATTN_SMEM_BYTES ((2 * 64 * AKS + 2 * 64 * AKS + 8 * 16 * AKS) * 2)

__global__ __launch_bounds__(256, 2) void fattn_k(
    const __half* __restrict__ Qh, const __half* __restrict__ Kh,
    const __half* __restrict__ Vh, float* __restrict__ O)
{
    extern __shared__ __half smh[];
    __half* KsB = smh;                         // [2][64][72]
    __half* VsB = KsB + 2 * 64 * AKS;          // [2][64][72]
    __half* Ps  = VsB + 2 * 64 * AKS;          // [8][16][72]

    int hd = blockIdx.y;
    int qt = (int)gridDim.x - 1 - (int)blockIdx.x;
    int tid = threadIdx.x, w = tid >> 5, lane = tid & 31;
    int gid = lane >> 2, tig = lane & 3;
    int rbase = qt * 128 + w * 16;
    __half* Pw = Ps + w * 16 * AKS;

    int bs_row = ((lane >> 4) << 3) + (lane & 7);   // S-phase K rows
    int bs_colh = ((lane >> 3) & 1) << 3;
    int pa_row = lane & 15;                         // P a-frag rows
    int pa_colh = (lane >> 4) << 3;
    int vt_row = lane & 15;                         // V trans rows (k within 16)
    int vt_colh = (lane >> 4) << 3;                 // d offset 0/8

    // Q fragments: packed halves straight from global (pre-scaled)
    uint32_t aq[4][4];
    {
        const __half* qp = Qh + (size_t)rbase * C_EMB + hd * D_HEAD;
#pragma unroll
        for (int kk = 0; kk < 4; kk++) {
            aq[kk][0] = *(const uint32_t*)(qp + (size_t)gid * C_EMB + kk * 16 + 2 * tig);
            aq[kk][1] = *(const uint32_t*)(qp + (size_t)(gid + 8) * C_EMB + kk * 16 + 2 * tig);
            aq[kk][2] = *(const uint32_t*)(qp + (size_t)gid * C_EMB + kk * 16 + 2 * tig + 8);
            aq[kk][3] = *(const uint32_t*)(qp + (size_t)(gid + 8) * C_EMB + kk * 16 + 2 * tig + 8);
        }
    }

    float oacc[8][4];
#pragma unroll
    for (int i = 0; i < 8; i++)
#pragma unroll
        for (int r = 0; r < 4; r++) oacc[i][r] = 0.f;
    float m_lo = -1e30f, m_hi = -1e30f, l_lo = 0.f, l_hi = 0.f;
    int row0 = rbase + gid, row1 = row0 + 8;

    int kb_last = 2 * qt + 1;

    // prefetch tile 0: K 512 16B-units + V 512 (64 rows x 8 units each)
#pragma unroll
    for (int i = 0; i < 2; i++) {
        int id = tid + i * 256;
        int rr = id >> 3, it = id & 7;
        cp_async16(s2u(KsB + rr * AKS + it * 8),
                   Kh + (size_t)rr * C_EMB + hd * D_HEAD + it * 8);
        cp_async16(s2u(VsB + rr * AKS + it * 8),
                   Vh + (size_t)rr * C_EMB + hd * D_HEAD + it * 8);
    }
    CP_COMMIT();

    for (int kb = 0; kb <= kb_last; kb++) {
        int cur = kb & 1;
        if (kb < kb_last) {
            int nb = (kb + 1) & 1;
            int nbase = (kb + 1) * 64;
#pragma unroll
            for (int i = 0; i < 2; i++) {
                int id = tid + i * 256;
                int rr = id >> 3, it = id & 7;
                cp_async16(s2u(KsB + (nb * 64 + rr) * AKS + it * 8),
                           Kh + (size_t)(nbase + rr) * C_EMB + hd * D_HEAD + it * 8);
                cp_async16(s2u(VsB + (nb * 64 + rr) * AKS + it * 8),
                           Vh + (size_t)(nbase + rr) * C_EMB + hd * D_HEAD + it * 8);
            }
            CP_COMMIT();
            CP_WAIT(1);
        } else {
            CP_WAIT(0);
        }
        __syncthreads();

        __half* Ks = KsB + cur * 64 * AKS;
        __half* Vs = VsB + cur * 64 * AKS;
        int kbase = kb * 64;

        if (kbase <= rbase + 15) {
            // S = Q K^T : 4 k-chunks x 4 n-tile-pairs
            float sacc[8][4];
#pragma unroll
            for (int n = 0; n < 8; n++)
#pragma unroll
                for (int r = 0; r < 4; r++) sacc[n][r] = 0.f;
#pragma unroll
            for (int kk = 0; kk < 4; kk++) {
#pragma unroll
                for (int np = 0; np < 4; np++) {
                    uint32_t b4[4];
                    uint32_t addr = s2u(&Ks[(np * 16 + bs_row) * AKS + kk * 16 + bs_colh]);
                    LDSM_X4(b4[0], b4[1], b4[2], b4[3], addr);
                    mma_f16(sacc[2 * np],     aq[kk], b4);
                    mma_f16(sacc[2 * np + 1], aq[kk], b4 + 2);
                }
            }

            bool boundary = (kbase + 63 > rbase);
            float ml0 = -1e30f, ml1 = -1e30f;
#pragma unroll
            for (int n = 0; n < 8; n++) {
                if (boundary) {
                    int c = kbase + n * 8 + 2 * tig;
                    if (c     > row0) sacc[n][0] = -1e30f;
                    if (c + 1 > row0) sacc[n][1] = -1e30f;
                    if (c     > row1) sacc[n][2] = -1e30f;
                    if (c + 1 > row1) sacc[n][3] = -1e30f;
                }
                ml0 = fmaxf(ml0, fmaxf(sacc[n][0], sacc[n][1]));
                ml1 = fmaxf(ml1, fmaxf(sacc[n][2], sacc[n][3]));
            }
            ml0 = fmaxf(ml0, __shfl_xor_sync(0xffffffffu, ml0, 1));
            ml0 = fmaxf(ml0, __shfl_xor_sync(0xffffffffu, ml0, 2));
            ml1 = fmaxf(ml1, __shfl_xor_sync(0xffffffffu, ml1, 1));
            ml1 = fmaxf(ml1, __shfl_xor_sync(0xffffffffu, ml1, 2));
            float mn0 = fmaxf(m_lo, ml0), mn1 = fmaxf(m_hi, ml1);
            float al0 = __expf(m_lo - mn0), al1 = __expf(m_hi - mn1);
            m_lo = mn0; m_hi = mn1;

            __syncwarp();
            float ls0 = 0.f, ls1 = 0.f;
#pragma unroll
            for (int n = 0; n < 8; n++) {
                float p0 = __expf(sacc[n][0] - mn0);
                float p1 = __expf(sacc[n][1] - mn0);
                float p2 = __expf(sacc[n][2] - mn1);
                float p3 = __expf(sacc[n][3] - mn1);
                ls0 += p0 + p1; ls1 += p2 + p3;
                *(uint32_t*)(Pw + gid * AKS + n * 8 + 2 * tig)       = packh(p0, p1);
                *(uint32_t*)(Pw + (gid + 8) * AKS + n * 8 + 2 * tig) = packh(p2, p3);
            }
            ls0 += __shfl_xor_sync(0xffffffffu, ls0, 1);
            ls0 += __shfl_xor_sync(0xffffffffu, ls0, 2);
            ls1 += __shfl_xor_sync(0xffffffffu, ls1, 1);
            ls1 += __shfl_xor_sync(0xffffffffu, ls1, 2);
            l_lo = l_lo * al0 + ls0;
            l_hi = l_hi * al1 + ls1;
#pragma unroll
            for (int n = 0; n < 8; n++) {
                oacc[n][0] *= al0; oacc[n][1] *= al0;
                oacc[n][2] *= al1; oacc[n][3] *= al1;
            }
            __syncwarp();

            // O += P V : 4 key-chunks x 4 d-tile-pairs; V via ldmatrix.trans
#pragma unroll
            for (int kt = 0; kt < 4; kt++) {
                uint32_t ap[4];
                uint32_t addr = s2u(&Pw[pa_row * AKS + kt * 16 + pa_colh]);
                LDSM_X4(ap[0], ap[1], ap[2], ap[3], addr);
#pragma unroll
                for (int np2 = 0; np2 < 4; np2++) {
                    uint32_t b4[4];
                    uint32_t va = s2u(&Vs[(kt * 16 + vt_row) * AKS + np2 * 16 + vt_colh]);
                    LDSM_X4_T(b4[0], b4[1], b4[2], b4[3], va);
                    mma_f16(oacc[2 * np2],     ap, b4);
                    mma_f16(oacc[2 * np2 + 1], ap, b4 + 2);
                }
            }
        }
        __syncthreads();
    }

    float inv0 = 1.0f / l_lo, inv1 = 1.0f / l_hi;
    float* o0 = O + (size_t)row0 * C_EMB + hd * D_HEAD;
    float* o1 = O + (size_t)row1 * C_EMB + hd * D_HEAD;
#pragma unroll
    for (int n = 0; n < 8; n++) {
        int c = n * 8 + 2 * tig;
        *(float2*)(o0 + c) = make_float2(oacc[n][0] * inv0, oacc[n][1] * inv0);
        *(float2*)(o1 + c) = make_float2(oacc[n][2] * inv1, oacc[n][3] * inv1);
    }
}

// ----------------------------------------------------------------------------
// launch
// ----------------------------------------------------------------------------
extern "C" void kernel_launch(void* const* d_in, const int* in_sizes, int n_in,
                              void* d_out, int out_size)
{
    const float* x     = (const float*)d_in[0];
    const float* Wq    = (const float*)d_in[1];
    const float* bq    = (const float*)d_in[2];
    const float* Wk    = (const float*)d_in[3];
    const float* bk    = (const float*)d_in[4];
    const float* Wv    = (const float*)d_in[5];
    const float* bv    = (const float*)d_in[6];
    const float* Wo    = (const float*)d_in[7];
    const float* bo    = (const float*)d_in[8];
    const float* ln1_g = (const float*)d_in[9];
    const float* ln1_b = (const float*)d_in[10];
    const float* ln2_g = (const float*)d_in[11];
    const float* ln2_b = (const float*)d_in[12];
    const float* W1    = (const float*)d_in[13];
    const float* b1    = (const float*)d_in[14];
    const float* W2    = (const float*)d_in[15];
    const float* b2    = (const float*)d_in[16];
    float* out = (float*)d_out;

    float *h, *ctx, *x2, *h2, *m1, *part;
    __half *qh, *kh, *vh;
    cudaGetSymbolAddress((void**)&h,    g_h);
    cudaGetSymbolAddress((void**)&qh,   g_qh);
    cudaGetSymbolAddress((void**)&kh,   g_kh);
    cudaGetSymbolAddress((void**)&vh,   g_vh);
    cudaGetSymbolAddress((void**)&ctx,  g_ctx);
    cudaGetSymbolAddress((void**)&x2,   g_x2);
    cudaGetSymbolAddress((void**)&h2,   g_h2);
    cudaGetSymbolAddress((void**)&m1,   g_m1);
    cudaGetSymbolAddress((void**)&part, g_part);

    cudaFuncSetAttribute(fattn_k, cudaFuncAttributeMaxDynamicSharedMemorySize,
                         ATTN_SMEM_BYTES);

    dim3 gQKV(18, T_SEQ / 128);
    dim3 gF(F_FFN / 128, T_SEQ / 128);
    dim3 gSplit(C_EMB / 128, T_SEQ / 128, 2);
    int  gComb = T_SEQ * C_EMB / 4 / 256;

    layernorm_k<<<T_SEQ, 256>>>(x, ln1_g, ln1_b, h);
    hgemm_qkv_k<<<gQKV, 256>>>(h, Wq, bq, qh, Wk, bk, kh, Wv, bv, vh);
    fattn_k<<<dim3(T_SEQ / 128, N_HEAD), 256, ATTN_SMEM_BYTES>>>(qh, kh, vh, ctx);
    hgemm_split_k<<<gSplit, 256>>>(ctx, Wo, part, C_EMB);
    combine_k<<<gComb, 256>>>(part, bo, h, x2);
    layernorm_k<<<T_SEQ, 256>>>(x2, ln2_g, ln2_b, h2);
    hgemm_k<1><<<gF, 256>>>(h2, W1, b1, nullptr, m1, F_FFN, C_EMB);
    hgemm_split_k<<<gSplit, 256>>>(m1, W2, part, F_FFN);
    combine_k<<<gComb, 256>>>(part, b2, h2, out);
}

// round 13
// speedup vs baseline: 1.6456x; 1.1432x over previous
#include <cuda_runtime.h>
#include <cuda_fp16.h>
#include <math.h>
#include <stdint.h>

#define T_SEQ 4096
#define C_EMB 768
#define N_HEAD 12
#define D_HEAD 64
#define F_FFN 3072

// f32 buffers (residual paths / partials / output staging)
__device__ float  g_h  [T_SEQ * C_EMB];
__device__ float  g_h2 [T_SEQ * C_EMB];
__device__ float  g_part[2 * T_SEQ * C_EMB];
// fp16 activation buffers
__device__ __half g_hh [T_SEQ * C_EMB];
__device__ __half g_h2h[T_SEQ * C_EMB];
__device__ __half g_qh [T_SEQ * C_EMB];
__device__ __half g_kh [T_SEQ * C_EMB];
__device__ __half g_vh [T_SEQ * C_EMB];
__device__ __half g_ctxh[T_SEQ * C_EMB];
__device__ __half g_m1h[T_SEQ * F_FFN];
// fp16 transposed weights [N][K]
__device__ __half g_wtq[C_EMB * C_EMB];
__device__ __half g_wtk[C_EMB * C_EMB];
__device__ __half g_wtv[C_EMB * C_EMB];
__device__ __half g_wto[C_EMB * C_EMB];
__device__ __half g_wt1[F_FFN * C_EMB];
__device__ __half g_wt2[C_EMB * F_FFN];

__device__ __forceinline__ uint32_t s2u(const void* p) {
    return (uint32_t)__cvta_generic_to_shared(p);
}
__device__ __forceinline__ uint32_t packh(float lo, float hi) {
    __half2 h = __floats2half2_rn(lo, hi);
    return *reinterpret_cast<uint32_t*>(&h);
}
__device__ __forceinline__ void mma_f16(float* d, const uint32_t* a, const uint32_t* b) {
    asm volatile(
        "mma.sync.aligned.m16n8k16.row.col.f32.f16.f16.f32 "
        "{%0,%1,%2,%3}, {%4,%5,%6,%7}, {%8,%9}, {%0,%1,%2,%3};\n"
        : "+f"(d[0]), "+f"(d[1]), "+f"(d[2]), "+f"(d[3])
        : "r"(a[0]), "r"(a[1]), "r"(a[2]), "r"(a[3]), "r"(b[0]), "r"(b[1]));
}
#define LDSM_X4(r0, r1, r2, r3, addr)                                          \
    asm volatile("ldmatrix.sync.aligned.m8n8.x4.shared.b16 {%0,%1,%2,%3}, [%4];" \
                 : "=r"(r0), "=r"(r1), "=r"(r2), "=r"(r3) : "r"(addr))
#define LDSM_X4_T(r0, r1, r2, r3, addr)                                        \
    asm volatile("ldmatrix.sync.aligned.m8n8.x4.trans.shared.b16 {%0,%1,%2,%3}, [%4];" \
                 : "=r"(r0), "=r"(r1), "=r"(r2), "=r"(r3) : "r"(addr))
__device__ __forceinline__ void cp_async16(uint32_t dst, const void* src) {
    asm volatile("cp.async.cg.shared.global [%0], [%1], 16;" :: "r"(dst), "l"(src));
}
#define CP_COMMIT() asm volatile("cp.async.commit_group;" ::: "memory")
#define CP_WAIT(n)  asm volatile("cp.async.wait_group %0;" :: "n"(n) : "memory")

__device__ __forceinline__ float gelu_exact(float v) {
    return 0.5f * v * (1.0f + erff(v * 0.70710678118654752440f));
}

// ----------------------------------------------------------------------------
// weight convert + transpose: out[n][k] = (half) in[k][n]; in is [R][Cc]
// ----------------------------------------------------------------------------
__global__ __launch_bounds__(256) void cvt_t_k(
    const float* __restrict__ in, __half* __restrict__ out, int R, int Cc)
{
    __shared__ float t[32][33];
    int bx = blockIdx.x * 32, by = blockIdx.y * 32;   // bx: col(n), by: row(k)
    int tx = threadIdx.x, ty = threadIdx.y;
#pragma unroll
    for (int i = 0; i < 4; i++)
        t[ty + i * 8][tx] = in[(size_t)(by + ty + i * 8) * Cc + bx + tx];
    __syncthreads();
#pragma unroll
    for (int i = 0; i < 4; i++)
        out[(size_t)(bx + ty + i * 8) * R + by + tx] = __float2half_rn(t[tx][ty + i * 8]);
}

// ----------------------------------------------------------------------------
// LayerNorm: writes f32 (residual) + fp16 (GEMM input)
// ----------------------------------------------------------------------------
__global__ __launch_bounds__(256) void layernorm_k(
    const float* __restrict__ in, const float* __restrict__ gamma,
    const float* __restrict__ beta, float* __restrict__ out,
    __half* __restrict__ outh)
{
    int row = blockIdx.x;
    const float* xr = in + (size_t)row * C_EMB;
    float s = 0.f, s2 = 0.f, v0[3];
#pragma unroll
    for (int i = 0; i < 3; i++) {
        float v = xr[threadIdx.x + i * 256];
        v0[i] = v; s += v; s2 += v * v;
    }
#pragma unroll
    for (int off = 16; off > 0; off >>= 1) {
        s  += __shfl_down_sync(0xffffffffu, s,  off);
        s2 += __shfl_down_sync(0xffffffffu, s2, off);
    }
    __shared__ float shs[8], shs2[8];
    int lane = threadIdx.x & 31, warp = threadIdx.x >> 5;
    if (lane == 0) { shs[warp] = s; shs2[warp] = s2; }
    __syncthreads();
    s = 0.f; s2 = 0.f;
#pragma unroll
    for (int i = 0; i < 8; i++) { s += shs[i]; s2 += shs2[i]; }
    float mu = s * (1.0f / C_EMB);
    float var = s2 * (1.0f / C_EMB) - mu * mu;
    float inv = rsqrtf(var + 1e-5f);
#pragma unroll
    for (int i = 0; i < 3; i++) {
        int c = threadIdx.x + i * 256;
        float v = (v0[i] - mu) * inv * gamma[c] + beta[c];
        out [(size_t)row * C_EMB + c] = v;
        outh[(size_t)row * C_EMB + c] = __float2half_rn(v);
    }
}

// fused combine + LayerNorm: t = p0+p1+bias+res; LN(t) -> f32 + fp16
__global__ __launch_bounds__(256) void combine_ln_k(
    const float* __restrict__ part, const float* __restrict__ bias,
    const float* __restrict__ res, const float* __restrict__ gamma,
    const float* __restrict__ beta, float* __restrict__ out,
    __half* __restrict__ outh)
{
    int row = blockIdx.x;
    size_t base = (size_t)row * C_EMB;
    float s = 0.f, s2 = 0.f, v0[3];
#pragma unroll
    for (int i = 0; i < 3; i++) {
        int c = threadIdx.x + i * 256;
        float v = part[base + c] + part[(size_t)T_SEQ * C_EMB + base + c]
                + bias[c] + res[base + c];
        v0[i] = v; s += v; s2 += v * v;
    }
#pragma unroll
    for (int off = 16; off > 0; off >>= 1) {
        s  += __shfl_down_sync(0xffffffffu, s,  off);
        s2 += __shfl_down_sync(0xffffffffu, s2, off);
    }
    __shared__ float shs[8], shs2[8];
    int lane = threadIdx.x & 31, warp = threadIdx.x >> 5;
    if (lane == 0) { shs[warp] = s; shs2[warp] = s2; }
    __syncthreads();
    s = 0.f; s2 = 0.f;
#pragma unroll
    for (int i = 0; i < 8; i++) { s += shs[i]; s2 += shs2[i]; }
    float mu = s * (1.0f / C_EMB);
    float var = s2 * (1.0f / C_EMB) - mu * mu;
    float inv = rsqrtf(var + 1e-5f);
#pragma unroll
    for (int i = 0; i < 3; i++) {
        int c = threadIdx.x + i * 256;
        float v = (v0[i] - mu) * inv * gamma[c] + beta[c];
        out [base + c] = v;
        outh[base + c] = __float2half_rn(v);
    }
}

// final combine: out = p0 + p1 + bias + res
__global__ __launch_bounds__(256) void combine_k(
    const float* __restrict__ part, const float* __restrict__ bias,
    const float* __restrict__ res, float* __restrict__ out)
{
    int i = blockIdx.x * 256 + threadIdx.x;
    int col = (i * 4) % C_EMB;
    float4 a = ((const float4*)part)[i];
    float4 b = ((const float4*)(part + (size_t)T_SEQ * C_EMB))[i];
    float4 bi = *(const float4*)(bias + col);
    float4 r = ((const float4*)res)[i];
    float4 o;
    o.x = a.x + b.x + bi.x + r.x;
    o.y = a.y + b.y + bi.y + r.y;
    o.z = a.z + b.z + bi.z + r.z;
    o.w = a.w + b.w + bi.w + r.w;
    ((float4*)out)[i] = o;
}

// ----------------------------------------------------------------------------
// fp16 GEMM body. A[M,K] half, B[N,K] half (pre-transposed weights).
// BM=BN=128, BK=16 halves, stride 24 halves (48B, conflict-free ldmatrix).
// All loads cp.async (1 unit A + 1 unit B per thread per stage).
// ----------------------------------------------------------------------------
template<int ACT, int PARTIAL, int OUTH>
__device__ __forceinline__ void hgemm_body(
    const __half* __restrict__ A, const __half* __restrict__ B,
    const float* __restrict__ bias, const float* __restrict__ res,
    float* __restrict__ C, __half* __restrict__ Ch,
    int N, int K, int kbeg, int klen, int bx, int by, float oscale)
{
    constexpr int S = 24;
    __shared__ __half As[2][128][S];
    __shared__ __half Bs[2][128][S];

    int tid = threadIdx.x, lane = tid & 31, wid = tid >> 5;
    int wm = wid & 1, wn = wid >> 1;
    int gid = lane >> 2, tig = lane & 3;
    int bm = by * 128, bn = bx * 128;

    int a_row  = wm * 64 + (lane & 15);
    int a_colh = (lane >> 4) << 3;
    int b_row  = wn * 32 + ((lane >> 4) << 3) + (lane & 7);
    int b_colh = ((lane >> 3) & 1) << 3;

    // cp.async slots: thread -> (row = tid>>1, unit = tid&1) for A and B
    int l_r = tid >> 1, l_u = (tid & 1) * 8;

    float acc[4][4][4];
#pragma unroll
    for (int i = 0; i < 4; i++)
#pragma unroll
        for (int j = 0; j < 4; j++)
#pragma unroll
            for (int r = 0; r < 4; r++) acc[i][j][r] = 0.f;

    int nt = klen / 16;

    // stage 0
    cp_async16(s2u(&As[0][l_r][l_u]), A + (size_t)(bm + l_r) * K + kbeg + l_u);
    cp_async16(s2u(&Bs[0][l_r][l_u]), B + (size_t)(bn + l_r) * K + kbeg + l_u);
    CP_COMMIT();

    for (int kt = 0; kt < nt; kt++) {
        int buf = kt & 1, nxt = buf ^ 1;
        bool has_next = (kt + 1 < nt);
        if (has_next) {
            int k0 = kbeg + (kt + 1) * 16;
            cp_async16(s2u(&As[nxt][l_r][l_u]), A + (size_t)(bm + l_r) * K + k0 + l_u);
            cp_async16(s2u(&Bs[nxt][l_r][l_u]), B + (size_t)(bn + l_r) * K + k0 + l_u);
            CP_COMMIT();
            CP_WAIT(1);
        } else {
            CP_WAIT(0);
        }
        __syncthreads();

        uint32_t af[4][4];
#pragma unroll
        for (int mt = 0; mt < 4; mt++) {
            uint32_t addr = s2u(&As[buf][a_row + mt * 16][a_colh]);
            LDSM_X4(af[mt][0], af[mt][1], af[mt][2], af[mt][3], addr);
        }
        uint32_t bf[4][2];
#pragma unroll
        for (int np = 0; np < 2; np++) {
            uint32_t addr = s2u(&Bs[buf][b_row + np * 16][b_colh]);
            LDSM_X4(bf[2 * np][0], bf[2 * np][1],
                    bf[2 * np + 1][0], bf[2 * np + 1][1], addr);
        }
#pragma unroll
        for (int mt = 0; mt < 4; mt++)
#pragma unroll
            for (int ntl = 0; ntl < 4; ntl++)
                mma_f16(acc[mt][ntl], af[mt], bf[ntl]);
        __syncthreads();
    }

#pragma unroll
    for (int mt = 0; mt < 4; mt++) {
#pragma unroll
        for (int ntl = 0; ntl < 4; ntl++) {
            int row = bm + wm * 64 + mt * 16 + gid;
            int col = bn + wn * 32 + ntl * 8 + tig * 2;
            if (OUTH) {
                float v0 = acc[mt][ntl][0] + bias[col];
                float v1 = acc[mt][ntl][1] + bias[col + 1];
                float v2 = acc[mt][ntl][2] + bias[col];
                float v3 = acc[mt][ntl][3] + bias[col + 1];
                if (ACT == 1) {
                    v0 = gelu_exact(v0); v1 = gelu_exact(v1);
                    v2 = gelu_exact(v2); v3 = gelu_exact(v3);
                }
                v0 *= oscale; v1 *= oscale; v2 *= oscale; v3 *= oscale;
                *(uint32_t*)&Ch[(size_t)row * N + col]       = packh(v0, v1);
                *(uint32_t*)&Ch[(size_t)(row + 8) * N + col] = packh(v2, v3);
            } else {
#pragma unroll
                for (int r = 0; r < 4; r++) {
                    int rr = row + (r >> 1) * 8;
                    int cc = col + (r & 1);
                    float v = acc[mt][ntl][r];
                    if (!PARTIAL) {
                        v += bias[cc];
                        if (res) v += res[(size_t)rr * N + cc];
                        if (ACT == 1) v = gelu_exact(v);
                    }
                    C[(size_t)rr * N + cc] = v;
                }
            }
        }
    }
}

// W1: gelu -> m1 fp16
__global__ __launch_bounds__(256) void hgemm_gelu_h_k(
    const __half* __restrict__ A, const __half* __restrict__ B,
    const float* __restrict__ bias, __half* __restrict__ Ch, int N, int K)
{
    hgemm_body<1, 0, 1>(A, B, bias, nullptr, nullptr, Ch, N, K, 0, K,
                        blockIdx.x, blockIdx.y, 1.0f);
}

__global__ __launch_bounds__(256) void hgemm_qkv_k(
    const __half* __restrict__ A,
    const __half* __restrict__ B0, const float* __restrict__ b0, __half* __restrict__ C0,
    const __half* __restrict__ B1, const float* __restrict__ b1, __half* __restrict__ C1,
    const __half* __restrict__ B2, const float* __restrict__ b2, __half* __restrict__ C2)
{
    int sel = blockIdx.x / 6, bx = blockIdx.x % 6;
    const __half* B  = (sel == 0) ? B0 : (sel == 1) ? B1 : B2;
    const float*  bb = (sel == 0) ? b0 : (sel == 1) ? b1 : b2;
    __half*       Ch = (sel == 0) ? C0 : (sel == 1) ? C1 : C2;
    float sc = (sel == 0) ? 0.125f : 1.0f;
    hgemm_body<0, 0, 1>(A, B, bb, nullptr, nullptr, Ch, C_EMB, C_EMB, 0, C_EMB,
                        bx, blockIdx.y, sc);
}

__global__ __launch_bounds__(256) void hgemm_split_k(
    const __half* __restrict__ A, const __half* __restrict__ B,
    float* __restrict__ part, int K)
{
    int z = blockIdx.z;
    hgemm_body<0, 1, 0>(A, B, nullptr, nullptr,
                        part + (size_t)z * T_SEQ * C_EMB, nullptr,
                        C_EMB, K, z * (K / 2), K / 2, blockIdx.x, blockIdx.y, 1.0f);
}

// ----------------------------------------------------------------------------
// Flash attention fp16 (R12), output written as fp16 ctx
// ----------------------------------------------------------------------------
#define AKS 72
#define ATTN_SMEM_BYTES ((2 * 64 * AKS + 2 * 64 * AKS + 8 * 16 * AKS) * 2)

__global__ __launch_bounds__(256, 2) void fattn_k(
    const __half* __restrict__ Qh, const __half* __restrict__ Kh,
    const __half* __restrict__ Vh, __half* __restrict__ Oh)
{
    extern __shared__ __half smh[];
    __half* KsB = smh;
    __half* VsB = KsB + 2 * 64 * AKS;
    __half* Ps  = VsB + 2 * 64 * AKS;

    int hd = blockIdx.y;
    int qt = (int)gridDim.x - 1 - (int)blockIdx.x;
    int tid = threadIdx.x, w = tid >> 5, lane = tid & 31;
    int gid = lane >> 2, tig = lane & 3;
    int rbase = qt * 128 + w * 16;
    __half* Pw = Ps + w * 16 * AKS;

    int bs_row = ((lane >> 4) << 3) + (lane & 7);
    int bs_colh = ((lane >> 3) & 1) << 3;
    int pa_row = lane & 15;
    int pa_colh = (lane >> 4) << 3;
    int vt_row = lane & 15;
    int vt_colh = (lane >> 4) << 3;

    uint32_t aq[4][4];
    {
        const __half* qp = Qh + (size_t)rbase * C_EMB + hd * D_HEAD;
#pragma unroll
        for (int kk = 0; kk < 4; kk++) {
            aq[kk][0] = *(const uint32_t*)(qp + (size_t)gid * C_EMB + kk * 16 + 2 * tig);
            aq[kk][1] = *(const uint32_t*)(qp + (size_t)(gid + 8) * C_EMB + kk * 16 + 2 * tig);
            aq[kk][2] = *(const uint32_t*)(qp + (size_t)gid * C_EMB + kk * 16 + 2 * tig + 8);
            aq[kk][3] = *(const uint32_t*)(qp + (size_t)(gid + 8) * C_EMB + kk * 16 + 2 * tig + 8);
        }
    }

    float oacc[8][4];
#pragma unroll
    for (int i = 0; i < 8; i++)
#pragma unroll
        for (int r = 0; r < 4; r++) oacc[i][r] = 0.f;
    float m_lo = -1e30f, m_hi = -1e30f, l_lo = 0.f, l_hi = 0.f;
    int row0 = rbase + gid, row1 = row0 + 8;

    int kb_last = 2 * qt + 1;

#pragma unroll
    for (int i = 0; i < 2; i++) {
        int id = tid + i * 256;
        int rr = id >> 3, it = id & 7;
        cp_async16(s2u(KsB + rr * AKS + it * 8),
                   Kh + (size_t)rr * C_EMB + hd * D_HEAD + it * 8);
        cp_async16(s2u(VsB + rr * AKS + it * 8),
                   Vh + (size_t)rr * C_EMB + hd * D_HEAD + it * 8);
    }
    CP_COMMIT();

    for (int kb = 0; kb <= kb_last; kb++) {
        int cur = kb & 1;
        if (kb < kb_last) {
            int nb = (kb + 1) & 1;
            int nbase = (kb + 1) * 64;
#pragma unroll
            for (int i = 0; i < 2; i++) {
                int id = tid + i * 256;
                int rr = id >> 3, it = id & 7;
                cp_async16(s2u(KsB + (nb * 64 + rr) * AKS + it * 8),
                           Kh + (size_t)(nbase + rr) * C_EMB + hd * D_HEAD + it * 8);
                cp_async16(s2u(VsB + (nb * 64 + rr) * AKS + it * 8),
                           Vh + (size_t)(nbase + rr) * C_EMB + hd * D_HEAD + it * 8);
            }
            CP_COMMIT();
            CP_WAIT(1);
        } else {
            CP_WAIT(0);
        }
        __syncthreads();

        __half* Ks = KsB + cur * 64 * AKS;
        __half* Vs = VsB + cur * 64 * AKS;
        int kbase = kb * 64;

        if (kbase <= rbase + 15) {
            float sacc[8][4];
#pragma unroll
            for (int n = 0; n < 8; n++)
#pragma unroll
                for (int r = 0; r < 4; r++) sacc[n][r] = 0.f;
#pragma unroll
            for (int kk = 0; kk < 4; kk++) {
#pragma unroll
                for (int np = 0; np < 4; np++) {
                    uint32_t b4[4];
                    uint32_t addr = s2u(&Ks[(np * 16 + bs_row) * AKS + kk * 16 + bs_colh]);
                    LDSM_X4(b4[0], b4[1], b4[2], b4[3], addr);
                    mma_f16(sacc[2 * np],     aq[kk], b4);
                    mma_f16(sacc[2 * np + 1], aq[kk], b4 + 2);
                }
            }

            bool boundary = (kbase + 63 > rbase);
            float ml0 = -1e30f, ml1 = -1e30f;
#pragma unroll
            for (int n = 0; n < 8; n++) {
                if (boundary) {
                    int c = kbase + n * 8 + 2 * tig;
                    if (c     > row0) sacc[n][0] = -1e30f;
                    if (c + 1 > row0) sacc[n][1] = -1e30f;
                    if (c     > row1) sacc[n][2] = -1e30f;
                    if (c + 1 > row1) sacc[n][3] = -1e30f;
                }
                ml0 = fmaxf(ml0, fmaxf(sacc[n][0], sacc[n][1]));
                ml1 = fmaxf(ml1, fmaxf(sacc[n][2], sacc[n][3]));
            }
            ml0 = fmaxf(ml0, __shfl_xor_sync(0xffffffffu, ml0, 1));
            ml0 = fmaxf(ml0, __shfl_xor_sync(0xffffffffu, ml0, 2));
            ml1 = fmaxf(ml1, __shfl_xor_sync(0xffffffffu, ml1, 1));
            ml1 = fmaxf(ml1, __shfl_xor_sync(0xffffffffu, ml1, 2));
            float mn0 = fmaxf(m_lo, ml0), mn1 = fmaxf(m_hi, ml1);
            float al0 = __expf(m_lo - mn0), al1 = __expf(m_hi - mn1);
            m_lo = mn0; m_hi = mn1;

            __syncwarp();
            float ls0 = 0.f, ls1 = 0.f;
#pragma unroll
            for (int n = 0; n < 8; n++) {
                float p0 = __expf(sacc[n][0] - mn0);
                float p1 = __expf(sacc[n][1] - mn0);
                float p2 = __expf(sacc[n][2] - mn1);
                float p3 = __expf(sacc[n][3] - mn1);
                ls0 += p0 + p1; ls1 += p2 + p3;
                *(uint32_t*)(Pw + gid * AKS + n * 8 + 2 * tig)       = packh(p0, p1);
                *(uint32_t*)(Pw + (gid + 8) * AKS + n * 8 + 2 * tig) = packh(p2, p3);
            }
            ls0 += __shfl_xor_sync(0xffffffffu, ls0, 1);
            ls0 += __shfl_xor_sync(0xffffffffu, ls0, 2);
            ls1 += __shfl_xor_sync(0xffffffffu, ls1, 1);
            ls1 += __shfl_xor_sync(0xffffffffu, ls1, 2);
            l_lo = l_lo * al0 + ls0;
            l_hi = l_hi * al1 + ls1;
#pragma unroll
            for (int n = 0; n < 8; n++) {
                oacc[n][0] *= al0; oacc[n][1] *= al0;
                oacc[n][2] *= al1; oacc[n][3] *= al1;
            }
            __syncwarp();

#pragma unroll
            for (int kt = 0; kt < 4; kt++) {
                uint32_t ap[4];
                uint32_t addr = s2u(&Pw[pa_row * AKS + kt * 16 + pa_colh]);
                LDSM_X4(ap[0], ap[1], ap[2], ap[3], addr);
#pragma unroll
                for (int np2 = 0; np2 < 4; np2++) {
                    uint32_t b4[4];
                    uint32_t va = s2u(&Vs[(kt * 16 + vt_row) * AKS + np2 * 16 + vt_colh]);
                    LDSM_X4_T(b4[0], b4[1], b4[2], b4[3], va);
                    mma_f16(oacc[2 * np2],     ap, b4);
                    mma_f16(oacc[2 * np2 + 1], ap, b4 + 2);
                }
            }
        }
        __syncthreads();
    }

    float inv0 = 1.0f / l_lo, inv1 = 1.0f / l_hi;
    __half* o0 = Oh + (size_t)row0 * C_EMB + hd * D_HEAD;
    __half* o1 = Oh + (size_t)row1 * C_EMB + hd * D_HEAD;
#pragma unroll
    for (int n = 0; n < 8; n++) {
        int c = n * 8 + 2 * tig;
        *(uint32_t*)(o0 + c) = packh(oacc[n][0] * inv0, oacc[n][1] * inv0);
        *(uint32_t*)(o1 + c) = packh(oacc[n][2] * inv1, oacc[n][3] * inv1);
    }
}

// ----------------------------------------------------------------------------
// launch
// ----------------------------------------------------------------------------
extern "C" void kernel_launch(void* const* d_in, const int* in_sizes, int n_in,
                              void* d_out, int out_size)
{
    const float* x     = (const float*)d_in[0];
    const float* Wq    = (const float*)d_in[1];
    const float* bq    = (const float*)d_in[2];
    const float* Wk    = (const float*)d_in[3];
    const float* bk    = (const float*)d_in[4];
    const float* Wv    = (const float*)d_in[5];
    const float* bv    = (const float*)d_in[6];
    const float* Wo    = (const float*)d_in[7];
    const float* bo    = (const float*)d_in[8];
    const float* ln1_g = (const float*)d_in[9];
    const float* ln1_b = (const float*)d_in[10];
    const float* ln2_g = (const float*)d_in[11];
    const float* ln2_b = (const float*)d_in[12];
    const float* W1    = (const float*)d_in[13];
    const float* b1    = (const float*)d_in[14];
    const float* W2    = (const float*)d_in[15];
    const float* b2    = (const float*)d_in[16];
    float* out = (float*)d_out;

    float *h, *h2, *part;
    __half *hh, *h2h, *qh, *kh, *vh, *ctxh, *m1h;
    __half *wtq, *wtk, *wtv, *wto, *wt1, *wt2;
    cudaGetSymbolAddress((void**)&h,    g_h);
    cudaGetSymbolAddress((void**)&h2,   g_h2);
    cudaGetSymbolAddress((void**)&part, g_part);
    cudaGetSymbolAddress((void**)&hh,   g_hh);
    cudaGetSymbolAddress((void**)&h2h,  g_h2h);
    cudaGetSymbolAddress((void**)&qh,   g_qh);
    cudaGetSymbolAddress((void**)&kh,   g_kh);
    cudaGetSymbolAddress((void**)&vh,   g_vh);
    cudaGetSymbolAddress((void**)&ctxh, g_ctxh);
    cudaGetSymbolAddress((void**)&m1h,  g_m1h);
    cudaGetSymbolAddress((void**)&wtq,  g_wtq);
    cudaGetSymbolAddress((void**)&wtk,  g_wtk);
    cudaGetSymbolAddress((void**)&wtv,  g_wtv);
    cudaGetSymbolAddress((void**)&wto,  g_wto);
    cudaGetSymbolAddress((void**)&wt1,  g_wt1);
    cudaGetSymbolAddress((void**)&wt2,  g_wt2);

    cudaFuncSetAttribute(fattn_k, cudaFuncAttributeMaxDynamicSharedMemorySize,
                         ATTN_SMEM_BYTES);

    dim3 tb(32, 8);
    cvt_t_k<<<dim3(24, 24), tb>>>(Wq, wtq, C_EMB, C_EMB);
    cvt_t_k<<<dim3(24, 24), tb>>>(Wk, wtk, C_EMB, C_EMB);
    cvt_t_k<<<dim3(24, 24), tb>>>(Wv, wtv, C_EMB, C_EMB);
    cvt_t_k<<<dim3(24, 24), tb>>>(Wo, wto, C_EMB, C_EMB);
    cvt_t_k<<<dim3(96, 24), tb>>>(W1, wt1, C_EMB, F_FFN);   // [768,3072] -> [3072,768]
    cvt_t_k<<<dim3(24, 96), tb>>>(W2, wt2, F_FFN, C_EMB);   // [3072,768] -> [768,3072]

    dim3 gQKV(18, T_SEQ / 128);
    dim3 gF(F_FFN / 128, T_SEQ / 128);
    dim3 gSplit(C_EMB / 128, T_SEQ / 128, 2);
    int  gComb = T_SEQ * C_EMB / 4 / 256;

    layernorm_k<<<T_SEQ, 256>>>(x, ln1_g, ln1_b, h, hh);
    hgemm_qkv_k<<<gQKV, 256>>>(hh, wtq, bq, qh, wtk, bk, kh, wtv, bv, vh);
    fattn_k<<<dim3(T_SEQ / 128, N_HEAD), 256, ATTN_SMEM_BYTES>>>(qh, kh, vh, ctxh);
    hgemm_split_k<<<gSplit, 256>>>(ctxh, wto, part, C_EMB);
    combine_ln_k<<<T_SEQ, 256>>>(part, bo, h, ln2_g, ln2_b, h2, h2h);
    hgemm_gelu_h_k<<<gF, 256>>>(h2h, wt1, b1, m1h, F_FFN, C_EMB);
    hgemm_split_k<<<gSplit, 256>>>(m1h, wt2, part, F_FFN);
    combine_k<<<gComb, 256>>>(part, b2, h2, out);
}

// round 14
// speedup vs baseline: 1.7508x; 1.0639x over previous
#include <cuda_runtime.h>
#include <cuda_fp16.h>
#include <math.h>
#include <stdint.h>

#define T_SEQ 4096
#define C_EMB 768
#define N_HEAD 12
#define D_HEAD 64
#define F_FFN 3072

__device__ float  g_h  [T_SEQ * C_EMB];
__device__ float  g_h2 [T_SEQ * C_EMB];
__device__ float  g_part[2 * T_SEQ * C_EMB];
__device__ __half g_hh [T_SEQ * C_EMB];
__device__ __half g_h2h[T_SEQ * C_EMB];
__device__ __half g_qh [T_SEQ * C_EMB];
__device__ __half g_kh [T_SEQ * C_EMB];
__device__ __half g_vh [T_SEQ * C_EMB];
__device__ __half g_ctxh[T_SEQ * C_EMB];
__device__ __half g_m1h[T_SEQ * F_FFN];
__device__ __half g_wtq[C_EMB * C_EMB];
__device__ __half g_wtk[C_EMB * C_EMB];
__device__ __half g_wtv[C_EMB * C_EMB];
__device__ __half g_wto[C_EMB * C_EMB];
__device__ __half g_wt1[F_FFN * C_EMB];
__device__ __half g_wt2[C_EMB * F_FFN];

__device__ __forceinline__ uint32_t s2u(const void* p) {
    return (uint32_t)__cvta_generic_to_shared(p);
}
__device__ __forceinline__ uint32_t packh(float lo, float hi) {
    __half2 h = __floats2half2_rn(lo, hi);
    return *reinterpret_cast<uint32_t*>(&h);
}
__device__ __forceinline__ void mma_f16(float* d, const uint32_t* a, const uint32_t* b) {
    asm volatile(
        "mma.sync.aligned.m16n8k16.row.col.f32.f16.f16.f32 "
        "{%0,%1,%2,%3}, {%4,%5,%6,%7}, {%8,%9}, {%0,%1,%2,%3};\n"
        : "+f"(d[0]), "+f"(d[1]), "+f"(d[2]), "+f"(d[3])
        : "r"(a[0]), "r"(a[1]), "r"(a[2]), "r"(a[3]), "r"(b[0]), "r"(b[1]));
}
#define LDSM_X4(r0, r1, r2, r3, addr)                                          \
    asm volatile("ldmatrix.sync.aligned.m8n8.x4.shared.b16 {%0,%1,%2,%3}, [%4];" \
                 : "=r"(r0), "=r"(r1), "=r"(r2), "=r"(r3) : "r"(addr))
#define LDSM_X4_T(r0, r1, r2, r3, addr)                                        \
    asm volatile("ldmatrix.sync.aligned.m8n8.x4.trans.shared.b16 {%0,%1,%2,%3}, [%4];" \
                 : "=r"(r0), "=r"(r1), "=r"(r2), "=r"(r3) : "r"(addr))
__device__ __forceinline__ void cp_async16(uint32_t dst, const void* src) {
    asm volatile("cp.async.cg.shared.global [%0], [%1], 16;" :: "r"(dst), "l"(src));
}
#define CP_COMMIT() asm volatile("cp.async.commit_group;" ::: "memory")
#define CP_WAIT(n)  asm volatile("cp.async.wait_group %0;" :: "n"(n) : "memory")

__device__ __forceinline__ float gelu_exact(float v) {
    return 0.5f * v * (1.0f + erff(v * 0.70710678118654752440f));
}

// ----------------------------------------------------------------------------
// fused weight convert+transpose for all 6 matrices in one launch.
// blocks: 0..2303 -> Wq/Wk/Wv/Wo (576 each); 2304..4607 -> W1; 4608..6911 -> W2
// ----------------------------------------------------------------------------
__global__ __launch_bounds__(256) void cvt_all_k(
    const float* __restrict__ Wq, const float* __restrict__ Wk,
    const float* __restrict__ Wv, const float* __restrict__ Wo,
    const float* __restrict__ W1, const float* __restrict__ W2,
    __half* __restrict__ wtq, __half* __restrict__ wtk,
    __half* __restrict__ wtv, __half* __restrict__ wto,
    __half* __restrict__ wt1, __half* __restrict__ wt2)
{
    __shared__ float t[32][33];
    int id = blockIdx.x;
    const float* in; __half* outp; int R, Cc, bx, by;
    if (id < 2304) {
        int i = id / 576, rem = id % 576;
        in   = (i == 0) ? Wq : (i == 1) ? Wk : (i == 2) ? Wv : Wo;
        outp = (i == 0) ? wtq : (i == 1) ? wtk : (i == 2) ? wtv : wto;
        R = C_EMB; Cc = C_EMB; bx = (rem % 24) * 32; by = (rem / 24) * 32;
    } else if (id < 4608) {
        int rem = id - 2304;
        in = W1; outp = wt1; R = C_EMB; Cc = F_FFN;
        bx = (rem % 96) * 32; by = (rem / 96) * 32;
    } else {
        int rem = id - 4608;
        in = W2; outp = wt2; R = F_FFN; Cc = C_EMB;
        bx = (rem % 24) * 32; by = (rem / 24) * 32;
    }
    int tx = threadIdx.x & 31, ty = threadIdx.x >> 5;
#pragma unroll
    for (int i = 0; i < 4; i++)
        t[ty + i * 8][tx] = in[(size_t)(by + ty + i * 8) * Cc + bx + tx];
    __syncthreads();
#pragma unroll
    for (int i = 0; i < 4; i++)
        outp[(size_t)(bx + ty + i * 8) * R + by + tx] = __float2half_rn(t[tx][ty + i * 8]);
}

// ----------------------------------------------------------------------------
// LayerNorm (f32 + fp16 outputs)
// ----------------------------------------------------------------------------
__global__ __launch_bounds__(256) void layernorm_k(
    const float* __restrict__ in, const float* __restrict__ gamma,
    const float* __restrict__ beta, float* __restrict__ out,
    __half* __restrict__ outh)
{
    int row = blockIdx.x;
    const float* xr = in + (size_t)row * C_EMB;
    float s = 0.f, s2 = 0.f, v0[3];
#pragma unroll
    for (int i = 0; i < 3; i++) {
        float v = xr[threadIdx.x + i * 256];
        v0[i] = v; s += v; s2 += v * v;
    }
#pragma unroll
    for (int off = 16; off > 0; off >>= 1) {
        s  += __shfl_down_sync(0xffffffffu, s,  off);
        s2 += __shfl_down_sync(0xffffffffu, s2, off);
    }
    __shared__ float shs[8], shs2[8];
    int lane = threadIdx.x & 31, warp = threadIdx.x >> 5;
    if (lane == 0) { shs[warp] = s; shs2[warp] = s2; }
    __syncthreads();
    s = 0.f; s2 = 0.f;
#pragma unroll
    for (int i = 0; i < 8; i++) { s += shs[i]; s2 += shs2[i]; }
    float mu = s * (1.0f / C_EMB);
    float var = s2 * (1.0f / C_EMB) - mu * mu;
    float inv = rsqrtf(var + 1e-5f);
#pragma unroll
    for (int i = 0; i < 3; i++) {
        int c = threadIdx.x + i * 256;
        float v = (v0[i] - mu) * inv * gamma[c] + beta[c];
        out [(size_t)row * C_EMB + c] = v;
        outh[(size_t)row * C_EMB + c] = __float2half_rn(v);
    }
}

__global__ __launch_bounds__(256) void combine_ln_k(
    const float* __restrict__ part, const float* __restrict__ bias,
    const float* __restrict__ res, const float* __restrict__ gamma,
    const float* __restrict__ beta, float* __restrict__ out,
    __half* __restrict__ outh)
{
    int row = blockIdx.x;
    size_t base = (size_t)row * C_EMB;
    float s = 0.f, s2 = 0.f, v0[3];
#pragma unroll
    for (int i = 0; i < 3; i++) {
        int c = threadIdx.x + i * 256;
        float v = part[base + c] + part[(size_t)T_SEQ * C_EMB + base + c]
                + bias[c] + res[base + c];
        v0[i] = v; s += v; s2 += v * v;
    }
#pragma unroll
    for (int off = 16; off > 0; off >>= 1) {
        s  += __shfl_down_sync(0xffffffffu, s,  off);
        s2 += __shfl_down_sync(0xffffffffu, s2, off);
    }
    __shared__ float shs[8], shs2[8];
    int lane = threadIdx.x & 31, warp = threadIdx.x >> 5;
    if (lane == 0) { shs[warp] = s; shs2[warp] = s2; }
    __syncthreads();
    s = 0.f; s2 = 0.f;
#pragma unroll
    for (int i = 0; i < 8; i++) { s += shs[i]; s2 += shs2[i]; }
    float mu = s * (1.0f / C_EMB);
    float var = s2 * (1.0f / C_EMB) - mu * mu;
    float inv = rsqrtf(var + 1e-5f);
#pragma unroll
    for (int i = 0; i < 3; i++) {
        int c = threadIdx.x + i * 256;
        float v = (v0[i] - mu) * inv * gamma[c] + beta[c];
        out [base + c] = v;
        outh[base + c] = __float2half_rn(v);
    }
}

__global__ __launch_bounds__(256) void combine_k(
    const float* __restrict__ part, const float* __restrict__ bias,
    const float* __restrict__ res, float* __restrict__ out)
{
    int i = blockIdx.x * 256 + threadIdx.x;
    int col = (i * 4) % C_EMB;
    float4 a = ((const float4*)part)[i];
    float4 b = ((const float4*)(part + (size_t)T_SEQ * C_EMB))[i];
    float4 bi = *(const float4*)(bias + col);
    float4 r = ((const float4*)res)[i];
    float4 o;
    o.x = a.x + b.x + bi.x + r.x;
    o.y = a.y + b.y + bi.y + r.y;
    o.z = a.z + b.z + bi.z + r.z;
    o.w = a.w + b.w + bi.w + r.w;
    ((float4*)out)[i] = o;
}

// ----------------------------------------------------------------------------
// fp16 GEMM body (R13, unchanged)
// ----------------------------------------------------------------------------
template<int ACT, int PARTIAL, int OUTH>
__device__ __forceinline__ void hgemm_body(
    const __half* __restrict__ A, const __half* __restrict__ B,
    const float* __restrict__ bias, const float* __restrict__ res,
    float* __restrict__ C, __half* __restrict__ Ch,
    int N, int K, int kbeg, int klen, int bx, int by, float oscale)
{
    constexpr int S = 24;
    __shared__ __half As[2][128][S];
    __shared__ __half Bs[2][128][S];

    int tid = threadIdx.x, lane = tid & 31, wid = tid >> 5;
    int wm = wid & 1, wn = wid >> 1;
    int gid = lane >> 2, tig = lane & 3;
    int bm = by * 128, bn = bx * 128;

    int a_row  = wm * 64 + (lane & 15);
    int a_colh = (lane >> 4) << 3;
    int b_row  = wn * 32 + ((lane >> 4) << 3) + (lane & 7);
    int b_colh = ((lane >> 3) & 1) << 3;

    int l_r = tid >> 1, l_u = (tid & 1) * 8;

    float acc[4][4][4];
#pragma unroll
    for (int i = 0; i < 4; i++)
#pragma unroll
        for (int j = 0; j < 4; j++)
#pragma unroll
            for (int r = 0; r < 4; r++) acc[i][j][r] = 0.f;

    int nt = klen / 16;

    cp_async16(s2u(&As[0][l_r][l_u]), A + (size_t)(bm + l_r) * K + kbeg + l_u);
    cp_async16(s2u(&Bs[0][l_r][l_u]), B + (size_t)(bn + l_r) * K + kbeg + l_u);
    CP_COMMIT();

    for (int kt = 0; kt < nt; kt++) {
        int buf = kt & 1, nxt = buf ^ 1;
        bool has_next = (kt + 1 < nt);
        if (has_next) {
            int k0 = kbeg + (kt + 1) * 16;
            cp_async16(s2u(&As[nxt][l_r][l_u]), A + (size_t)(bm + l_r) * K + k0 + l_u);
            cp_async16(s2u(&Bs[nxt][l_r][l_u]), B + (size_t)(bn + l_r) * K + k0 + l_u);
            CP_COMMIT();
            CP_WAIT(1);
        } else {
            CP_WAIT(0);
        }
        __syncthreads();

        uint32_t af[4][4];
#pragma unroll
        for (int mt = 0; mt < 4; mt++) {
            uint32_t addr = s2u(&As[buf][a_row + mt * 16][a_colh]);
            LDSM_X4(af[mt][0], af[mt][1], af[mt][2], af[mt][3], addr);
        }
        uint32_t bf[4][2];
#pragma unroll
        for (int np = 0; np < 2; np++) {
            uint32_t addr = s2u(&Bs[buf][b_row + np * 16][b_colh]);
            LDSM_X4(bf[2 * np][0], bf[2 * np][1],
                    bf[2 * np + 1][0], bf[2 * np + 1][1], addr);
        }
#pragma unroll
        for (int mt = 0; mt < 4; mt++)
#pragma unroll
            for (int ntl = 0; ntl < 4; ntl++)
                mma_f16(acc[mt][ntl], af[mt], bf[ntl]);
        __syncthreads();
    }

#pragma unroll
    for (int mt = 0; mt < 4; mt++) {
#pragma unroll
        for (int ntl = 0; ntl < 4; ntl++) {
            int row = bm + wm * 64 + mt * 16 + gid;
            int col = bn + wn * 32 + ntl * 8 + tig * 2;
            if (OUTH) {
                float v0 = acc[mt][ntl][0] + bias[col];
                float v1 = acc[mt][ntl][1] + bias[col + 1];
                float v2 = acc[mt][ntl][2] + bias[col];
                float v3 = acc[mt][ntl][3] + bias[col + 1];
                if (ACT == 1) {
                    v0 = gelu_exact(v0); v1 = gelu_exact(v1);
                    v2 = gelu_exact(v2); v3 = gelu_exact(v3);
                }
                v0 *= oscale; v1 *= oscale; v2 *= oscale; v3 *= oscale;
                *(uint32_t*)&Ch[(size_t)row * N + col]       = packh(v0, v1);
                *(uint32_t*)&Ch[(size_t)(row + 8) * N + col] = packh(v2, v3);
            } else {
#pragma unroll
                for (int r = 0; r < 4; r++) {
                    int rr = row + (r >> 1) * 8;
                    int cc = col + (r & 1);
                    float v = acc[mt][ntl][r];
                    if (!PARTIAL) {
                        v += bias[cc];
                        if (res) v += res[(size_t)rr * N + cc];
                        if (ACT == 1) v = gelu_exact(v);
                    }
                    C[(size_t)rr * N + cc] = v;
                }
            }
        }
    }
}

__global__ __launch_bounds__(256) void hgemm_gelu_h_k(
    const __half* __restrict__ A, const __half* __restrict__ B,
    const float* __restrict__ bias, __half* __restrict__ Ch, int N, int K)
{
    hgemm_body<1, 0, 1>(A, B, bias, nullptr, nullptr, Ch, N, K, 0, K,
                        blockIdx.x, blockIdx.y, 1.0f);
}

__global__ __launch_bounds__(256) void hgemm_qkv_k(
    const __half* __restrict__ A,
    const __half* __restrict__ B0, const float* __restrict__ b0, __half* __restrict__ C0,
    const __half* __restrict__ B1, const float* __restrict__ b1, __half* __restrict__ C1,
    const __half* __restrict__ B2, const float* __restrict__ b2, __half* __restrict__ C2)
{
    int sel = blockIdx.x / 6, bx = blockIdx.x % 6;
    const __half* B  = (sel == 0) ? B0 : (sel == 1) ? B1 : B2;
    const float*  bb = (sel == 0) ? b0 : (sel == 1) ? b1 : b2;
    __half*       Ch = (sel == 0) ? C0 : (sel == 1) ? C1 : C2;
    float sc = (sel == 0) ? 0.125f : 1.0f;
    hgemm_body<0, 0, 1>(A, B, bb, nullptr, nullptr, Ch, C_EMB, C_EMB, 0, C_EMB,
                        bx, blockIdx.y, sc);
}

__global__ __launch_bounds__(256) void hgemm_split_k(
    const __half* __restrict__ A, const __half* __restrict__ B,
    float* __restrict__ part, int K)
{
    int z = blockIdx.z;
    hgemm_body<0, 1, 0>(A, B, nullptr, nullptr,
                        part + (size_t)z * T_SEQ * C_EMB, nullptr,
                        C_EMB, K, z * (K / 2), K / 2, blockIdx.x, blockIdx.y, 1.0f);
}

// ----------------------------------------------------------------------------
// Flash attention fp16, P kept in registers (C-frag == A-frag layout).
// smem: only K/V double buffers. Fixed causal gate.
// ----------------------------------------------------------------------------
#define AKS 72
#define ATTN_SMEM_BYTES ((2 * 64 * AKS + 2 * 64 * AKS) * 2)

__global__ __launch_bounds__(256, 2) void fattn_k(
    const __half* __restrict__ Qh, const __half* __restrict__ Kh,
    const __half* __restrict__ Vh, __half* __restrict__ Oh)
{
    extern __shared__ __half smh[];
    __half* KsB = smh;                       // [2][64][72]
    __half* VsB = KsB + 2 * 64 * AKS;        // [2][64][72]

    int hd = blockIdx.y;
    int qt = (int)gridDim.x - 1 - (int)blockIdx.x;
    int tid = threadIdx.x, w = tid >> 5, lane = tid & 31;
    int gid = lane >> 2, tig = lane & 3;
    int rbase = qt * 128 + w * 16;

    int bs_row = ((lane >> 4) << 3) + (lane & 7);
    int bs_colh = ((lane >> 3) & 1) << 3;
    int vt_row = lane & 15;
    int vt_colh = (lane >> 4) << 3;

    uint32_t aq[4][4];
    {
        const __half* qp = Qh + (size_t)rbase * C_EMB + hd * D_HEAD;
#pragma unroll
        for (int kk = 0; kk < 4; kk++) {
            aq[kk][0] = *(const uint32_t*)(qp + (size_t)gid * C_EMB + kk * 16 + 2 * tig);
            aq[kk][1] = *(const uint32_t*)(qp + (size_t)(gid + 8) * C_EMB + kk * 16 + 2 * tig);
            aq[kk][2] = *(const uint32_t*)(qp + (size_t)gid * C_EMB + kk * 16 + 2 * tig + 8);
            aq[kk][3] = *(const uint32_t*)(qp + (size_t)(gid + 8) * C_EMB + kk * 16 + 2 * tig + 8);
        }
    }

    float oacc[8][4];
#pragma unroll
    for (int i = 0; i < 8; i++)
#pragma unroll
        for (int r = 0; r < 4; r++) oacc[i][r] = 0.f;
    float m_lo = -1e30f, m_hi = -1e30f, l_lo = 0.f, l_hi = 0.f;
    int row0 = rbase + gid, row1 = row0 + 8;

    int kb_last = 2 * qt + 1;

#pragma unroll
    for (int i = 0; i < 2; i++) {
        int id = tid + i * 256;
        int rr = id >> 3, it = id & 7;
        cp_async16(s2u(KsB + rr * AKS + it * 8),
                   Kh + (size_t)rr * C_EMB + hd * D_HEAD + it * 8);
        cp_async16(s2u(VsB + rr * AKS + it * 8),
                   Vh + (size_t)rr * C_EMB + hd * D_HEAD + it * 8);
    }
    CP_COMMIT();

    for (int kb = 0; kb <= kb_last; kb++) {
        int cur = kb & 1;
        if (kb < kb_last) {
            int nb = (kb + 1) & 1;
            int nbase = (kb + 1) * 64;
#pragma unroll
            for (int i = 0; i < 2; i++) {
                int id = tid + i * 256;
                int rr = id >> 3, it = id & 7;
                cp_async16(s2u(KsB + (nb * 64 + rr) * AKS + it * 8),
                           Kh + (size_t)(nbase + rr) * C_EMB + hd * D_HEAD + it * 8);
                cp_async16(s2u(VsB + (nb * 64 + rr) * AKS + it * 8),
                           Vh + (size_t)(nbase + rr) * C_EMB + hd * D_HEAD + it * 8);
            }
            CP_COMMIT();
            CP_WAIT(1);
        } else {
            CP_WAIT(0);
        }
        __syncthreads();

        __half* Ks = KsB + cur * 64 * AKS;
        __half* Vs = VsB + cur * 64 * AKS;
        int kbase = kb * 64;

        if (kbase <= rbase + 15) {
            float sacc[8][4];
#pragma unroll
            for (int n = 0; n < 8; n++)
#pragma unroll
                for (int r = 0; r < 4; r++) sacc[n][r] = 0.f;
#pragma unroll
            for (int kk = 0; kk < 4; kk++) {
#pragma unroll
                for (int np = 0; np < 4; np++) {
                    uint32_t b4[4];
                    uint32_t addr = s2u(&Ks[(np * 16 + bs_row) * AKS + kk * 16 + bs_colh]);
                    LDSM_X4(b4[0], b4[1], b4[2], b4[3], addr);
                    mma_f16(sacc[2 * np],     aq[kk], b4);
                    mma_f16(sacc[2 * np + 1], aq[kk], b4 + 2);
                }
            }

            bool boundary = (kbase + 63 > rbase);
            float ml0 = -1e30f, ml1 = -1e30f;
#pragma unroll
            for (int n = 0; n < 8; n++) {
                if (boundary) {
                    int c = kbase + n * 8 + 2 * tig;
                    if (c     > row0) sacc[n][0] = -1e30f;
                    if (c + 1 > row0) sacc[n][1] = -1e30f;
                    if (c     > row1) sacc[n][2] = -1e30f;
                    if (c + 1 > row1) sacc[n][3] = -1e30f;
                }
                ml0 = fmaxf(ml0, fmaxf(sacc[n][0], sacc[n][1]));
                ml1 = fmaxf(ml1, fmaxf(sacc[n][2], sacc[n][3]));
            }
            ml0 = fmaxf(ml0, __shfl_xor_sync(0xffffffffu, ml0, 1));
            ml0 = fmaxf(ml0, __shfl_xor_sync(0xffffffffu, ml0, 2));
            ml1 = fmaxf(ml1, __shfl_xor_sync(0xffffffffu, ml1, 1));
            ml1 = fmaxf(ml1, __shfl_xor_sync(0xffffffffu, ml1, 2));
            float mn0 = fmaxf(m_lo, ml0), mn1 = fmaxf(m_hi, ml1);
            float al0 = __expf(m_lo - mn0), al1 = __expf(m_hi - mn1);
            m_lo = mn0; m_hi = mn1;

            // exp in place; accumulate row sums
            float ls0 = 0.f, ls1 = 0.f;
#pragma unroll
            for (int n = 0; n < 8; n++) {
                sacc[n][0] = __expf(sacc[n][0] - mn0);
                sacc[n][1] = __expf(sacc[n][1] - mn0);
                sacc[n][2] = __expf(sacc[n][2] - mn1);
                sacc[n][3] = __expf(sacc[n][3] - mn1);
                ls0 += sacc[n][0] + sacc[n][1];
                ls1 += sacc[n][2] + sacc[n][3];
            }
            ls0 += __shfl_xor_sync(0xffffffffu, ls0, 1);
            ls0 += __shfl_xor_sync(0xffffffffu, ls0, 2);
            ls1 += __shfl_xor_sync(0xffffffffu, ls1, 1);
            ls1 += __shfl_xor_sync(0xffffffffu, ls1, 2);
            l_lo = l_lo * al0 + ls0;
            l_hi = l_hi * al1 + ls1;
#pragma unroll
            for (int n = 0; n < 8; n++) {
                oacc[n][0] *= al0; oacc[n][1] *= al0;
                oacc[n][2] *= al1; oacc[n][3] *= al1;
            }

            // O += P V : P a-frags built in registers (C-frag == A-frag layout)
#pragma unroll
            for (int kt = 0; kt < 4; kt++) {
                uint32_t ap[4];
                ap[0] = packh(sacc[2 * kt][0],     sacc[2 * kt][1]);
                ap[1] = packh(sacc[2 * kt][2],     sacc[2 * kt][3]);
                ap[2] = packh(sacc[2 * kt + 1][0], sacc[2 * kt + 1][1]);
                ap[3] = packh(sacc[2 * kt + 1][2], sacc[2 * kt + 1][3]);
#pragma unroll
                for (int np2 = 0; np2 < 4; np2++) {
                    uint32_t b4[4];
                    uint32_t va = s2u(&Vs[(kt * 16 + vt_row) * AKS + np2 * 16 + vt_colh]);
                    LDSM_X4_T(b4[0], b4[1], b4[2], b4[3], va);
                    mma_f16(oacc[2 * np2],     ap, b4);
                    mma_f16(oacc[2 * np2 + 1], ap, b4 + 2);
                }
            }
        }
        __syncthreads();
    }

    float inv0 = 1.0f / l_lo, inv1 = 1.0f / l_hi;
    __half* o0 = Oh + (size_t)row0 * C_EMB + hd * D_HEAD;
    __half* o1 = Oh + (size_t)row1 * C_EMB + hd * D_HEAD;
#pragma unroll
    for (int n = 0; n < 8; n++) {
        int c = n * 8 + 2 * tig;
        *(uint32_t*)(o0 + c) = packh(oacc[n][0] * inv0, oacc[n][1] * inv0);
        *(uint32_t*)(o1 + c) = packh(oacc[n][2] * inv1, oacc[n][3] * inv1);
    }
}

// ----------------------------------------------------------------------------
// launch
// ----------------------------------------------------------------------------
extern "C" void kernel_launch(void* const* d_in, const int* in_sizes, int n_in,
                              void* d_out, int out_size)
{
    const float* x     = (const float*)d_in[0];
    const float* Wq    = (const float*)d_in[1];
    const float* bq    = (const float*)d_in[2];
    const float* Wk    = (const float*)d_in[3];
    const float* bk    = (const float*)d_in[4];
    const float* Wv    = (const float*)d_in[5];
    const float* bv    = (const float*)d_in[6];
    const float* Wo    = (const float*)d_in[7];
    const float* bo    = (const float*)d_in[8];
    const float* ln1_g = (const float*)d_in[9];
    const float* ln1_b = (const float*)d_in[10];
    const float* ln2_g = (const float*)d_in[11];
    const float* ln2_b = (const float*)d_in[12];
    const float* W1    = (const float*)d_in[13];
    const float* b1    = (const float*)d_in[14];
    const float* W2    = (const float*)d_in[15];
    const float* b2    = (const float*)d_in[16];
    float* out = (float*)d_out;

    float *h, *h2, *part;
    __half *hh, *h2h, *qh, *kh, *vh, *ctxh, *m1h;
    __half *wtq, *wtk, *wtv, *wto, *wt1, *wt2;
    cudaGetSymbolAddress((void**)&h,    g_h);
    cudaGetSymbolAddress((void**)&h2,   g_h2);
    cudaGetSymbolAddress((void**)&part, g_part);
    cudaGetSymbolAddress((void**)&hh,   g_hh);
    cudaGetSymbolAddress((void**)&h2h,  g_h2h);
    cudaGetSymbolAddress((void**)&qh,   g_qh);
    cudaGetSymbolAddress((void**)&kh,   g_kh);
    cudaGetSymbolAddress((void**)&vh,   g_vh);
    cudaGetSymbolAddress((void**)&ctxh, g_ctxh);
    cudaGetSymbolAddress((void**)&m1h,  g_m1h);
    cudaGetSymbolAddress((void**)&wtq,  g_wtq);
    cudaGetSymbolAddress((void**)&wtk,  g_wtk);
    cudaGetSymbolAddress((void**)&wtv,  g_wtv);
    cudaGetSymbolAddress((void**)&wto,  g_wto);
    cudaGetSymbolAddress((void**)&wt1,  g_wt1);
    cudaGetSymbolAddress((void**)&wt2,  g_wt2);

    cudaFuncSetAttribute(fattn_k, cudaFuncAttributeMaxDynamicSharedMemorySize,
                         ATTN_SMEM_BYTES);

    cvt_all_k<<<6912, 256>>>(Wq, Wk, Wv, Wo, W1, W2,
                             wtq, wtk, wtv, wto, wt1, wt2);

    dim3 gQKV(18, T_SEQ / 128);
    dim3 gF(F_FFN / 128, T_SEQ / 128);
    dim3 gSplit(C_EMB / 128, T_SEQ / 128, 2);
    int  gComb = T_SEQ * C_EMB / 4 / 256;

    layernorm_k<<<T_SEQ, 256>>>(x, ln1_g, ln1_b, h, hh);
    hgemm_qkv_k<<<gQKV, 256>>>(hh, wtq, bq, qh, wtk, bk, kh, wtv, bv, vh);
    fattn_k<<<dim3(T_SEQ / 128, N_HEAD), 256, ATTN_SMEM_BYTES>>>(qh, kh, vh, ctxh);
    hgemm_split_k<<<gSplit, 256>>>(ctxh, wto, part, C_EMB);
    combine_ln_k<<<T_SEQ, 256>>>(part, bo, h, ln2_g, ln2_b, h2, h2h);
    hgemm_gelu_h_k<<<gF, 256>>>(h2h, wt1, b1, m1h, F_FFN, C_EMB);
    hgemm_split_k<<<gSplit, 256>>>(m1h, wt2, part, F_FFN);
    combine_k<<<gComb, 256>>>(part, b2, h2, out);
}

// round 15
// speedup vs baseline: 1.8106x; 1.0342x over previous
#include <cuda_runtime.h>
#include <cuda_fp16.h>
#include <math.h>
#include <stdint.h>

#define T_SEQ 4096
#define C_EMB 768
#define N_HEAD 12
#define D_HEAD 64
#define F_FFN 3072

__device__ float  g_h  [T_SEQ * C_EMB];
__device__ float  g_h2 [T_SEQ * C_EMB];
__device__ float  g_part[2 * T_SEQ * C_EMB];
__device__ __half g_hh [T_SEQ * C_EMB];
__device__ __half g_h2h[T_SEQ * C_EMB];
__device__ __half g_qh [T_SEQ * C_EMB];
__device__ __half g_kh [T_SEQ * C_EMB];
__device__ __half g_vh [T_SEQ * C_EMB];
__device__ __half g_ctxh[T_SEQ * C_EMB];
__device__ __half g_m1h[T_SEQ * F_FFN];
__device__ __half g_wtq[C_EMB * C_EMB];
__device__ __half g_wtk[C_EMB * C_EMB];
__device__ __half g_wtv[C_EMB * C_EMB];
__device__ __half g_wto[C_EMB * C_EMB];
__device__ __half g_wt1[F_FFN * C_EMB];
__device__ __half g_wt2[C_EMB * F_FFN];

__device__ __forceinline__ uint32_t s2u(const void* p) {
    return (uint32_t)__cvta_generic_to_shared(p);
}
__device__ __forceinline__ uint32_t packh(float lo, float hi) {
    __half2 h = __floats2half2_rn(lo, hi);
    return *reinterpret_cast<uint32_t*>(&h);
}
__device__ __forceinline__ void mma_f16(float* d, const uint32_t* a, const uint32_t* b) {
    asm volatile(
        "mma.sync.aligned.m16n8k16.row.col.f32.f16.f16.f32 "
        "{%0,%1,%2,%3}, {%4,%5,%6,%7}, {%8,%9}, {%0,%1,%2,%3};\n"
        : "+f"(d[0]), "+f"(d[1]), "+f"(d[2]), "+f"(d[3])
        : "r"(a[0]), "r"(a[1]), "r"(a[2]), "r"(a[3]), "r"(b[0]), "r"(b[1]));
}
#define LDSM_X4(r0, r1, r2, r3, addr)                                          \
    asm volatile("ldmatrix.sync.aligned.m8n8.x4.shared.b16 {%0,%1,%2,%3}, [%4];" \
                 : "=r"(r0), "=r"(r1), "=r"(r2), "=r"(r3) : "r"(addr))
#define LDSM_X4_T(r0, r1, r2, r3, addr)                                        \
    asm volatile("ldmatrix.sync.aligned.m8n8.x4.trans.shared.b16 {%0,%1,%2,%3}, [%4];" \
                 : "=r"(r0), "=r"(r1), "=r"(r2), "=r"(r3) : "r"(addr))
__device__ __forceinline__ void cp_async16(uint32_t dst, const void* src) {
    asm volatile("cp.async.cg.shared.global [%0], [%1], 16;" :: "r"(dst), "l"(src));
}
#define CP_COMMIT() asm volatile("cp.async.commit_group;" ::: "memory")
#define CP_WAIT(n)  asm volatile("cp.async.wait_group %0;" :: "n"(n) : "memory")

__device__ __forceinline__ float gelu_exact(float v) {
    return 0.5f * v * (1.0f + erff(v * 0.70710678118654752440f));
}

// ----------------------------------------------------------------------------
// fused weight convert+transpose (R14)
// ----------------------------------------------------------------------------
__global__ __launch_bounds__(256) void cvt_all_k(
    const float* __restrict__ Wq, const float* __restrict__ Wk,
    const float* __restrict__ Wv, const float* __restrict__ Wo,
    const float* __restrict__ W1, const float* __restrict__ W2,
    __half* __restrict__ wtq, __half* __restrict__ wtk,
    __half* __restrict__ wtv, __half* __restrict__ wto,
    __half* __restrict__ wt1, __half* __restrict__ wt2)
{
    __shared__ float t[32][33];
    int id = blockIdx.x;
    const float* in; __half* outp; int R, Cc, bx, by;
    if (id < 2304) {
        int i = id / 576, rem = id % 576;
        in   = (i == 0) ? Wq : (i == 1) ? Wk : (i == 2) ? Wv : Wo;
        outp = (i == 0) ? wtq : (i == 1) ? wtk : (i == 2) ? wtv : wto;
        R = C_EMB; Cc = C_EMB; bx = (rem % 24) * 32; by = (rem / 24) * 32;
    } else if (id < 4608) {
        int rem = id - 2304;
        in = W1; outp = wt1; R = C_EMB; Cc = F_FFN;
        bx = (rem % 96) * 32; by = (rem / 96) * 32;
    } else {
        int rem = id - 4608;
        in = W2; outp = wt2; R = F_FFN; Cc = C_EMB;
        bx = (rem % 24) * 32; by = (rem / 24) * 32;
    }
    int tx = threadIdx.x & 31, ty = threadIdx.x >> 5;
#pragma unroll
    for (int i = 0; i < 4; i++)
        t[ty + i * 8][tx] = in[(size_t)(by + ty + i * 8) * Cc + bx + tx];
    __syncthreads();
#pragma unroll
    for (int i = 0; i < 4; i++)
        outp[(size_t)(bx + ty + i * 8) * R + by + tx] = __float2half_rn(t[tx][ty + i * 8]);
}

// ----------------------------------------------------------------------------
// LayerNorm / combine kernels (R14)
// ----------------------------------------------------------------------------
__global__ __launch_bounds__(256) void layernorm_k(
    const float* __restrict__ in, const float* __restrict__ gamma,
    const float* __restrict__ beta, float* __restrict__ out,
    __half* __restrict__ outh)
{
    int row = blockIdx.x;
    const float* xr = in + (size_t)row * C_EMB;
    float s = 0.f, s2 = 0.f, v0[3];
#pragma unroll
    for (int i = 0; i < 3; i++) {
        float v = xr[threadIdx.x + i * 256];
        v0[i] = v; s += v; s2 += v * v;
    }
#pragma unroll
    for (int off = 16; off > 0; off >>= 1) {
        s  += __shfl_down_sync(0xffffffffu, s,  off);
        s2 += __shfl_down_sync(0xffffffffu, s2, off);
    }
    __shared__ float shs[8], shs2[8];
    int lane = threadIdx.x & 31, warp = threadIdx.x >> 5;
    if (lane == 0) { shs[warp] = s; shs2[warp] = s2; }
    __syncthreads();
    s = 0.f; s2 = 0.f;
#pragma unroll
    for (int i = 0; i < 8; i++) { s += shs[i]; s2 += shs2[i]; }
    float mu = s * (1.0f / C_EMB);
    float var = s2 * (1.0f / C_EMB) - mu * mu;
    float inv = rsqrtf(var + 1e-5f);
#pragma unroll
    for (int i = 0; i < 3; i++) {
        int c = threadIdx.x + i * 256;
        float v = (v0[i] - mu) * inv * gamma[c] + beta[c];
        out [(size_t)row * C_EMB + c] = v;
        outh[(size_t)row * C_EMB + c] = __float2half_rn(v);
    }
}

__global__ __launch_bounds__(256) void combine_ln_k(
    const float* __restrict__ part, const float* __restrict__ bias,
    const float* __restrict__ res, const float* __restrict__ gamma,
    const float* __restrict__ beta, float* __restrict__ out,
    __half* __restrict__ outh)
{
    int row = blockIdx.x;
    size_t base = (size_t)row * C_EMB;
    float s = 0.f, s2 = 0.f, v0[3];
#pragma unroll
    for (int i = 0; i < 3; i++) {
        int c = threadIdx.x + i * 256;
        float v = part[base + c] + part[(size_t)T_SEQ * C_EMB + base + c]
                + bias[c] + res[base + c];
        v0[i] = v; s += v; s2 += v * v;
    }
#pragma unroll
    for (int off = 16; off > 0; off >>= 1) {
        s  += __shfl_down_sync(0xffffffffu, s,  off);
        s2 += __shfl_down_sync(0xffffffffu, s2, off);
    }
    __shared__ float shs[8], shs2[8];
    int lane = threadIdx.x & 31, warp = threadIdx.x >> 5;
    if (lane == 0) { shs[warp] = s; shs2[warp] = s2; }
    __syncthreads();
    s = 0.f; s2 = 0.f;
#pragma unroll
    for (int i = 0; i < 8; i++) { s += shs[i]; s2 += shs2[i]; }
    float mu = s * (1.0f / C_EMB);
    float var = s2 * (1.0f / C_EMB) - mu * mu;
    float inv = rsqrtf(var + 1e-5f);
#pragma unroll
    for (int i = 0; i < 3; i++) {
        int c = threadIdx.x + i * 256;
        float v = (v0[i] - mu) * inv * gamma[c] + beta[c];
        out [base + c] = v;
        outh[base + c] = __float2half_rn(v);
    }
}

__global__ __launch_bounds__(256) void combine_k(
    const float* __restrict__ part, const float* __restrict__ bias,
    const float* __restrict__ res, float* __restrict__ out)
{
    int i = blockIdx.x * 256 + threadIdx.x;
    int col = (i * 4) % C_EMB;
    float4 a = ((const float4*)part)[i];
    float4 b = ((const float4*)(part + (size_t)T_SEQ * C_EMB))[i];
    float4 bi = *(const float4*)(bias + col);
    float4 r = ((const float4*)res)[i];
    float4 o;
    o.x = a.x + b.x + bi.x + r.x;
    o.y = a.y + b.y + bi.y + r.y;
    o.z = a.z + b.z + bi.z + r.z;
    o.w = a.w + b.w + bi.w + r.w;
    ((float4*)out)[i] = o;
}

// ----------------------------------------------------------------------------
// fp16 GEMM body, BK=32 (2 k-steps per stage, half the barriers of R14).
// A[M,K] half, B[N,K] half. Stride 40 halves (= 20 words, conflict-free).
// Per stage each thread cp.asyncs 2 units for A and 2 for B.
// ----------------------------------------------------------------------------
template<int ACT, int PARTIAL, int OUTH>
__device__ __forceinline__ void hgemm_body(
    const __half* __restrict__ A, const __half* __restrict__ B,
    const float* __restrict__ bias, const float* __restrict__ res,
    float* __restrict__ C, __half* __restrict__ Ch,
    int N, int K, int kbeg, int klen, int bx, int by, float oscale)
{
    constexpr int S = 40;                  // 32 + 8 pad halves
    __shared__ __half As[2][128][S];
    __shared__ __half Bs[2][128][S];

    int tid = threadIdx.x, lane = tid & 31, wid = tid >> 5;
    int wm = wid & 1, wn = wid >> 1;
    int gid = lane >> 2, tig = lane & 3;
    int bm = by * 128, bn = bx * 128;

    int a_row  = wm * 64 + (lane & 15);
    int a_colh = (lane >> 4) << 3;
    int b_row  = wn * 32 + ((lane >> 4) << 3) + (lane & 7);
    int b_colh = ((lane >> 3) & 1) << 3;

    int l_r = tid >> 1, l_h = (tid & 1) * 16;   // two 8-half units at l_h, l_h+8

    float acc[4][4][4];
#pragma unroll
    for (int i = 0; i < 4; i++)
#pragma unroll
        for (int j = 0; j < 4; j++)
#pragma unroll
            for (int r = 0; r < 4; r++) acc[i][j][r] = 0.f;

    int nt = klen / 32;

    cp_async16(s2u(&As[0][l_r][l_h]),     A + (size_t)(bm + l_r) * K + kbeg + l_h);
    cp_async16(s2u(&As[0][l_r][l_h + 8]), A + (size_t)(bm + l_r) * K + kbeg + l_h + 8);
    cp_async16(s2u(&Bs[0][l_r][l_h]),     B + (size_t)(bn + l_r) * K + kbeg + l_h);
    cp_async16(s2u(&Bs[0][l_r][l_h + 8]), B + (size_t)(bn + l_r) * K + kbeg + l_h + 8);
    CP_COMMIT();

    for (int kt = 0; kt < nt; kt++) {
        int buf = kt & 1, nxt = buf ^ 1;
        bool has_next = (kt + 1 < nt);
        if (has_next) {
            int k0 = kbeg + (kt + 1) * 32;
            cp_async16(s2u(&As[nxt][l_r][l_h]),     A + (size_t)(bm + l_r) * K + k0 + l_h);
            cp_async16(s2u(&As[nxt][l_r][l_h + 8]), A + (size_t)(bm + l_r) * K + k0 + l_h + 8);
            cp_async16(s2u(&Bs[nxt][l_r][l_h]),     B + (size_t)(bn + l_r) * K + k0 + l_h);
            cp_async16(s2u(&Bs[nxt][l_r][l_h + 8]), B + (size_t)(bn + l_r) * K + k0 + l_h + 8);
            CP_COMMIT();
            CP_WAIT(1);
        } else {
            CP_WAIT(0);
        }
        __syncthreads();

#pragma unroll
        for (int ks = 0; ks < 2; ks++) {
            int kk = ks * 16;
            uint32_t af[4][4];
#pragma unroll
            for (int mt = 0; mt < 4; mt++) {
                uint32_t addr = s2u(&As[buf][a_row + mt * 16][kk + a_colh]);
                LDSM_X4(af[mt][0], af[mt][1], af[mt][2], af[mt][3], addr);
            }
            uint32_t bf[4][2];
#pragma unroll
            for (int np = 0; np < 2; np++) {
                uint32_t addr = s2u(&Bs[buf][b_row + np * 16][kk + b_colh]);
                LDSM_X4(bf[2 * np][0], bf[2 * np][1],
                        bf[2 * np + 1][0], bf[2 * np + 1][1], addr);
            }
#pragma unroll
            for (int mt = 0; mt < 4; mt++)
#pragma unroll
                for (int ntl = 0; ntl < 4; ntl++)
                    mma_f16(acc[mt][ntl], af[mt], bf[ntl]);
        }
        __syncthreads();
    }

#pragma unroll
    for (int mt = 0; mt < 4; mt++) {
#pragma unroll
        for (int ntl = 0; ntl < 4; ntl++) {
            int row = bm + wm * 64 + mt * 16 + gid;
            int col = bn + wn * 32 + ntl * 8 + tig * 2;
            if (OUTH) {
                float v0 = acc[mt][ntl][0] + bias[col];
                float v1 = acc[mt][ntl][1] + bias[col + 1];
                float v2 = acc[mt][ntl][2] + bias[col];
                float v3 = acc[mt][ntl][3] + bias[col + 1];
                if (ACT == 1) {
                    v0 = gelu_exact(v0); v1 = gelu_exact(v1);
                    v2 = gelu_exact(v2); v3 = gelu_exact(v3);
                }
                v0 *= oscale; v1 *= oscale; v2 *= oscale; v3 *= oscale;
                *(uint32_t*)&Ch[(size_t)row * N + col]       = packh(v0, v1);
                *(uint32_t*)&Ch[(size_t)(row + 8) * N + col] = packh(v2, v3);
            } else {
#pragma unroll
                for (int r = 0; r < 4; r++) {
                    int rr = row + (r >> 1) * 8;
                    int cc = col + (r & 1);
                    float v = acc[mt][ntl][r];
                    if (!PARTIAL) {
                        v += bias[cc];
                        if (res) v += res[(size_t)rr * N + cc];
                        if (ACT == 1) v = gelu_exact(v);
                    }
                    C[(size_t)rr * N + cc] = v;
                }
            }
        }
    }
}

__global__ __launch_bounds__(256) void hgemm_gelu_h_k(
    const __half* __restrict__ A, const __half* __restrict__ B,
    const float* __restrict__ bias, __half* __restrict__ Ch, int N, int K)
{
    hgemm_body<1, 0, 1>(A, B, bias, nullptr, nullptr, Ch, N, K, 0, K,
                        blockIdx.x, blockIdx.y, 1.0f);
}

__global__ __launch_bounds__(256) void hgemm_qkv_k(
    const __half* __restrict__ A,
    const __half* __restrict__ B0, const float* __restrict__ b0, __half* __restrict__ C0,
    const __half* __restrict__ B1, const float* __restrict__ b1, __half* __restrict__ C1,
    const __half* __restrict__ B2, const float* __restrict__ b2, __half* __restrict__ C2)
{
    int sel = blockIdx.x / 6, bx = blockIdx.x % 6;
    const __half* B  = (sel == 0) ? B0 : (sel == 1) ? B1 : B2;
    const float*  bb = (sel == 0) ? b0 : (sel == 1) ? b1 : b2;
    __half*       Ch = (sel == 0) ? C0 : (sel == 1) ? C1 : C2;
    // q pre-scaled by (1/sqrt(D)) * log2(e) for exp2-domain softmax
    float sc = (sel == 0) ? 0.125f * 1.44269504088896f : 1.0f;
    hgemm_body<0, 0, 1>(A, B, bb, nullptr, nullptr, Ch, C_EMB, C_EMB, 0, C_EMB,
                        bx, blockIdx.y, sc);
}

__global__ __launch_bounds__(256) void hgemm_split_k(
    const __half* __restrict__ A, const __half* __restrict__ B,
    float* __restrict__ part, int K)
{
    int z = blockIdx.z;
    hgemm_body<0, 1, 0>(A, B, nullptr, nullptr,
                        part + (size_t)z * T_SEQ * C_EMB, nullptr,
                        C_EMB, K, z * (K / 2), K / 2, blockIdx.x, blockIdx.y, 1.0f);
}

// ----------------------------------------------------------------------------
// Flash attention fp16, register-P (R14), exp2-domain softmax.
// ----------------------------------------------------------------------------
#define AKS 72
#define ATTN_SMEM_BYTES ((2 * 64 * AKS + 2 * 64 * AKS) * 2)

__global__ __launch_bounds__(256, 2) void fattn_k(
    const __half* __restrict__ Qh, const __half* __restrict__ Kh,
    const __half* __restrict__ Vh, __half* __restrict__ Oh)
{
    extern __shared__ __half smh[];
    __half* KsB = smh;
    __half* VsB = KsB + 2 * 64 * AKS;

    int hd = blockIdx.y;
    int qt = (int)gridDim.x - 1 - (int)blockIdx.x;
    int tid = threadIdx.x, w = tid >> 5, lane = tid & 31;
    int gid = lane >> 2, tig = lane & 3;
    int rbase = qt * 128 + w * 16;

    int bs_row = ((lane >> 4) << 3) + (lane & 7);
    int bs_colh = ((lane >> 3) & 1) << 3;
    int vt_row = lane & 15;
    int vt_colh = (lane >> 4) << 3;

    uint32_t aq[4][4];
    {
        const __half* qp = Qh + (size_t)rbase * C_EMB + hd * D_HEAD;
#pragma unroll
        for (int kk = 0; kk < 4; kk++) {
            aq[kk][0] = *(const uint32_t*)(qp + (size_t)gid * C_EMB + kk * 16 + 2 * tig);
            aq[kk][1] = *(const uint32_t*)(qp + (size_t)(gid + 8) * C_EMB + kk * 16 + 2 * tig);
            aq[kk][2] = *(const uint32_t*)(qp + (size_t)gid * C_EMB + kk * 16 + 2 * tig + 8);
            aq[kk][3] = *(const uint32_t*)(qp + (size_t)(gid + 8) * C_EMB + kk * 16 + 2 * tig + 8);
        }
    }

    float oacc[8][4];
#pragma unroll
    for (int i = 0; i < 8; i++)
#pragma unroll
        for (int r = 0; r < 4; r++) oacc[i][r] = 0.f;
    float m_lo = -1e30f, m_hi = -1e30f, l_lo = 0.f, l_hi = 0.f;
    int row0 = rbase + gid, row1 = row0 + 8;

    int kb_last = 2 * qt + 1;

#pragma unroll
    for (int i = 0; i < 2; i++) {
        int id = tid + i * 256;
        int rr = id >> 3, it = id & 7;
        cp_async16(s2u(KsB + rr * AKS + it * 8),
                   Kh + (size_t)rr * C_EMB + hd * D_HEAD + it * 8);
        cp_async16(s2u(VsB + rr * AKS + it * 8),
                   Vh + (size_t)rr * C_EMB + hd * D_HEAD + it * 8);
    }
    CP_COMMIT();

    for (int kb = 0; kb <= kb_last; kb++) {
        int cur = kb & 1;
        if (kb < kb_last) {
            int nb = (kb + 1) & 1;
            int nbase = (kb + 1) * 64;
#pragma unroll
            for (int i = 0; i < 2; i++) {
                int id = tid + i * 256;
                int rr = id >> 3, it = id & 7;
                cp_async16(s2u(KsB + (nb * 64 + rr) * AKS + it * 8),
                           Kh + (size_t)(nbase + rr) * C_EMB + hd * D_HEAD + it * 8);
                cp_async16(s2u(VsB + (nb * 64 + rr) * AKS + it * 8),
                           Vh + (size_t)(nbase + rr) * C_EMB + hd * D_HEAD + it * 8);
            }
            CP_COMMIT();
            CP_WAIT(1);
        } else {
            CP_WAIT(0);
        }
        __syncthreads();

        __half* Ks = KsB + cur * 64 * AKS;
        __half* Vs = VsB + cur * 64 * AKS;
        int kbase = kb * 64;

        if (kbase <= rbase + 15) {
            float sacc[8][4];
#pragma unroll
            for (int n = 0; n < 8; n++)
#pragma unroll
                for (int r = 0; r < 4; r++) sacc[n][r] = 0.f;
#pragma unroll
            for (int kk = 0; kk < 4; kk++) {
#pragma unroll
                for (int np = 0; np < 4; np++) {
                    uint32_t b4[4];
                    uint32_t addr = s2u(&Ks[(np * 16 + bs_row) * AKS + kk * 16 + bs_colh]);
                    LDSM_X4(b4[0], b4[1], b4[2], b4[3], addr);
                    mma_f16(sacc[2 * np],     aq[kk], b4);
                    mma_f16(sacc[2 * np + 1], aq[kk], b4 + 2);
                }
            }

            bool boundary = (kbase + 63 > rbase);
            float ml0 = -1e30f, ml1 = -1e30f;
#pragma unroll
            for (int n = 0; n < 8; n++) {
                if (boundary) {
                    int c = kbase + n * 8 + 2 * tig;
                    if (c     > row0) sacc[n][0] = -1e30f;
                    if (c + 1 > row0) sacc[n][1] = -1e30f;
                    if (c     > row1) sacc[n][2] = -1e30f;
                    if (c + 1 > row1) sacc[n][3] = -1e30f;
                }
                ml0 = fmaxf(ml0, fmaxf(sacc[n][0], sacc[n][1]));
                ml1 = fmaxf(ml1, fmaxf(sacc[n][2], sacc[n][3]));
            }
            ml0 = fmaxf(ml0, __shfl_xor_sync(0xffffffffu, ml0, 1));
            ml0 = fmaxf(ml0, __shfl_xor_sync(0xffffffffu, ml0, 2));
            ml1 = fmaxf(ml1, __shfl_xor_sync(0xffffffffu, ml1, 1));
            ml1 = fmaxf(ml1, __shfl_xor_sync(0xffffffffu, ml1, 2));
            float mn0 = fmaxf(m_lo, ml0), mn1 = fmaxf(m_hi, ml1);
            float al0 = exp2f(m_lo - mn0), al1 = exp2f(m_hi - mn1);
            m_lo = mn0; m_hi = mn1;

            float ls0 = 0.f, ls1 = 0.f;
#pragma unroll
            for (int n = 0; n < 8; n++) {
                sacc[n][0] = exp2f(sacc[n][0] - mn0);
                sacc[n][1] = exp2f(sacc[n][1] - mn0);
                sacc[n][2] = exp2f(sacc[n][2] - mn1);
                sacc[n][3] = exp2f(sacc[n][3] - mn1);
                ls0 += sacc[n][0] + sacc[n][1];
                ls1 += sacc[n][2] + sacc[n][3];
            }
            ls0 += __shfl_xor_sync(0xffffffffu, ls0, 1);
            ls0 += __shfl_xor_sync(0xffffffffu, ls0, 2);
            ls1 += __shfl_xor_sync(0xffffffffu, ls1, 1);
            ls1 += __shfl_xor_sync(0xffffffffu, ls1, 2);
            l_lo = l_lo * al0 + ls0;
            l_hi = l_hi * al1 + ls1;
#pragma unroll
            for (int n = 0; n < 8; n++) {
                oacc[n][0] *= al0; oacc[n][1] *= al0;
                oacc[n][2] *= al1; oacc[n][3] *= al1;
            }

#pragma unroll
            for (int kt = 0; kt < 4; kt++) {
                uint32_t ap[4];
                ap[0] = packh(sacc[2 * kt][0],     sacc[2 * kt][1]);
                ap[1] = packh(sacc[2 * kt][2],     sacc[2 * kt][3]);
                ap[2] = packh(sacc[2 * kt + 1][0], sacc[2 * kt + 1][1]);
                ap[3] = packh(sacc[2 * kt + 1][2], sacc[2 * kt + 1][3]);
#pragma unroll
                for (int np2 = 0; np2 < 4; np2++) {
                    uint32_t b4[4];
                    uint32_t va = s2u(&Vs[(kt * 16 + vt_row) * AKS + np2 * 16 + vt_colh]);
                    LDSM_X4_T(b4[0], b4[1], b4[2], b4[3], va);
                    mma_f16(oacc[2 * np2],     ap, b4);
                    mma_f16(oacc[2 * np2 + 1], ap, b4 + 2);
                }
            }
        }
        __syncthreads();
    }

    float inv0 = 1.0f / l_lo, inv1 = 1.0f / l_hi;
    __half* o0 = Oh + (size_t)row0 * C_EMB + hd * D_HEAD;
    __half* o1 = Oh + (size_t)row1 * C_EMB + hd * D_HEAD;
#pragma unroll
    for (int n = 0; n < 8; n++) {
        int c = n * 8 + 2 * tig;
        *(uint32_t*)(o0 + c) = packh(oacc[n][0] * inv0, oacc[n][1] * inv0);
        *(uint32_t*)(o1 + c) = packh(oacc[n][2] * inv1, oacc[n][3] * inv1);
    }
}

// ----------------------------------------------------------------------------
// launch
// ----------------------------------------------------------------------------
extern "C" void kernel_launch(void* const* d_in, const int* in_sizes, int n_in,
                              void* d_out, int out_size)
{
    const float* x     = (const float*)d_in[0];
    const float* Wq    = (const float*)d_in[1];
    const float* bq    = (const float*)d_in[2];
    const float* Wk    = (const float*)d_in[3];
    const float* bk    = (const float*)d_in[4];
    const float* Wv    = (const float*)d_in[5];
    const float* bv    = (const float*)d_in[6];
    const float* Wo    = (const float*)d_in[7];
    const float* bo    = (const float*)d_in[8];
    const float* ln1_g = (const float*)d_in[9];
    const float* ln1_b = (const float*)d_in[10];
    const float* ln2_g = (const float*)d_in[11];
    const float* ln2_b = (const float*)d_in[12];
    const float* W1    = (const float*)d_in[13];
    const float* b1    = (const float*)d_in[14];
    const float* W2    = (const float*)d_in[15];
    const float* b2    = (const float*)d_in[16];
    float* out = (float*)d_out;

    float *h, *h2, *part;
    __half *hh, *h2h, *qh, *kh, *vh, *ctxh, *m1h;
    __half *wtq, *wtk, *wtv, *wto, *wt1, *wt2;
    cudaGetSymbolAddress((void**)&h,    g_h);
    cudaGetSymbolAddress((void**)&h2,   g_h2);
    cudaGetSymbolAddress((void**)&part, g_part);
    cudaGetSymbolAddress((void**)&hh,   g_hh);
    cudaGetSymbolAddress((void**)&h2h,  g_h2h);
    cudaGetSymbolAddress((void**)&qh,   g_qh);
    cudaGetSymbolAddress((void**)&kh,   g_kh);
    cudaGetSymbolAddress((void**)&vh,   g_vh);
    cudaGetSymbolAddress((void**)&ctxh, g_ctxh);
    cudaGetSymbolAddress((void**)&m1h,  g_m1h);
    cudaGetSymbolAddress((void**)&wtq,  g_wtq);
    cudaGetSymbolAddress((void**)&wtk,  g_wtk);
    cudaGetSymbolAddress((void**)&wtv,  g_wtv);
    cudaGetSymbolAddress((void**)&wto,  g_wto);
    cudaGetSymbolAddress((void**)&wt1,  g_wt1);
    cudaGetSymbolAddress((void**)&wt2,  g_wt2);

    cudaFuncSetAttribute(fattn_k, cudaFuncAttributeMaxDynamicSharedMemorySize,
                         ATTN_SMEM_BYTES);

    cvt_all_k<<<6912, 256>>>(Wq, Wk, Wv, Wo, W1, W2,
                             wtq, wtk, wtv, wto, wt1, wt2);

    dim3 gQKV(18, T_SEQ / 128);
    dim3 gF(F_FFN / 128, T_SEQ / 128);
    dim3 gSplit(C_EMB / 128, T_SEQ / 128, 2);
    int  gComb = T_SEQ * C_EMB / 4 / 256;

    layernorm_k<<<T_SEQ, 256>>>(x, ln1_g, ln1_b, h, hh);
    hgemm_qkv_k<<<gQKV, 256>>>(hh, wtq, bq, qh, wtk, bk, kh, wtv, bv, vh);
    fattn_k<<<dim3(T_SEQ / 128, N_HEAD), 256, ATTN_SMEM_BYTES>>>(qh, kh, vh, ctxh);
    hgemm_split_k<<<gSplit, 256>>>(ctxh, wto, part, C_EMB);
    combine_ln_k<<<T_SEQ, 256>>>(part, bo, h, ln2_g, ln2_b, h2, h2h);
    hgemm_gelu_h_k<<<gF, 256>>>(h2h, wt1, b1, m1h, F_FFN, C_EMB);
    hgemm_split_k<<<gSplit, 256>>>(m1h, wt2, part, F_FFN);
    combine_k<<<gComb, 256>>>(part, b2, h2, out);
}

// round 16
// speedup vs baseline: 1.8152x; 1.0025x over previous
#include <cuda_runtime.h>
#include <cuda_fp16.h>
#include <math.h>
#include <stdint.h>

#define T_SEQ 4096
#define C_EMB 768
#define N_HEAD 12
#define D_HEAD 64
#define F_FFN 3072

__device__ float  g_h  [T_SEQ * C_EMB];
__device__ float  g_h2 [T_SEQ * C_EMB];
__device__ float  g_part[2 * T_SEQ * C_EMB];
__device__ __half g_hh [T_SEQ * C_EMB];
__device__ __half g_h2h[T_SEQ * C_EMB];
__device__ __half g_qh [T_SEQ * C_EMB];
__device__ __half g_kh [T_SEQ * C_EMB];
__device__ __half g_vh [T_SEQ * C_EMB];
__device__ __half g_ctxh[T_SEQ * C_EMB];
__device__ __half g_m1h[T_SEQ * F_FFN];
__device__ __half g_wtq[C_EMB * C_EMB];
__device__ __half g_wtk[C_EMB * C_EMB];
__device__ __half g_wtv[C_EMB * C_EMB];
__device__ __half g_wto[C_EMB * C_EMB];
__device__ __half g_wt1[F_FFN * C_EMB];
__device__ __half g_wt2[C_EMB * F_FFN];

__device__ __forceinline__ uint32_t s2u(const void* p) {
    return (uint32_t)__cvta_generic_to_shared(p);
}
__device__ __forceinline__ uint32_t packh(float lo, float hi) {
    __half2 h = __floats2half2_rn(lo, hi);
    return *reinterpret_cast<uint32_t*>(&h);
}
__device__ __forceinline__ void mma_f16(float* d, const uint32_t* a, const uint32_t* b) {
    asm volatile(
        "mma.sync.aligned.m16n8k16.row.col.f32.f16.f16.f32 "
        "{%0,%1,%2,%3}, {%4,%5,%6,%7}, {%8,%9}, {%0,%1,%2,%3};\n"
        : "+f"(d[0]), "+f"(d[1]), "+f"(d[2]), "+f"(d[3])
        : "r"(a[0]), "r"(a[1]), "r"(a[2]), "r"(a[3]), "r"(b[0]), "r"(b[1]));
}
#define LDSM_X4(r0, r1, r2, r3, addr)                                          \
    asm volatile("ldmatrix.sync.aligned.m8n8.x4.shared.b16 {%0,%1,%2,%3}, [%4];" \
                 : "=r"(r0), "=r"(r1), "=r"(r2), "=r"(r3) : "r"(addr))
#define LDSM_X4_T(r0, r1, r2, r3, addr)                                        \
    asm volatile("ldmatrix.sync.aligned.m8n8.x4.trans.shared.b16 {%0,%1,%2,%3}, [%4];" \
                 : "=r"(r0), "=r"(r1), "=r"(r2), "=r"(r3) : "r"(addr))
__device__ __forceinline__ void cp_async16(uint32_t dst, const void* src) {
    asm volatile("cp.async.cg.shared.global [%0], [%1], 16;" :: "r"(dst), "l"(src));
}
#define CP_COMMIT() asm volatile("cp.async.commit_group;" ::: "memory")
#define CP_WAIT(n)  asm volatile("cp.async.wait_group %0;" :: "n"(n) : "memory")

__device__ __forceinline__ float gelu_exact(float v) {
    return 0.5f * v * (1.0f + erff(v * 0.70710678118654752440f));
}

// ----------------------------------------------------------------------------
// fused weight convert+transpose (R14)
// ----------------------------------------------------------------------------
__global__ __launch_bounds__(256) void cvt_all_k(
    const float* __restrict__ Wq, const float* __restrict__ Wk,
    const float* __restrict__ Wv, const float* __restrict__ Wo,
    const float* __restrict__ W1, const float* __restrict__ W2,
    __half* __restrict__ wtq, __half* __restrict__ wtk,
    __half* __restrict__ wtv, __half* __restrict__ wto,
    __half* __restrict__ wt1, __half* __restrict__ wt2)
{
    __shared__ float t[32][33];
    int id = blockIdx.x;
    const float* in; __half* outp; int R, Cc, bx, by;
    if (id < 2304) {
        int i = id / 576, rem = id % 576;
        in   = (i == 0) ? Wq : (i == 1) ? Wk : (i == 2) ? Wv : Wo;
        outp = (i == 0) ? wtq : (i == 1) ? wtk : (i == 2) ? wtv : wto;
        R = C_EMB; Cc = C_EMB; bx = (rem % 24) * 32; by = (rem / 24) * 32;
    } else if (id < 4608) {
        int rem = id - 2304;
        in = W1; outp = wt1; R = C_EMB; Cc = F_FFN;
        bx = (rem % 96) * 32; by = (rem / 96) * 32;
    } else {
        int rem = id - 4608;
        in = W2; outp = wt2; R = F_FFN; Cc = C_EMB;
        bx = (rem % 24) * 32; by = (rem / 24) * 32;
    }
    int tx = threadIdx.x & 31, ty = threadIdx.x >> 5;
#pragma unroll
    for (int i = 0; i < 4; i++)
        t[ty + i * 8][tx] = in[(size_t)(by + ty + i * 8) * Cc + bx + tx];
    __syncthreads();
#pragma unroll
    for (int i = 0; i < 4; i++)
        outp[(size_t)(bx + ty + i * 8) * R + by + tx] = __float2half_rn(t[tx][ty + i * 8]);
}

// ----------------------------------------------------------------------------
// LayerNorm / combine kernels (R14)
// ----------------------------------------------------------------------------
__global__ __launch_bounds__(256) void layernorm_k(
    const float* __restrict__ in, const float* __restrict__ gamma,
    const float* __restrict__ beta, float* __restrict__ out,
    __half* __restrict__ outh)
{
    int row = blockIdx.x;
    const float* xr = in + (size_t)row * C_EMB;
    float s = 0.f, s2 = 0.f, v0[3];
#pragma unroll
    for (int i = 0; i < 3; i++) {
        float v = xr[threadIdx.x + i * 256];
        v0[i] = v; s += v; s2 += v * v;
    }
#pragma unroll
    for (int off = 16; off > 0; off >>= 1) {
        s  += __shfl_down_sync(0xffffffffu, s,  off);
        s2 += __shfl_down_sync(0xffffffffu, s2, off);
    }
    __shared__ float shs[8], shs2[8];
    int lane = threadIdx.x & 31, warp = threadIdx.x >> 5;
    if (lane == 0) { shs[warp] = s; shs2[warp] = s2; }
    __syncthreads();
    s = 0.f; s2 = 0.f;
#pragma unroll
    for (int i = 0; i < 8; i++) { s += shs[i]; s2 += shs2[i]; }
    float mu = s * (1.0f / C_EMB);
    float var = s2 * (1.0f / C_EMB) - mu * mu;
    float inv = rsqrtf(var + 1e-5f);
#pragma unroll
    for (int i = 0; i < 3; i++) {
        int c = threadIdx.x + i * 256;
        float v = (v0[i] - mu) * inv * gamma[c] + beta[c];
        out [(size_t)row * C_EMB + c] = v;
        outh[(size_t)row * C_EMB + c] = __float2half_rn(v);
    }
}

__global__ __launch_bounds__(256) void combine_ln_k(
    const float* __restrict__ part, const float* __restrict__ bias,
    const float* __restrict__ res, const float* __restrict__ gamma,
    const float* __restrict__ beta, float* __restrict__ out,
    __half* __restrict__ outh)
{
    int row = blockIdx.x;
    size_t base = (size_t)row * C_EMB;
    float s = 0.f, s2 = 0.f, v0[3];
#pragma unroll
    for (int i = 0; i < 3; i++) {
        int c = threadIdx.x + i * 256;
        float v = part[base + c] + part[(size_t)T_SEQ * C_EMB + base + c]
                + bias[c] + res[base + c];
        v0[i] = v; s += v; s2 += v * v;
    }
#pragma unroll
    for (int off = 16; off > 0; off >>= 1) {
        s  += __shfl_down_sync(0xffffffffu, s,  off);
        s2 += __shfl_down_sync(0xffffffffu, s2, off);
    }
    __shared__ float shs[8], shs2[8];
    int lane = threadIdx.x & 31, warp = threadIdx.x >> 5;
    if (lane == 0) { shs[warp] = s; shs2[warp] = s2; }
    __syncthreads();
    s = 0.f; s2 = 0.f;
#pragma unroll
    for (int i = 0; i < 8; i++) { s += shs[i]; s2 += shs2[i]; }
    float mu = s * (1.0f / C_EMB);
    float var = s2 * (1.0f / C_EMB) - mu * mu;
    float inv = rsqrtf(var + 1e-5f);
#pragma unroll
    for (int i = 0; i < 3; i++) {
        int c = threadIdx.x + i * 256;
        float v = (v0[i] - mu) * inv * gamma[c] + beta[c];
        out [base + c] = v;
        outh[base + c] = __float2half_rn(v);
    }
}

__global__ __launch_bounds__(256) void combine_k(
    const float* __restrict__ part, const float* __restrict__ bias,
    const float* __restrict__ res, float* __restrict__ out)
{
    int i = blockIdx.x * 256 + threadIdx.x;
    int col = (i * 4) % C_EMB;
    float4 a = ((const float4*)part)[i];
    float4 b = ((const float4*)(part + (size_t)T_SEQ * C_EMB))[i];
    float4 bi = *(const float4*)(bias + col);
    float4 r = ((const float4*)res)[i];
    float4 o;
    o.x = a.x + b.x + bi.x + r.x;
    o.y = a.y + b.y + bi.y + r.y;
    o.z = a.z + b.z + bi.z + r.z;
    o.w = a.w + b.w + bi.w + r.w;
    ((float4*)out)[i] = o;
}

// ----------------------------------------------------------------------------
// fp16 GEMM body, BK=32, 3-stage cp.async pipeline, ONE barrier per stage.
// Dynamic smem: As[3][128][40] + Bs[3][128][40] halves = 60 KB.
// ----------------------------------------------------------------------------
#define GEMM_S      40
#define GEMM_STAGES 3
#define GEMM_SMEM   (2 * GEMM_STAGES * 128 * GEMM_S * (int)sizeof(__half))

template<int ACT, int PARTIAL, int OUTH>
__device__ __forceinline__ void hgemm_body(
    const __half* __restrict__ A, const __half* __restrict__ B,
    const float* __restrict__ bias, const float* __restrict__ res,
    float* __restrict__ C, __half* __restrict__ Ch,
    int N, int K, int kbeg, int klen, int bx, int by, float oscale)
{
    extern __shared__ __half gsm[];
    __half (*As)[128][GEMM_S] = (__half(*)[128][GEMM_S])gsm;
    __half (*Bs)[128][GEMM_S] = (__half(*)[128][GEMM_S])(gsm + GEMM_STAGES * 128 * GEMM_S);

    int tid = threadIdx.x, lane = tid & 31, wid = tid >> 5;
    int wm = wid & 1, wn = wid >> 1;
    int gid = lane >> 2, tig = lane & 3;
    int bm = by * 128, bn = bx * 128;

    int a_row  = wm * 64 + (lane & 15);
    int a_colh = (lane >> 4) << 3;
    int b_row  = wn * 32 + ((lane >> 4) << 3) + (lane & 7);
    int b_colh = ((lane >> 3) & 1) << 3;

    int l_r = tid >> 1, l_h = (tid & 1) * 16;

    float acc[4][4][4];
#pragma unroll
    for (int i = 0; i < 4; i++)
#pragma unroll
        for (int j = 0; j < 4; j++)
#pragma unroll
            for (int r = 0; r < 4; r++) acc[i][j][r] = 0.f;

    int nt = klen / 32;
    const __half* Arow = A + (size_t)(bm + l_r) * K + kbeg + l_h;
    const __half* Brow = B + (size_t)(bn + l_r) * K + kbeg + l_h;

    // prologue: fill stages 0,1 (chunks 0,1)
#pragma unroll
    for (int p = 0; p < 2; p++) {
        cp_async16(s2u(&As[p][l_r][l_h]),     Arow + p * 32);
        cp_async16(s2u(&As[p][l_r][l_h + 8]), Arow + p * 32 + 8);
        cp_async16(s2u(&Bs[p][l_r][l_h]),     Brow + p * 32);
        cp_async16(s2u(&Bs[p][l_r][l_h + 8]), Brow + p * 32 + 8);
        CP_COMMIT();
    }

    for (int kt = 0; kt < nt; kt++) {
        if (kt + 1 < nt) { CP_WAIT(1); } else { CP_WAIT(0); }
        __syncthreads();
        // prefetch chunk kt+2 into stage (kt+2)%3 (its old data, chunk kt-1,
        // was finished by all warps before this barrier)
        if (kt + 2 < nt) {
            int st = (kt + 2) % GEMM_STAGES;
            int off = (kt + 2) * 32;
            cp_async16(s2u(&As[st][l_r][l_h]),     Arow + off);
            cp_async16(s2u(&As[st][l_r][l_h + 8]), Arow + off + 8);
            cp_async16(s2u(&Bs[st][l_r][l_h]),     Brow + off);
            cp_async16(s2u(&Bs[st][l_r][l_h + 8]), Brow + off + 8);
            CP_COMMIT();
        }

        int buf = kt % GEMM_STAGES;
#pragma unroll
        for (int ks = 0; ks < 2; ks++) {
            int kk = ks * 16;
            uint32_t af[4][4];
#pragma unroll
            for (int mt = 0; mt < 4; mt++) {
                uint32_t addr = s2u(&As[buf][a_row + mt * 16][kk + a_colh]);
                LDSM_X4(af[mt][0], af[mt][1], af[mt][2], af[mt][3], addr);
            }
            uint32_t bf[4][2];
#pragma unroll
            for (int np = 0; np < 2; np++) {
                uint32_t addr = s2u(&Bs[buf][b_row + np * 16][kk + b_colh]);
                LDSM_X4(bf[2 * np][0], bf[2 * np][1],
                        bf[2 * np + 1][0], bf[2 * np + 1][1], addr);
            }
#pragma unroll
            for (int mt = 0; mt < 4; mt++)
#pragma unroll
                for (int ntl = 0; ntl < 4; ntl++)
                    mma_f16(acc[mt][ntl], af[mt], bf[ntl]);
        }
    }

#pragma unroll
    for (int mt = 0; mt < 4; mt++) {
#pragma unroll
        for (int ntl = 0; ntl < 4; ntl++) {
            int row = bm + wm * 64 + mt * 16 + gid;
            int col = bn + wn * 32 + ntl * 8 + tig * 2;
            if (OUTH) {
                float v0 = acc[mt][ntl][0] + bias[col];
                float v1 = acc[mt][ntl][1] + bias[col + 1];
                float v2 = acc[mt][ntl][2] + bias[col];
                float v3 = acc[mt][ntl][3] + bias[col + 1];
                if (ACT == 1) {
                    v0 = gelu_exact(v0); v1 = gelu_exact(v1);
                    v2 = gelu_exact(v2); v3 = gelu_exact(v3);
                }
                v0 *= oscale; v1 *= oscale; v2 *= oscale; v3 *= oscale;
                *(uint32_t*)&Ch[(size_t)row * N + col]       = packh(v0, v1);
                *(uint32_t*)&Ch[(size_t)(row + 8) * N + col] = packh(v2, v3);
            } else {
#pragma unroll
                for (int r = 0; r < 4; r++) {
                    int rr = row + (r >> 1) * 8;
                    int cc = col + (r & 1);
                    float v = acc[mt][ntl][r];
                    if (!PARTIAL) {
                        v += bias[cc];
                        if (res) v += res[(size_t)rr * N + cc];
                        if (ACT == 1) v = gelu_exact(v);
                    }
                    C[(size_t)rr * N + cc] = v;
                }
            }
        }
    }
}

__global__ __launch_bounds__(256) void hgemm_gelu_h_k(
    const __half* __restrict__ A, const __half* __restrict__ B,
    const float* __restrict__ bias, __half* __restrict__ Ch, int N, int K)
{
    hgemm_body<1, 0, 1>(A, B, bias, nullptr, nullptr, Ch, N, K, 0, K,
                        blockIdx.x, blockIdx.y, 1.0f);
}

__global__ __launch_bounds__(256) void hgemm_qkv_k(
    const __half* __restrict__ A,
    const __half* __restrict__ B0, const float* __restrict__ b0, __half* __restrict__ C0,
    const __half* __restrict__ B1, const float* __restrict__ b1, __half* __restrict__ C1,
    const __half* __restrict__ B2, const float* __restrict__ b2, __half* __restrict__ C2)
{
    int sel = blockIdx.x / 6, bx = blockIdx.x % 6;
    const __half* B  = (sel == 0) ? B0 : (sel == 1) ? B1 : B2;
    const float*  bb = (sel == 0) ? b0 : (sel == 1) ? b1 : b2;
    __half*       Ch = (sel == 0) ? C0 : (sel == 1) ? C1 : C2;
    float sc = (sel == 0) ? 0.125f * 1.44269504088896f : 1.0f;
    hgemm_body<0, 0, 1>(A, B, bb, nullptr, nullptr, Ch, C_EMB, C_EMB, 0, C_EMB,
                        bx, blockIdx.y, sc);
}

__global__ __launch_bounds__(256) void hgemm_split_k(
    const __half* __restrict__ A, const __half* __restrict__ B,
    float* __restrict__ part, int K)
{
    int z = blockIdx.z;
    hgemm_body<0, 1, 0>(A, B, nullptr, nullptr,
                        part + (size_t)z * T_SEQ * C_EMB, nullptr,
                        C_EMB, K, z * (K / 2), K / 2, blockIdx.x, blockIdx.y, 1.0f);
}

// ----------------------------------------------------------------------------
// Flash attention fp16, register-P, exp2 softmax (R15, unchanged)
// ----------------------------------------------------------------------------
#define AKS 72
#define ATTN_SMEM_BYTES ((2 * 64 * AKS + 2 * 64 * AKS) * 2)

__global__ __launch_bounds__(256, 2) void fattn_k(
    const __half* __restrict__ Qh, const __half* __restrict__ Kh,
    const __half* __restrict__ Vh, __half* __restrict__ Oh)
{
    extern __shared__ __half smh[];
    __half* KsB = smh;
    __half* VsB = KsB + 2 * 64 * AKS;

    int hd = blockIdx.y;
    int qt = (int)gridDim.x - 1 - (int)blockIdx.x;
    int tid = threadIdx.x, w = tid >> 5, lane = tid & 31;
    int gid = lane >> 2, tig = lane & 3;
    int rbase = qt * 128 + w * 16;

    int bs_row = ((lane >> 4) << 3) + (lane & 7);
    int bs_colh = ((lane >> 3) & 1) << 3;
    int vt_row = lane & 15;
    int vt_colh = (lane >> 4) << 3;

    uint32_t aq[4][4];
    {
        const __half* qp = Qh + (size_t)rbase * C_EMB + hd * D_HEAD;
#pragma unroll
        for (int kk = 0; kk < 4; kk++) {
            aq[kk][0] = *(const uint32_t*)(qp + (size_t)gid * C_EMB + kk * 16 + 2 * tig);
            aq[kk][1] = *(const uint32_t*)(qp + (size_t)(gid + 8) * C_EMB + kk * 16 + 2 * tig);
            aq[kk][2] = *(const uint32_t*)(qp + (size_t)gid * C_EMB + kk * 16 + 2 * tig + 8);
            aq[kk][3] = *(const uint32_t*)(qp + (size_t)(gid + 8) * C_EMB + kk * 16 + 2 * tig + 8);
        }
    }

    float oacc[8][4];
#pragma unroll
    for (int i = 0; i < 8; i++)
#pragma unroll
        for (int r = 0; r < 4; r++) oacc[i][r] = 0.f;
    float m_lo = -1e30f, m_hi = -1e30f, l_lo = 0.f, l_hi = 0.f;
    int row0 = rbase + gid, row1 = row0 + 8;

    int kb_last = 2 * qt + 1;

#pragma unroll
    for (int i = 0; i < 2; i++) {
        int id = tid + i * 256;
        int rr = id >> 3, it = id & 7;
        cp_async16(s2u(KsB + rr * AKS + it * 8),
                   Kh + (size_t)rr * C_EMB + hd * D_HEAD + it * 8);
        cp_async16(s2u(VsB + rr * AKS + it * 8),
                   Vh + (size_t)rr * C_EMB + hd * D_HEAD + it * 8);
    }
    CP_COMMIT();

    for (int kb = 0; kb <= kb_last; kb++) {
        int cur = kb & 1;
        if (kb < kb_last) {
            int nb = (kb + 1) & 1;
            int nbase = (kb + 1) * 64;
#pragma unroll
            for (int i = 0; i < 2; i++) {
                int id = tid + i * 256;
                int rr = id >> 3, it = id & 7;
                cp_async16(s2u(KsB + (nb * 64 + rr) * AKS + it * 8),
                           Kh + (size_t)(nbase + rr) * C_EMB + hd * D_HEAD + it * 8);
                cp_async16(s2u(VsB + (nb * 64 + rr) * AKS + it * 8),
                           Vh + (size_t)(nbase + rr) * C_EMB + hd * D_HEAD + it * 8);
            }
            CP_COMMIT();
            CP_WAIT(1);
        } else {
            CP_WAIT(0);
        }
        __syncthreads();

        __half* Ks = KsB + cur * 64 * AKS;
        __half* Vs = VsB + cur * 64 * AKS;
        int kbase = kb * 64;

        if (kbase <= rbase + 15) {
            float sacc[8][4];
#pragma unroll
            for (int n = 0; n < 8; n++)
#pragma unroll
                for (int r = 0; r < 4; r++) sacc[n][r] = 0.f;
#pragma unroll
            for (int kk = 0; kk < 4; kk++) {
#pragma unroll
                for (int np = 0; np < 4; np++) {
                    uint32_t b4[4];
                    uint32_t addr = s2u(&Ks[(np * 16 + bs_row) * AKS + kk * 16 + bs_colh]);
                    LDSM_X4(b4[0], b4[1], b4[2], b4[3], addr);
                    mma_f16(sacc[2 * np],     aq[kk], b4);
                    mma_f16(sacc[2 * np + 1], aq[kk], b4 + 2);
                }
            }

            bool boundary = (kbase + 63 > rbase);
            float ml0 = -1e30f, ml1 = -1e30f;
#pragma unroll
            for (int n = 0; n < 8; n++) {
                if (boundary) {
                    int c = kbase + n * 8 + 2 * tig;
                    if (c     > row0) sacc[n][0] = -1e30f;
                    if (c + 1 > row0) sacc[n][1] = -1e30f;
                    if (c     > row1) sacc[n][2] = -1e30f;
                    if (c + 1 > row1) sacc[n][3] = -1e30f;
                }
                ml0 = fmaxf(ml0, fmaxf(sacc[n][0], sacc[n][1]));
                ml1 = fmaxf(ml1, fmaxf(sacc[n][2], sacc[n][3]));
            }
            ml0 = fmaxf(ml0, __shfl_xor_sync(0xffffffffu, ml0, 1));
            ml0 = fmaxf(ml0, __shfl_xor_sync(0xffffffffu, ml0, 2));
            ml1 = fmaxf(ml1, __shfl_xor_sync(0xffffffffu, ml1, 1));
            ml1 = fmaxf(ml1, __shfl_xor_sync(0xffffffffu, ml1, 2));
            float mn0 = fmaxf(m_lo, ml0), mn1 = fmaxf(m_hi, ml1);
            float al0 = exp2f(m_lo - mn0), al1 = exp2f(m_hi - mn1);
            m_lo = mn0; m_hi = mn1;

            float ls0 = 0.f, ls1 = 0.f;
#pragma unroll
            for (int n = 0; n < 8; n++) {
                sacc[n][0] = exp2f(sacc[n][0] - mn0);
                sacc[n][1] = exp2f(sacc[n][1] - mn0);
                sacc[n][2] = exp2f(sacc[n][2] - mn1);
                sacc[n][3] = exp2f(sacc[n][3] - mn1);
                ls0 += sacc[n][0] + sacc[n][1];
                ls1 += sacc[n][2] + sacc[n][3];
            }
            ls0 += __shfl_xor_sync(0xffffffffu, ls0, 1);
            ls0 += __shfl_xor_sync(0xffffffffu, ls0, 2);
            ls1 += __shfl_xor_sync(0xffffffffu, ls1, 1);
            ls1 += __shfl_xor_sync(0xffffffffu, ls1, 2);
            l_lo = l_lo * al0 + ls0;
            l_hi = l_hi * al1 + ls1;
#pragma unroll
            for (int n = 0; n < 8; n++) {
                oacc[n][0] *= al0; oacc[n][1] *= al0;
                oacc[n][2] *= al1; oacc[n][3] *= al1;
            }

#pragma unroll
            for (int kt = 0; kt < 4; kt++) {
                uint32_t ap[4];
                ap[0] = packh(sacc[2 * kt][0],     sacc[2 * kt][1]);
                ap[1] = packh(sacc[2 * kt][2],     sacc[2 * kt][3]);
                ap[2] = packh(sacc[2 * kt + 1][0], sacc[2 * kt + 1][1]);
                ap[3] = packh(sacc[2 * kt + 1][2], sacc[2 * kt + 1][3]);
#pragma unroll
                for (int np2 = 0; np2 < 4; np2++) {
                    uint32_t b4[4];
                    uint32_t va = s2u(&Vs[(kt * 16 + vt_row) * AKS + np2 * 16 + vt_colh]);
                    LDSM_X4_T(b4[0], b4[1], b4[2], b4[3], va);
                    mma_f16(oacc[2 * np2],     ap, b4);
                    mma_f16(oacc[2 * np2 + 1], ap, b4 + 2);
                }
            }
        }
        __syncthreads();
    }

    float inv0 = 1.0f / l_lo, inv1 = 1.0f / l_hi;
    __half* o0 = Oh + (size_t)row0 * C_EMB + hd * D_HEAD;
    __half* o1 = Oh + (size_t)row1 * C_EMB + hd * D_HEAD;
#pragma unroll
    for (int n = 0; n < 8; n++) {
        int c = n * 8 + 2 * tig;
        *(uint32_t*)(o0 + c) = packh(oacc[n][0] * inv0, oacc[n][1] * inv0);
        *(uint32_t*)(o1 + c) = packh(oacc[n][2] * inv1, oacc[n][3] * inv1);
    }
}

// ----------------------------------------------------------------------------
// launch
// ----------------------------------------------------------------------------
extern "C" void kernel_launch(void* const* d_in, const int* in_sizes, int n_in,
                              void* d_out, int out_size)
{
    const float* x     = (const float*)d_in[0];
    const float* Wq    = (const float*)d_in[1];
    const float* bq    = (const float*)d_in[2];
    const float* Wk    = (const float*)d_in[3];
    const float* bk    = (const float*)d_in[4];
    const float* Wv    = (const float*)d_in[5];
    const float* bv    = (const float*)d_in[6];
    const float* Wo    = (const float*)d_in[7];
    const float* bo    = (const float*)d_in[8];
    const float* ln1_g = (const float*)d_in[9];
    const float* ln1_b = (const float*)d_in[10];
    const float* ln2_g = (const float*)d_in[11];
    const float* ln2_b = (const float*)d_in[12];
    const float* W1    = (const float*)d_in[13];
    const float* b1    = (const float*)d_in[14];
    const float* W2    = (const float*)d_in[15];
    const float* b2    = (const float*)d_in[16];
    float* out = (float*)d_out;

    float *h, *h2, *part;
    __half *hh, *h2h, *qh, *kh, *vh, *ctxh, *m1h;
    __half *wtq, *wtk, *wtv, *wto, *wt1, *wt2;
    cudaGetSymbolAddress((void**)&h,    g_h);
    cudaGetSymbolAddress((void**)&h2,   g_h2);
    cudaGetSymbolAddress((void**)&part, g_part);
    cudaGetSymbolAddress((void**)&hh,   g_hh);
    cudaGetSymbolAddress((void**)&h2h,  g_h2h);
    cudaGetSymbolAddress((void**)&qh,   g_qh);
    cudaGetSymbolAddress((void**)&kh,   g_kh);
    cudaGetSymbolAddress((void**)&vh,   g_vh);
    cudaGetSymbolAddress((void**)&ctxh, g_ctxh);
    cudaGetSymbolAddress((void**)&m1h,  g_m1h);
    cudaGetSymbolAddress((void**)&wtq,  g_wtq);
    cudaGetSymbolAddress((void**)&wtk,  g_wtk);
    cudaGetSymbolAddress((void**)&wtv,  g_wtv);
    cudaGetSymbolAddress((void**)&wto,  g_wto);
    cudaGetSymbolAddress((void**)&wt1,  g_wt1);
    cudaGetSymbolAddress((void**)&wt2,  g_wt2);

    cudaFuncSetAttribute(fattn_k, cudaFuncAttributeMaxDynamicSharedMemorySize,
                         ATTN_SMEM_BYTES);
    cudaFuncSetAttribute(hgemm_gelu_h_k, cudaFuncAttributeMaxDynamicSharedMemorySize,
                         GEMM_SMEM);
    cudaFuncSetAttribute(hgemm_qkv_k, cudaFuncAttributeMaxDynamicSharedMemorySize,
                         GEMM_SMEM);
    cudaFuncSetAttribute(hgemm_split_k, cudaFuncAttributeMaxDynamicSharedMemorySize,
                         GEMM_SMEM);

    cvt_all_k<<<6912, 256>>>(Wq, Wk, Wv, Wo, W1, W2,
                             wtq, wtk, wtv, wto, wt1, wt2);

    dim3 gQKV(18, T_SEQ / 128);
    dim3 gF(F_FFN / 128, T_SEQ / 128);
    dim3 gSplit(C_EMB / 128, T_SEQ / 128, 2);
    int  gComb = T_SEQ * C_EMB / 4 / 256;

    layernorm_k<<<T_SEQ, 256>>>(x, ln1_g, ln1_b, h, hh);
    hgemm_qkv_k<<<gQKV, 256, GEMM_SMEM>>>(hh, wtq, bq, qh, wtk, bk, kh, wtv, bv, vh);
    fattn_k<<<dim3(T_SEQ / 128, N_HEAD), 256, ATTN_SMEM_BYTES>>>(qh, kh, vh, ctxh);
    hgemm_split_k<<<gSplit, 256, GEMM_SMEM>>>(ctxh, wto, part, C_EMB);
    combine_ln_k<<<T_SEQ, 256>>>(part, bo, h, ln2_g, ln2_b, h2, h2h);
    hgemm_gelu_h_k<<<gF, 256, GEMM_SMEM>>>(h2h, wt1, b1, m1h, F_FFN, C_EMB);
    hgemm_split_k<<<gSplit, 256, GEMM_SMEM>>>(m1h, wt2, part, F_FFN);
    combine_k<<<gComb, 256>>>(part, b2, h2, out);
}

// round 17
// speedup vs baseline: 1.8189x; 1.0020x over previous
#include <cuda_runtime.h>
#include <cuda_fp16.h>
#include <math.h>
#include <stdint.h>

#define T_SEQ 4096
#define C_EMB 768
#define N_HEAD 12
#define D_HEAD 64
#define F_FFN 3072

__device__ float  g_h  [T_SEQ * C_EMB];
__device__ float  g_h2 [T_SEQ * C_EMB];
__device__ float  g_part[2 * T_SEQ * C_EMB];
__device__ __half g_hh [T_SEQ * C_EMB];
__device__ __half g_h2h[T_SEQ * C_EMB];
__device__ __half g_qh [T_SEQ * C_EMB];
__device__ __half g_kh [T_SEQ * C_EMB];
__device__ __half g_vh [T_SEQ * C_EMB];
__device__ __half g_ctxh[T_SEQ * C_EMB];
__device__ __half g_m1h[T_SEQ * F_FFN];
__device__ __half g_wtq[C_EMB * C_EMB];
__device__ __half g_wtk[C_EMB * C_EMB];
__device__ __half g_wtv[C_EMB * C_EMB];
__device__ __half g_wto[C_EMB * C_EMB];
__device__ __half g_wt1[F_FFN * C_EMB];
__device__ __half g_wt2[C_EMB * F_FFN];

__device__ __forceinline__ uint32_t s2u(const void* p) {
    return (uint32_t)__cvta_generic_to_shared(p);
}
__device__ __forceinline__ uint32_t packh(float lo, float hi) {
    __half2 h = __floats2half2_rn(lo, hi);
    return *reinterpret_cast<uint32_t*>(&h);
}
__device__ __forceinline__ void mma_f16(float* d, const uint32_t* a, const uint32_t* b) {
    asm volatile(
        "mma.sync.aligned.m16n8k16.row.col.f32.f16.f16.f32 "
        "{%0,%1,%2,%3}, {%4,%5,%6,%7}, {%8,%9}, {%0,%1,%2,%3};\n"
        : "+f"(d[0]), "+f"(d[1]), "+f"(d[2]), "+f"(d[3])
        : "r"(a[0]), "r"(a[1]), "r"(a[2]), "r"(a[3]), "r"(b[0]), "r"(b[1]));
}
#define LDSM_X4(r0, r1, r2, r3, addr)                                          \
    asm volatile("ldmatrix.sync.aligned.m8n8.x4.shared.b16 {%0,%1,%2,%3}, [%4];" \
                 : "=r"(r0), "=r"(r1), "=r"(r2), "=r"(r3) : "r"(addr))
#define LDSM_X4_T(r0, r1, r2, r3, addr)                                        \
    asm volatile("ldmatrix.sync.aligned.m8n8.x4.trans.shared.b16 {%0,%1,%2,%3}, [%4];" \
                 : "=r"(r0), "=r"(r1), "=r"(r2), "=r"(r3) : "r"(addr))
__device__ __forceinline__ void cp_async16(uint32_t dst, const void* src) {
    asm volatile("cp.async.cg.shared.global [%0], [%1], 16;" :: "r"(dst), "l"(src));
}
#define CP_COMMIT() asm volatile("cp.async.commit_group;" ::: "memory")
#define CP_WAIT(n)  asm volatile("cp.async.wait_group %0;" :: "n"(n) : "memory")

__device__ __forceinline__ float gelu_exact(float v) {
    return 0.5f * v * (1.0f + erff(v * 0.70710678118654752440f));
}

// ----------------------------------------------------------------------------
// fused weight convert+transpose (R14)
// ----------------------------------------------------------------------------
__global__ __launch_bounds__(256) void cvt_all_k(
    const float* __restrict__ Wq, const float* __restrict__ Wk,
    const float* __restrict__ Wv, const float* __restrict__ Wo,
    const float* __restrict__ W1, const float* __restrict__ W2,
    __half* __restrict__ wtq, __half* __restrict__ wtk,
    __half* __restrict__ wtv, __half* __restrict__ wto,
    __half* __restrict__ wt1, __half* __restrict__ wt2)
{
    __shared__ float t[32][33];
    int id = blockIdx.x;
    const float* in; __half* outp; int R, Cc, bx, by;
    if (id < 2304) {
        int i = id / 576, rem = id % 576;
        in   = (i == 0) ? Wq : (i == 1) ? Wk : (i == 2) ? Wv : Wo;
        outp = (i == 0) ? wtq : (i == 1) ? wtk : (i == 2) ? wtv : wto;
        R = C_EMB; Cc = C_EMB; bx = (rem % 24) * 32; by = (rem / 24) * 32;
    } else if (id < 4608) {
        int rem = id - 2304;
        in = W1; outp = wt1; R = C_EMB; Cc = F_FFN;
        bx = (rem % 96) * 32; by = (rem / 96) * 32;
    } else {
        int rem = id - 4608;
        in = W2; outp = wt2; R = F_FFN; Cc = C_EMB;
        bx = (rem % 24) * 32; by = (rem / 24) * 32;
    }
    int tx = threadIdx.x & 31, ty = threadIdx.x >> 5;
#pragma unroll
    for (int i = 0; i < 4; i++)
        t[ty + i * 8][tx] = in[(size_t)(by + ty + i * 8) * Cc + bx + tx];
    __syncthreads();
#pragma unroll
    for (int i = 0; i < 4; i++)
        outp[(size_t)(bx + ty + i * 8) * R + by + tx] = __float2half_rn(t[tx][ty + i * 8]);
}

// ----------------------------------------------------------------------------
// LayerNorm / combine kernels (unchanged)
// ----------------------------------------------------------------------------
__global__ __launch_bounds__(256) void layernorm_k(
    const float* __restrict__ in, const float* __restrict__ gamma,
    const float* __restrict__ beta, float* __restrict__ out,
    __half* __restrict__ outh)
{
    int row = blockIdx.x;
    const float* xr = in + (size_t)row * C_EMB;
    float s = 0.f, s2 = 0.f, v0[3];
#pragma unroll
    for (int i = 0; i < 3; i++) {
        float v = xr[threadIdx.x + i * 256];
        v0[i] = v; s += v; s2 += v * v;
    }
#pragma unroll
    for (int off = 16; off > 0; off >>= 1) {
        s  += __shfl_down_sync(0xffffffffu, s,  off);
        s2 += __shfl_down_sync(0xffffffffu, s2, off);
    }
    __shared__ float shs[8], shs2[8];
    int lane = threadIdx.x & 31, warp = threadIdx.x >> 5;
    if (lane == 0) { shs[warp] = s; shs2[warp] = s2; }
    __syncthreads();
    s = 0.f; s2 = 0.f;
#pragma unroll
    for (int i = 0; i < 8; i++) { s += shs[i]; s2 += shs2[i]; }
    float mu = s * (1.0f / C_EMB);
    float var = s2 * (1.0f / C_EMB) - mu * mu;
    float inv = rsqrtf(var + 1e-5f);
#pragma unroll
    for (int i = 0; i < 3; i++) {
        int c = threadIdx.x + i * 256;
        float v = (v0[i] - mu) * inv * gamma[c] + beta[c];
        out [(size_t)row * C_EMB + c] = v;
        outh[(size_t)row * C_EMB + c] = __float2half_rn(v);
    }
}

__global__ __launch_bounds__(256) void combine_ln_k(
    const float* __restrict__ part, const float* __restrict__ bias,
    const float* __restrict__ res, const float* __restrict__ gamma,
    const float* __restrict__ beta, float* __restrict__ out,
    __half* __restrict__ outh)
{
    int row = blockIdx.x;
    size_t base = (size_t)row * C_EMB;
    float s = 0.f, s2 = 0.f, v0[3];
#pragma unroll
    for (int i = 0; i < 3; i++) {
        int c = threadIdx.x + i * 256;
        float v = part[base + c] + part[(size_t)T_SEQ * C_EMB + base + c]
                + bias[c] + res[base + c];
        v0[i] = v; s += v; s2 += v * v;
    }
#pragma unroll
    for (int off = 16; off > 0; off >>= 1) {
        s  += __shfl_down_sync(0xffffffffu, s,  off);
        s2 += __shfl_down_sync(0xffffffffu, s2, off);
    }
    __shared__ float shs[8], shs2[8];
    int lane = threadIdx.x & 31, warp = threadIdx.x >> 5;
    if (lane == 0) { shs[warp] = s; shs2[warp] = s2; }
    __syncthreads();
    s = 0.f; s2 = 0.f;
#pragma unroll
    for (int i = 0; i < 8; i++) { s += shs[i]; s2 += shs2[i]; }
    float mu = s * (1.0f / C_EMB);
    float var = s2 * (1.0f / C_EMB) - mu * mu;
    float inv = rsqrtf(var + 1e-5f);
#pragma unroll
    for (int i = 0; i < 3; i++) {
        int c = threadIdx.x + i * 256;
        float v = (v0[i] - mu) * inv * gamma[c] + beta[c];
        out [base + c] = v;
        outh[base + c] = __float2half_rn(v);
    }
}

__global__ __launch_bounds__(256) void combine_k(
    const float* __restrict__ part, const float* __restrict__ bias,
    const float* __restrict__ res, float* __restrict__ out)
{
    int i = blockIdx.x * 256 + threadIdx.x;
    int col = (i * 4) % C_EMB;
    float4 a = ((const float4*)part)[i];
    float4 b = ((const float4*)(part + (size_t)T_SEQ * C_EMB))[i];
    float4 bi = *(const float4*)(bias + col);
    float4 r = ((const float4*)res)[i];
    float4 o;
    o.x = a.x + b.x + bi.x + r.x;
    o.y = a.y + b.y + bi.y + r.y;
    o.z = a.z + b.z + bi.z + r.z;
    o.w = a.w + b.w + bi.w + r.w;
    ((float4*)out)[i] = o;
}

// ----------------------------------------------------------------------------
// fp16 GEMM (R16: BK=32, 3-stage pipeline — unchanged)
// ----------------------------------------------------------------------------
#define GEMM_S      40
#define GEMM_STAGES 3
#define GEMM_SMEM   (2 * GEMM_STAGES * 128 * GEMM_S * (int)sizeof(__half))

template<int ACT, int PARTIAL, int OUTH>
__device__ __forceinline__ void hgemm_body(
    const __half* __restrict__ A, const __half* __restrict__ B,
    const float* __restrict__ bias, const float* __restrict__ res,
    float* __restrict__ C, __half* __restrict__ Ch,
    int N, int K, int kbeg, int klen, int bx, int by, float oscale)
{
    extern __shared__ __half gsm[];
    __half (*As)[128][GEMM_S] = (__half(*)[128][GEMM_S])gsm;
    __half (*Bs)[128][GEMM_S] = (__half(*)[128][GEMM_S])(gsm + GEMM_STAGES * 128 * GEMM_S);

    int tid = threadIdx.x, lane = tid & 31, wid = tid >> 5;
    int wm = wid & 1, wn = wid >> 1;
    int gid = lane >> 2, tig = lane & 3;
    int bm = by * 128, bn = bx * 128;

    int a_row  = wm * 64 + (lane & 15);
    int a_colh = (lane >> 4) << 3;
    int b_row  = wn * 32 + ((lane >> 4) << 3) + (lane & 7);
    int b_colh = ((lane >> 3) & 1) << 3;

    int l_r = tid >> 1, l_h = (tid & 1) * 16;

    float acc[4][4][4];
#pragma unroll
    for (int i = 0; i < 4; i++)
#pragma unroll
        for (int j = 0; j < 4; j++)
#pragma unroll
            for (int r = 0; r < 4; r++) acc[i][j][r] = 0.f;

    int nt = klen / 32;
    const __half* Arow = A + (size_t)(bm + l_r) * K + kbeg + l_h;
    const __half* Brow = B + (size_t)(bn + l_r) * K + kbeg + l_h;

#pragma unroll
    for (int p = 0; p < 2; p++) {
        cp_async16(s2u(&As[p][l_r][l_h]),     Arow + p * 32);
        cp_async16(s2u(&As[p][l_r][l_h + 8]), Arow + p * 32 + 8);
        cp_async16(s2u(&Bs[p][l_r][l_h]),     Brow + p * 32);
        cp_async16(s2u(&Bs[p][l_r][l_h + 8]), Brow + p * 32 + 8);
        CP_COMMIT();
    }

    for (int kt = 0; kt < nt; kt++) {
        if (kt + 1 < nt) { CP_WAIT(1); } else { CP_WAIT(0); }
        __syncthreads();
        if (kt + 2 < nt) {
            int st = (kt + 2) % GEMM_STAGES;
            int off = (kt + 2) * 32;
            cp_async16(s2u(&As[st][l_r][l_h]),     Arow + off);
            cp_async16(s2u(&As[st][l_r][l_h + 8]), Arow + off + 8);
            cp_async16(s2u(&Bs[st][l_r][l_h]),     Brow + off);
            cp_async16(s2u(&Bs[st][l_r][l_h + 8]), Brow + off + 8);
            CP_COMMIT();
        }

        int buf = kt % GEMM_STAGES;
#pragma unroll
        for (int ks = 0; ks < 2; ks++) {
            int kk = ks * 16;
            uint32_t af[4][4];
#pragma unroll
            for (int mt = 0; mt < 4; mt++) {
                uint32_t addr = s2u(&As[buf][a_row + mt * 16][kk + a_colh]);
                LDSM_X4(af[mt][0], af[mt][1], af[mt][2], af[mt][3], addr);
            }
            uint32_t bf[4][2];
#pragma unroll
            for (int np = 0; np < 2; np++) {
                uint32_t addr = s2u(&Bs[buf][b_row + np * 16][kk + b_colh]);
                LDSM_X4(bf[2 * np][0], bf[2 * np][1],
                        bf[2 * np + 1][0], bf[2 * np + 1][1], addr);
            }
#pragma unroll
            for (int mt = 0; mt < 4; mt++)
#pragma unroll
                for (int ntl = 0; ntl < 4; ntl++)
                    mma_f16(acc[mt][ntl], af[mt], bf[ntl]);
        }
    }

#pragma unroll
    for (int mt = 0; mt < 4; mt++) {
#pragma unroll
        for (int ntl = 0; ntl < 4; ntl++) {
            int row = bm + wm * 64 + mt * 16 + gid;
            int col = bn + wn * 32 + ntl * 8 + tig * 2;
            if (OUTH) {
                float v0 = acc[mt][ntl][0] + bias[col];
                float v1 = acc[mt][ntl][1] + bias[col + 1];
                float v2 = acc[mt][ntl][2] + bias[col];
                float v3 = acc[mt][ntl][3] + bias[col + 1];
                if (ACT == 1) {
                    v0 = gelu_exact(v0); v1 = gelu_exact(v1);
                    v2 = gelu_exact(v2); v3 = gelu_exact(v3);
                }
                v0 *= oscale; v1 *= oscale; v2 *= oscale; v3 *= oscale;
                *(uint32_t*)&Ch[(size_t)row * N + col]       = packh(v0, v1);
                *(uint32_t*)&Ch[(size_t)(row + 8) * N + col] = packh(v2, v3);
            } else {
#pragma unroll
                for (int r = 0; r < 4; r++) {
                    int rr = row + (r >> 1) * 8;
                    int cc = col + (r & 1);
                    float v = acc[mt][ntl][r];
                    if (!PARTIAL) {
                        v += bias[cc];
                        if (res) v += res[(size_t)rr * N + cc];
                        if (ACT == 1) v = gelu_exact(v);
                    }
                    C[(size_t)rr * N + cc] = v;
                }
            }
        }
    }
}

__global__ __launch_bounds__(256) void hgemm_gelu_h_k(
    const __half* __restrict__ A, const __half* __restrict__ B,
    const float* __restrict__ bias, __half* __restrict__ Ch, int N, int K)
{
    hgemm_body<1, 0, 1>(A, B, bias, nullptr, nullptr, Ch, N, K, 0, K,
                        blockIdx.x, blockIdx.y, 1.0f);
}

__global__ __launch_bounds__(256) void hgemm_qkv_k(
    const __half* __restrict__ A,
    const __half* __restrict__ B0, const float* __restrict__ b0, __half* __restrict__ C0,
    const __half* __restrict__ B1, const float* __restrict__ b1, __half* __restrict__ C1,
    const __half* __restrict__ B2, const float* __restrict__ b2, __half* __restrict__ C2)
{
    int sel = blockIdx.x / 6, bx = blockIdx.x % 6;
    const __half* B  = (sel == 0) ? B0 : (sel == 1) ? B1 : B2;
    const float*  bb = (sel == 0) ? b0 : (sel == 1) ? b1 : b2;
    __half*       Ch = (sel == 0) ? C0 : (sel == 1) ? C1 : C2;
    float sc = (sel == 0) ? 0.125f * 1.44269504088896f : 1.0f;
    hgemm_body<0, 0, 1>(A, B, bb, nullptr, nullptr, Ch, C_EMB, C_EMB, 0, C_EMB,
                        bx, blockIdx.y, sc);
}

__global__ __launch_bounds__(256) void hgemm_split_k(
    const __half* __restrict__ A, const __half* __restrict__ B,
    float* __restrict__ part, int K)
{
    int z = blockIdx.z;
    hgemm_body<0, 1, 0>(A, B, nullptr, nullptr,
                        part + (size_t)z * T_SEQ * C_EMB, nullptr,
                        C_EMB, K, z * (K / 2), K / 2, blockIdx.x, blockIdx.y, 1.0f);
}

// ----------------------------------------------------------------------------
// Flash attention fp16, register-P, exp2 softmax.
// R17: 128-thread blocks (4 warps), 64 query rows/block, grid (64, heads);
// 4 CTAs/SM for cross-CTA latency overlap; every warp active on every tile.
// ----------------------------------------------------------------------------
#define AKS 72
#define ATTN_SMEM_BYTES ((2 * 64 * AKS + 2 * 64 * AKS) * 2)

__global__ __launch_bounds__(128, 4) void fattn_k(
    const __half* __restrict__ Qh, const __half* __restrict__ Kh,
    const __half* __restrict__ Vh, __half* __restrict__ Oh)
{
    extern __shared__ __half smh[];
    __half* KsB = smh;                       // [2][64][72]
    __half* VsB = KsB + 2 * 64 * AKS;        // [2][64][72]

    int hd = blockIdx.y;
    int qt = (int)gridDim.x - 1 - (int)blockIdx.x;   // heavy tiles first
    int tid = threadIdx.x, w = tid >> 5, lane = tid & 31;
    int gid = lane >> 2, tig = lane & 3;
    int rbase = qt * 64 + w * 16;

    int bs_row = ((lane >> 4) << 3) + (lane & 7);
    int bs_colh = ((lane >> 3) & 1) << 3;
    int vt_row = lane & 15;
    int vt_colh = (lane >> 4) << 3;

    uint32_t aq[4][4];
    {
        const __half* qp = Qh + (size_t)rbase * C_EMB + hd * D_HEAD;
#pragma unroll
        for (int kk = 0; kk < 4; kk++) {
            aq[kk][0] = *(const uint32_t*)(qp + (size_t)gid * C_EMB + kk * 16 + 2 * tig);
            aq[kk][1] = *(const uint32_t*)(qp + (size_t)(gid + 8) * C_EMB + kk * 16 + 2 * tig);
            aq[kk][2] = *(const uint32_t*)(qp + (size_t)gid * C_EMB + kk * 16 + 2 * tig + 8);
            aq[kk][3] = *(const uint32_t*)(qp + (size_t)(gid + 8) * C_EMB + kk * 16 + 2 * tig + 8);
        }
    }

    float oacc[8][4];
#pragma unroll
    for (int i = 0; i < 8; i++)
#pragma unroll
        for (int r = 0; r < 4; r++) oacc[i][r] = 0.f;
    float m_lo = -1e30f, m_hi = -1e30f, l_lo = 0.f, l_hi = 0.f;
    int row0 = rbase + gid, row1 = row0 + 8;

    int kb_last = qt;    // tiles 0..qt cover keys up to 64*(qt+1)-1 >= all rows

    // per-thread load slots: 512 8-half units per matrix, 128 threads -> 4 each
#pragma unroll
    for (int i = 0; i < 4; i++) {
        int id = tid + i * 128;
        int rr = id >> 3, it = id & 7;
        cp_async16(s2u(KsB + rr * AKS + it * 8),
                   Kh + (size_t)rr * C_EMB + hd * D_HEAD + it * 8);
        cp_async16(s2u(VsB + rr * AKS + it * 8),
                   Vh + (size_t)rr * C_EMB + hd * D_HEAD + it * 8);
    }
    CP_COMMIT();

    for (int kb = 0; kb <= kb_last; kb++) {
        int cur = kb & 1;
        if (kb < kb_last) {
            int nb = (kb + 1) & 1;
            int nbase = (kb + 1) * 64;
#pragma unroll
            for (int i = 0; i < 4; i++) {
                int id = tid + i * 128;
                int rr = id >> 3, it = id & 7;
                cp_async16(s2u(KsB + (nb * 64 + rr) * AKS + it * 8),
                           Kh + (size_t)(nbase + rr) * C_EMB + hd * D_HEAD + it * 8);
                cp_async16(s2u(VsB + (nb * 64 + rr) * AKS + it * 8),
                           Vh + (size_t)(nbase + rr) * C_EMB + hd * D_HEAD + it * 8);
            }
            CP_COMMIT();
            CP_WAIT(1);
        } else {
            CP_WAIT(0);
        }
        __syncthreads();

        __half* Ks = KsB + cur * 64 * AKS;
        __half* Vs = VsB + cur * 64 * AKS;
        int kbase = kb * 64;

        {
            float sacc[8][4];
#pragma unroll
            for (int n = 0; n < 8; n++)
#pragma unroll
                for (int r = 0; r < 4; r++) sacc[n][r] = 0.f;
#pragma unroll
            for (int kk = 0; kk < 4; kk++) {
#pragma unroll
                for (int np = 0; np < 4; np++) {
                    uint32_t b4[4];
                    uint32_t addr = s2u(&Ks[(np * 16 + bs_row) * AKS + kk * 16 + bs_colh]);
                    LDSM_X4(b4[0], b4[1], b4[2], b4[3], addr);
                    mma_f16(sacc[2 * np],     aq[kk], b4);
                    mma_f16(sacc[2 * np + 1], aq[kk], b4 + 2);
                }
            }

            bool boundary = (kbase + 63 > rbase);
            float ml0 = -1e30f, ml1 = -1e30f;
#pragma unroll
            for (int n = 0; n < 8; n++) {
                if (boundary) {
                    int c = kbase + n * 8 + 2 * tig;
                    if (c     > row0) sacc[n][0] = -1e30f;
                    if (c + 1 > row0) sacc[n][1] = -1e30f;
                    if (c     > row1) sacc[n][2] = -1e30f;
                    if (c + 1 > row1) sacc[n][3] = -1e30f;
                }
                ml0 = fmaxf(ml0, fmaxf(sacc[n][0], sacc[n][1]));
                ml1 = fmaxf(ml1, fmaxf(sacc[n][2], sacc[n][3]));
            }
            ml0 = fmaxf(ml0, __shfl_xor_sync(0xffffffffu, ml0, 1));
            ml0 = fmaxf(ml0, __shfl_xor_sync(0xffffffffu, ml0, 2));
            ml1 = fmaxf(ml1, __shfl_xor_sync(0xffffffffu, ml1, 1));
            ml1 = fmaxf(ml1, __shfl_xor_sync(0xffffffffu, ml1, 2));
            float mn0 = fmaxf(m_lo, ml0), mn1 = fmaxf(m_hi, ml1);
            float al0 = exp2f(m_lo - mn0), al1 = exp2f(m_hi - mn1);
            m_lo = mn0; m_hi = mn1;

            float ls0 = 0.f, ls1 = 0.f;
#pragma unroll
            for (int n = 0; n < 8; n++) {
                sacc[n][0] = exp2f(sacc[n][0] - mn0);
                sacc[n][1] = exp2f(sacc[n][1] - mn0);
                sacc[n][2] = exp2f(sacc[n][2] - mn1);
                sacc[n][3] = exp2f(sacc[n][3] - mn1);
                ls0 += sacc[n][0] + sacc[n][1];
                ls1 += sacc[n][2] + sacc[n][3];
            }
            ls0 += __shfl_xor_sync(0xffffffffu, ls0, 1);
            ls0 += __shfl_xor_sync(0xffffffffu, ls0, 2);
            ls1 += __shfl_xor_sync(0xffffffffu, ls1, 1);
            ls1 += __shfl_xor_sync(0xffffffffu, ls1, 2);
            l_lo = l_lo * al0 + ls0;
            l_hi = l_hi * al1 + ls1;
#pragma unroll
            for (int n = 0; n < 8; n++) {
                oacc[n][0] *= al0; oacc[n][1] *= al0;
                oacc[n][2] *= al1; oacc[n][3] *= al1;
            }

#pragma unroll
            for (int kt = 0; kt < 4; kt++) {
                uint32_t ap[4];
                ap[0] = packh(sacc[2 * kt][0],     sacc[2 * kt][1]);
                ap[1] = packh(sacc[2 * kt][2],     sacc[2 * kt][3]);
                ap[2] = packh(sacc[2 * kt + 1][0], sacc[2 * kt + 1][1]);
                ap[3] = packh(sacc[2 * kt + 1][2], sacc[2 * kt + 1][3]);
#pragma unroll
                for (int np2 = 0; np2 < 4; np2++) {
                    uint32_t b4[4];
                    uint32_t va = s2u(&Vs[(kt * 16 + vt_row) * AKS + np2 * 16 + vt_colh]);
                    LDSM_X4_T(b4[0], b4[1], b4[2], b4[3], va);
                    mma_f16(oacc[2 * np2],     ap, b4);
                    mma_f16(oacc[2 * np2 + 1], ap, b4 + 2);
                }
            }
        }
        __syncthreads();
    }

    float inv0 = 1.0f / l_lo, inv1 = 1.0f / l_hi;
    __half* o0 = Oh + (size_t)row0 * C_EMB + hd * D_HEAD;
    __half* o1 = Oh + (size_t)row1 * C_EMB + hd * D_HEAD;
#pragma unroll
    for (int n = 0; n < 8; n++) {
        int c = n * 8 + 2 * tig;
        *(uint32_t*)(o0 + c) = packh(oacc[n][0] * inv0, oacc[n][1] * inv0);
        *(uint32_t*)(o1 + c) = packh(oacc[n][2] * inv1, oacc[n][3] * inv1);
    }
}

// ----------------------------------------------------------------------------
// launch
// ----------------------------------------------------------------------------
extern "C" void kernel_launch(void* const* d_in, const int* in_sizes, int n_in,
                              void* d_out, int out_size)
{
    const float* x     = (const float*)d_in[0];
    const float* Wq    = (const float*)d_in[1];
    const float* bq    = (const float*)d_in[2];
    const float* Wk    = (const float*)d_in[3];
    const float* bk    = (const float*)d_in[4];
    const float* Wv    = (const float*)d_in[5];
    const float* bv    = (const float*)d_in[6];
    const float* Wo    = (const float*)d_in[7];
    const float* bo    = (const float*)d_in[8];
    const float* ln1_g = (const float*)d_in[9];
    const float* ln1_b = (const float*)d_in[10];
    const float* ln2_g = (const float*)d_in[11];
    const float* ln2_b = (const float*)d_in[12];
    const float* W1    = (const float*)d_in[13];
    const float* b1    = (const float*)d_in[14];
    const float* W2    = (const float*)d_in[15];
    const float* b2    = (const float*)d_in[16];
    float* out = (float*)d_out;

    float *h, *h2, *part;
    __half *hh, *h2h, *qh, *kh, *vh, *ctxh, *m1h;
    __half *wtq, *wtk, *wtv, *wto, *wt1, *wt2;
    cudaGetSymbolAddress((void**)&h,    g_h);
    cudaGetSymbolAddress((void**)&h2,   g_h2);
    cudaGetSymbolAddress((void**)&part, g_part);
    cudaGetSymbolAddress((void**)&hh,   g_hh);
    cudaGetSymbolAddress((void**)&h2h,  g_h2h);
    cudaGetSymbolAddress((void**)&qh,   g_qh);
    cudaGetSymbolAddress((void**)&kh,   g_kh);
    cudaGetSymbolAddress((void**)&vh,   g_vh);
    cudaGetSymbolAddress((void**)&ctxh, g_ctxh);
    cudaGetSymbolAddress((void**)&m1h,  g_m1h);
    cudaGetSymbolAddress((void**)&wtq,  g_wtq);
    cudaGetSymbolAddress((void**)&wtk,  g_wtk);
    cudaGetSymbolAddress((void**)&wtv,  g_wtv);
    cudaGetSymbolAddress((void**)&wto,  g_wto);
    cudaGetSymbolAddress((void**)&wt1,  g_wt1);
    cudaGetSymbolAddress((void**)&wt2,  g_wt2);

    cudaFuncSetAttribute(fattn_k, cudaFuncAttributeMaxDynamicSharedMemorySize,
                         ATTN_SMEM_BYTES);
    cudaFuncSetAttribute(hgemm_gelu_h_k, cudaFuncAttributeMaxDynamicSharedMemorySize,
                         GEMM_SMEM);
    cudaFuncSetAttribute(hgemm_qkv_k, cudaFuncAttributeMaxDynamicSharedMemorySize,
                         GEMM_SMEM);
    cudaFuncSetAttribute(hgemm_split_k, cudaFuncAttributeMaxDynamicSharedMemorySize,
                         GEMM_SMEM);

    cvt_all_k<<<6912, 256>>>(Wq, Wk, Wv, Wo, W1, W2,
                             wtq, wtk, wtv, wto, wt1, wt2);

    dim3 gQKV(18, T_SEQ / 128);
    dim3 gF(F_FFN / 128, T_SEQ / 128);
    dim3 gSplit(C_EMB / 128, T_SEQ / 128, 2);
    int  gComb = T_SEQ * C_EMB / 4 / 256;

    layernorm_k<<<T_SEQ, 256>>>(x, ln1_g, ln1_b, h, hh);
    hgemm_qkv_k<<<gQKV, 256, GEMM_SMEM>>>(hh, wtq, bq, qh, wtk, bk, kh, wtv, bv, vh);
    fattn_k<<<dim3(T_SEQ / 64, N_HEAD), 128, ATTN_SMEM_BYTES>>>(qh, kh, vh, ctxh);
    hgemm_split_k<<<gSplit, 256, GEMM_SMEM>>>(ctxh, wto, part, C_EMB);
    combine_ln_k<<<T_SEQ, 256>>>(part, bo, h, ln2_g, ln2_b, h2, h2h);
    hgemm_gelu_h_k<<<gF, 256, GEMM_SMEM>>>(h2h, wt1, b1, m1h, F_FFN, C_EMB);
    hgemm_split_k<<<gSplit, 256, GEMM_SMEM>>>(m1h, wt2, part, F_FFN);
    combine_k<<<gComb, 256>>>(part, b2, h2, out);
}